// round 9
// baseline (speedup 1.0000x reference)
#include <cuda_runtime.h>
#include <cstdint>

#define NH   16
#define NKV  4
#define HD   64
#define DM   1024
#define BB   2
#define SEQ  2048
#define MROWS (BB*SEQ)   // 4096

// Q pre-scale: HD^-0.5 * log2(e)  (softmax done in exp2 domain)
#define QSC 0.18033688011112042f

// ---------------------------------------------------------------------------
// Scratch (allocation-free device globals)
// ---------------------------------------------------------------------------
__device__ float g_xr [(size_t)MROWS * DM];       // tf32-rounded x
__device__ float g_wqr[(size_t)DM * DM];
__device__ float g_wkr[(size_t)DM * 256];
__device__ float g_wvr[(size_t)DM * 256];
__device__ float g_wor[(size_t)DM * DM];
__device__ float g_q  [(size_t)BB * NH  * SEQ * HD];  // head-major, d-permuted, *QSC, rope'd
__device__ float g_k  [(size_t)BB * NKV * SEQ * HD];  // head-major, d-permuted, rope'd
__device__ float g_v  [(size_t)BB * NKV * HD * SEQ];  // head-major TRANSPOSED: [d][seq]
__device__ float g_attn[(size_t)MROWS * DM];          // (b,n,1024), tf32-rounded

// ---------------------------------------------------------------------------
// helpers
// ---------------------------------------------------------------------------
__device__ __forceinline__ uint32_t f2tf(float f) {
    uint32_t u;
    asm("cvt.rna.tf32.f32 %0, %1;" : "=r"(u) : "f"(f));
    return u;
}
__device__ __forceinline__ float r2f(uint32_t u) { return __uint_as_float(u); }

__device__ __forceinline__ float ex2f(float x) {
    float r;
    asm("ex2.approx.ftz.f32 %0, %1;" : "=f"(r) : "f"(x));
    return r;
}
__device__ __forceinline__ int perm8p(int j) {
    int u = j & 7;
    return (j & ~7) + ((u < 4) ? 2 * u : 2 * (u - 4) + 1);
}
__device__ __forceinline__ void mma8(float c[4], const uint32_t a[4], const uint32_t b[2]) {
    asm volatile(
        "mma.sync.aligned.m16n8k8.row.col.f32.tf32.tf32.f32 "
        "{%0,%1,%2,%3},{%4,%5,%6,%7},{%8,%9},{%0,%1,%2,%3};"
        : "+f"(c[0]), "+f"(c[1]), "+f"(c[2]), "+f"(c[3])
        : "r"(a[0]), "r"(a[1]), "r"(a[2]), "r"(a[3]), "r"(b[0]), "r"(b[1]));
}
__device__ __forceinline__ void cpa16(uint32_t dst, const void* src) {
    asm volatile("cp.async.cg.shared.global [%0], [%1], 16;" :: "r"(dst), "l"(src) : "memory");
}
#define CPA_COMMIT() asm volatile("cp.async.commit_group;" ::: "memory")

// ---------------------------------------------------------------------------
// Pre-pass: round x + weights to the tf32 grid (then mma can eat them raw).
// ---------------------------------------------------------------------------
__global__ void prep_round(const float* __restrict__ x,  const float* __restrict__ Wq,
                           const float* __restrict__ Wk, const float* __restrict__ Wv,
                           const float* __restrict__ Wo)
{
    size_t i = (size_t)blockIdx.x * 256 + threadIdx.x;   // float4 index
    const float* src; float* dst; size_t off;
    if      (i < 1048576) { src = x;  dst = g_xr;  off = i; }
    else if (i < 1310720) { src = Wq; dst = g_wqr; off = i - 1048576; }
    else if (i < 1376256) { src = Wk; dst = g_wkr; off = i - 1310720; }
    else if (i < 1441792) { src = Wv; dst = g_wvr; off = i - 1376256; }
    else                  { src = Wo; dst = g_wor; off = i - 1441792; }
    float4 v = ((const float4*)src)[off];
    v.x = r2f(f2tf(v.x)); v.y = r2f(f2tf(v.y));
    v.z = r2f(f2tf(v.z)); v.w = r2f(f2tf(v.w));
    ((float4*)dst)[off] = v;
}

// ---------------------------------------------------------------------------
// cp.async 3-stage GEMM: 128x128 tile, kstep 32, 256 threads, warp tile 64x32.
// Stage: As[128][40] (5120 w) + Bs[32][132] (4224 w) = 9344 words.
// ---------------------------------------------------------------------------
#define GSTAGE 9344
#define GEMM_SMEM (3 * GSTAGE * 4)   // 112128 B

__device__ __forceinline__ void gemm_main(uint32_t* sm, uint32_t smb,
    const float* __restrict__ A, const float* __restrict__ B,
    int ldb, int n0, int row0, float acc[4][4][4])
{
    const int K = DM, KT = DM / 32;
    const int tid = threadIdx.x, lane = tid & 31, wid = tid >> 5;
    const int g = lane >> 2, t = lane & 3;
    const int m0 = (wid >> 2) * 64, nw = (wid & 3) * 32;

    const int ar = tid >> 3, ac = (tid & 7) << 2;
    const int bk = tid >> 5, bn = (tid & 31) << 2;
    const uint32_t aDst = (ar * 40 + ac) * 4;
    const uint32_t bDst = (5120 + bk * 132 + bn) * 4;
    const float* aS = A + (size_t)(row0 + ar) * K + ac;
    const float* bS = B + (size_t)bk * ldb + n0 + bn;

    auto issue = [&](int slot, int kt) {
        uint32_t base = smb + slot * (GSTAGE * 4);
        const float* a = aS + kt * 32;
        const float* b = bS + (size_t)kt * 32 * ldb;
#pragma unroll
        for (int i = 0; i < 4; i++)
            cpa16(base + aDst + i * (32 * 40 * 4), a + (size_t)i * 32 * K);
#pragma unroll
        for (int i = 0; i < 4; i++)
            cpa16(base + bDst + i * (8 * 132 * 4), b + (size_t)i * 8 * ldb);
        CPA_COMMIT();
    };

#pragma unroll
    for (int mi = 0; mi < 4; mi++)
#pragma unroll
        for (int ni = 0; ni < 4; ni++)
#pragma unroll
            for (int r = 0; r < 4; r++) acc[mi][ni][r] = 0.f;

    issue(0, 0);
    issue(1, 1);

    for (int kt = 0; kt < KT; kt++) {
        if (kt + 1 < KT) asm volatile("cp.async.wait_group 1;" ::: "memory");
        else             asm volatile("cp.async.wait_group 0;" ::: "memory");
        __syncthreads();
        if (kt + 2 < KT) issue((kt + 2) % 3, kt + 2);

        uint32_t* st = sm + (kt % 3) * GSTAGE;
        uint32_t (*As)[40]  = (uint32_t(*)[40])st;
        uint32_t (*Bs)[132] = (uint32_t(*)[132])(st + 5120);
#pragma unroll
        for (int kk0 = 0; kk0 < 32; kk0 += 8) {
            uint32_t a[4][4], b[4][2];
#pragma unroll
            for (int mi = 0; mi < 4; mi++) {
                int rb = m0 + mi * 16 + g;
                uint2 av0 = *(const uint2*)&As[rb][kk0 + 2 * t];
                uint2 av1 = *(const uint2*)&As[rb + 8][kk0 + 2 * t];
                a[mi][0] = av0.x; a[mi][1] = av1.x; a[mi][2] = av0.y; a[mi][3] = av1.y;
            }
#pragma unroll
            for (int ni = 0; ni < 4; ni++) {
                b[ni][0] = Bs[kk0 + 2 * t][nw + ni * 8 + g];
                b[ni][1] = Bs[kk0 + 2 * t + 1][nw + ni * 8 + g];
            }
#pragma unroll
            for (int mi = 0; mi < 4; mi++)
#pragma unroll
                for (int ni = 0; ni < 4; ni++)
                    mma8(acc[mi][ni], a[mi], b[ni]);
        }
    }
}

// ---------------------------------------------------------------------------
// QKV projection + fused RoPE + permuted head-major stores (V transposed).
// ---------------------------------------------------------------------------
__global__ __launch_bounds__(256, 2) void qkv_gemm(
    const float* __restrict__ cs, const float* __restrict__ sn)
{
    extern __shared__ uint32_t sm[];
    uint32_t smb = (uint32_t)__cvta_generic_to_shared(sm);
    const int bx = blockIdx.x, row0 = blockIdx.y * 128;
    const int tid = threadIdx.x, lane = tid & 31, wid = tid >> 5;
    const int g = lane >> 2, t = lane & 3;
    const int m0 = (wid >> 2) * 64, nw = (wid & 3) * 32;
    float acc[4][4][4];

    if (bx < 8) {
        gemm_main(sm, smb, g_xr, g_wqr, DM, bx * 128, row0, acc);
#pragma unroll
        for (int mi = 0; mi < 4; mi++)
#pragma unroll
            for (int ni = 0; ni < 4; ni++) {
                int gc = bx * 128 + nw + ni * 8 + 2 * t;       // even original col
                int head = gc >> 6, j = (gc & 63) >> 1;
                int pj = perm8p(j), pj2 = perm8p(j + 32);
#pragma unroll
                for (int rr = 0; rr < 2; rr++) {
                    int row = row0 + m0 + mi * 16 + g + rr * 8;
                    int n = row & (SEQ - 1), bi = row >> 11;
                    float cv = cs[n * 32 + j], sv = sn[n * 32 + j];
                    float a0 = acc[mi][ni][rr * 2], a1 = acc[mi][ni][rr * 2 + 1];
                    size_t bp = ((size_t)(bi * NH + head) * SEQ + n) * HD;
                    g_q[bp + pj]  = r2f(f2tf((a0 * cv - a1 * sv) * QSC));
                    g_q[bp + pj2] = r2f(f2tf((a0 * sv + a1 * cv) * QSC));
                }
            }
    } else if (bx < 10) {
        gemm_main(sm, smb, g_xr, g_wkr, 256, (bx - 8) * 128, row0, acc);
#pragma unroll
        for (int mi = 0; mi < 4; mi++)
#pragma unroll
            for (int ni = 0; ni < 4; ni++) {
                int gc = (bx - 8) * 128 + nw + ni * 8 + 2 * t;
                int kvh = gc >> 6, j = (gc & 63) >> 1;
                int pj = perm8p(j), pj2 = perm8p(j + 32);
#pragma unroll
                for (int rr = 0; rr < 2; rr++) {
                    int row = row0 + m0 + mi * 16 + g + rr * 8;
                    int n = row & (SEQ - 1), bi = row >> 11;
                    float cv = cs[n * 32 + j], sv = sn[n * 32 + j];
                    float a0 = acc[mi][ni][rr * 2], a1 = acc[mi][ni][rr * 2 + 1];
                    size_t bp = ((size_t)(bi * NKV + kvh) * SEQ + n) * HD;
                    g_k[bp + pj]  = r2f(f2tf(a0 * cv - a1 * sv));
                    g_k[bp + pj2] = r2f(f2tf(a0 * sv + a1 * cv));
                }
            }
    } else {
        gemm_main(sm, smb, g_xr, g_wvr, 256, (bx - 10) * 128, row0, acc);
#pragma unroll
        for (int mi = 0; mi < 4; mi++)
#pragma unroll
            for (int ni = 0; ni < 4; ni++) {
                int gc = (bx - 10) * 128 + nw + ni * 8 + 2 * t;
                int kvh = gc >> 6, d = gc & 63;
#pragma unroll
                for (int rr = 0; rr < 2; rr++) {
                    int row = row0 + m0 + mi * 16 + g + rr * 8;
                    int n = row & (SEQ - 1), bi = row >> 11;
                    size_t hb = ((size_t)(bi * NKV + kvh) * HD);
                    g_v[(hb + d) * SEQ + n]     = r2f(f2tf(acc[mi][ni][rr * 2]));
                    g_v[(hb + d + 1) * SEQ + n] = r2f(f2tf(acc[mi][ni][rr * 2 + 1]));
                }
            }
    }
}

// ---------------------------------------------------------------------------
// Output projection
// ---------------------------------------------------------------------------
__global__ __launch_bounds__(256, 2) void out_gemm(float* __restrict__ out)
{
    extern __shared__ uint32_t sm[];
    uint32_t smb = (uint32_t)__cvta_generic_to_shared(sm);
    const int tid = threadIdx.x, lane = tid & 31, wid = tid >> 5;
    const int g = lane >> 2, t = lane & 3;
    const int m0 = (wid >> 2) * 64, nw = (wid & 3) * 32;
    const int n0 = blockIdx.x * 128, row0 = blockIdx.y * 128;
    float acc[4][4][4];
    gemm_main(sm, smb, g_attn, g_wor, DM, n0, row0, acc);
#pragma unroll
    for (int mi = 0; mi < 4; mi++) {
        int r = row0 + m0 + mi * 16 + g;
#pragma unroll
        for (int ni = 0; ni < 4; ni++) {
            int c = n0 + nw + ni * 8 + 2 * t;
            *(float2*)(out + (size_t)r * DM + c)       = make_float2(acc[mi][ni][0], acc[mi][ni][1]);
            *(float2*)(out + (size_t)(r + 8) * DM + c) = make_float2(acc[mi][ni][2], acc[mi][ni][3]);
        }
    }
}

// ---------------------------------------------------------------------------
// Flash attention: BM=256, 256 threads (8 warps), 1 CTA/SM, 3-stage KV ring.
// Each warp owns 32 q-rows (2 mtiles) -> every K/V b-frag LDS.64 feeds TWO
// mmas (halves the dominant crossbar term vs 16-warp layout).
// V transposed (d x keys); softmax in exp2 domain (QSC pre-scale).
// Smem (u32): Qs[256*72]=18432 | 3 stages x (Ks[64*72]+Vt[64*72]=9216)
// = 46080 words = 184320 B.
// ---------------------------------------------------------------------------
#define ATT_SMEM 184320

__device__ __forceinline__ void attn_issue_kv(uint32_t smb, int slot,
    const float* __restrict__ Kb, const float* __restrict__ Vb, int kt, int tid)
{
    uint32_t base = smb + (18432 + slot * 9216) * 4;
    const float* K0 = Kb + (size_t)kt * 64 * HD;
#pragma unroll
    for (int i = 0; i < 4; i++) {
        int c = tid + i * 256;
        int r = c >> 4, col = (c & 15) << 2;
        cpa16(base + (r * 72 + col) * 4, K0 + r * HD + col);
    }
#pragma unroll
    for (int i = 0; i < 4; i++) {
        int c = tid + i * 256;
        int r = c >> 4, col = (c & 15) << 2;
        cpa16(base + (4608 + r * 72 + col) * 4, Vb + (size_t)r * SEQ + kt * 64 + col);
    }
    CPA_COMMIT();
}

// per-mtile online softmax update (registers + shfl only)
__device__ __forceinline__ void softmax_upd(float s[8][4], float o[8][4],
    float& m0s, float& m1s, float& l0s, float& l1s)
{
    float mx0 = -1e30f, mx1 = -1e30f;
#pragma unroll
    for (int ni = 0; ni < 8; ni++) {
        mx0 = fmaxf(mx0, fmaxf(s[ni][0], s[ni][1]));
        mx1 = fmaxf(mx1, fmaxf(s[ni][2], s[ni][3]));
    }
    mx0 = fmaxf(mx0, __shfl_xor_sync(0xffffffffu, mx0, 1));
    mx0 = fmaxf(mx0, __shfl_xor_sync(0xffffffffu, mx0, 2));
    mx1 = fmaxf(mx1, __shfl_xor_sync(0xffffffffu, mx1, 1));
    mx1 = fmaxf(mx1, __shfl_xor_sync(0xffffffffu, mx1, 2));

    float mn0 = fmaxf(m0s, mx0), mn1 = fmaxf(m1s, mx1);
    float cor0 = ex2f(m0s - mn0), cor1 = ex2f(m1s - mn1);
    m0s = mn0; m1s = mn1;

    float rs0 = 0.f, rs1 = 0.f;
#pragma unroll
    for (int ni = 0; ni < 8; ni++) {
        s[ni][0] = ex2f(s[ni][0] - mn0);
        s[ni][1] = ex2f(s[ni][1] - mn0);
        s[ni][2] = ex2f(s[ni][2] - mn1);
        s[ni][3] = ex2f(s[ni][3] - mn1);
        rs0 += s[ni][0] + s[ni][1];
        rs1 += s[ni][2] + s[ni][3];
    }
    rs0 += __shfl_xor_sync(0xffffffffu, rs0, 1);
    rs0 += __shfl_xor_sync(0xffffffffu, rs0, 2);
    rs1 += __shfl_xor_sync(0xffffffffu, rs1, 1);
    rs1 += __shfl_xor_sync(0xffffffffu, rs1, 2);
    l0s = l0s * cor0 + rs0;
    l1s = l1s * cor1 + rs1;

#pragma unroll
    for (int ni = 0; ni < 8; ni++) {
        o[ni][0] *= cor0; o[ni][1] *= cor0;
        o[ni][2] *= cor1; o[ni][3] *= cor1;
    }
}

__global__ __launch_bounds__(256, 1) void attn_mma()
{
    extern __shared__ uint32_t sm[];
    uint32_t smb = (uint32_t)__cvta_generic_to_shared(sm);
    const int b = blockIdx.z, h = blockIdx.y;
    const int n0 = blockIdx.x * 256;
    const int kvh = h >> 2;
    const int tid = threadIdx.x, lane = tid & 31, wid = tid >> 5;  // wid 0..7
    const int g = lane >> 2, t = lane & 3;
    const int m0 = wid * 32;    // warp owns rows m0..m0+31 (2 mtiles)

    const float* Qb = g_q + ((size_t)(b * NH + h) * SEQ + n0) * HD;
    const float* Kb = g_k + ((size_t)(b * NKV + kvh) * SEQ) * HD;
    const float* Vb = g_v + ((size_t)(b * NKV + kvh) * HD) * SEQ;

    // Q tile: 256 rows x 64 words
#pragma unroll
    for (int i = 0; i < 16; i++) {
        int c = tid + i * 256;
        int r = c >> 4, col = (c & 15) << 2;
        cpa16(smb + (r * 72 + col) * 4, Qb + r * HD + col);
    }
    CPA_COMMIT();
    attn_issue_kv(smb, 0, Kb, Vb, 0, tid);
    attn_issue_kv(smb, 1, Kb, Vb, 1, tid);

    uint32_t* Qs = sm;
    float m0a = -1e30f, m1a = -1e30f, l0a = 0.f, l1a = 0.f;   // mtile 0 stats
    float m0b = -1e30f, m1b = -1e30f, l0b = 0.f, l1b = 0.f;   // mtile 1 stats
    float s[2][8][4], o[2][8][4];
#pragma unroll
    for (int mt = 0; mt < 2; mt++)
#pragma unroll
        for (int ni = 0; ni < 8; ni++)
#pragma unroll
            for (int r = 0; r < 4; r++) o[mt][ni][r] = 0.f;

    const int KT = SEQ / 64;
    for (int kt = 0; kt < KT; kt++) {
        if (kt + 1 < KT) asm volatile("cp.async.wait_group 1;" ::: "memory");
        else             asm volatile("cp.async.wait_group 0;" ::: "memory");
        __syncthreads();    // stage kt ready; slot (kt+2)%3's prior data consumed
        if (kt + 2 < KT) attn_issue_kv(smb, (kt + 2) % 3, Kb, Vb, kt + 2, tid);

        uint32_t* Ks = sm + 18432 + (kt % 3) * 9216;
        uint32_t* Vt = Ks + 4608;

        // S = Q*K^T for 32 rows x 64 keys; K b-frag loaded once per (kk,ni),
        // feeds both mtiles.
#pragma unroll
        for (int mt = 0; mt < 2; mt++)
#pragma unroll
            for (int ni = 0; ni < 8; ni++)
#pragma unroll
                for (int r = 0; r < 4; r++) s[mt][ni][r] = 0.f;
#pragma unroll
        for (int kk = 0; kk < 8; kk++) {
            uint32_t a0[4], a1[4];
            uint2 p00 = *(const uint2*)&Qs[(m0 + g) * 72 + kk * 8 + 2 * t];
            uint2 p01 = *(const uint2*)&Qs[(m0 + g + 8) * 72 + kk * 8 + 2 * t];
            uint2 p10 = *(const uint2*)&Qs[(m0 + g + 16) * 72 + kk * 8 + 2 * t];
            uint2 p11 = *(const uint2*)&Qs[(m0 + g + 24) * 72 + kk * 8 + 2 * t];
            a0[0] = p00.x; a0[1] = p01.x; a0[2] = p00.y; a0[3] = p01.y;
            a1[0] = p10.x; a1[1] = p11.x; a1[2] = p10.y; a1[3] = p11.y;
#pragma unroll
            for (int ni = 0; ni < 8; ni++) {
                uint2 bv = *(const uint2*)&Ks[(ni * 8 + g) * 72 + kk * 8 + 2 * t];
                uint32_t bb[2] = {bv.x, bv.y};
                mma8(s[0][ni], a0, bb);
                mma8(s[1][ni], a1, bb);
            }
        }

        // online softmax per mtile (register-only)
        softmax_upd(s[0], o[0], m0a, m1a, l0a, l1a);
        softmax_upd(s[1], o[1], m0b, m1b, l0b, l1b);

        // O += P*V: Vt b-frag loaded once per (kk,ni), feeds both mtiles.
#pragma unroll
        for (int kk = 0; kk < 8; kk++) {
            uint32_t a0[4], a1[4];
            a0[0] = f2tf(s[0][kk][0]); a0[1] = f2tf(s[0][kk][2]);
            a0[2] = f2tf(s[0][kk][1]); a0[3] = f2tf(s[0][kk][3]);
            a1[0] = f2tf(s[1][kk][0]); a1[1] = f2tf(s[1][kk][2]);
            a1[2] = f2tf(s[1][kk][1]); a1[3] = f2tf(s[1][kk][3]);
#pragma unroll
            for (int ni = 0; ni < 8; ni++) {
                uint2 bv = *(const uint2*)&Vt[(ni * 8 + g) * 72 + kk * 8 + 2 * t];
                uint32_t bb[2] = {bv.x, bv.y};
                mma8(o[0][ni], a0, bb);
                mma8(o[1][ni], a1, bb);
            }
        }
    }

    // epilogue: normalize, round to tf32, write (b,n,1024) for out_gemm
#pragma unroll
    for (int mt = 0; mt < 2; mt++) {
        float inv0 = 1.f / (mt ? l0b : l0a);
        float inv1 = 1.f / (mt ? l1b : l1a);
        size_t r0 = (size_t)b * SEQ + n0 + m0 + mt * 16 + g;
#pragma unroll
        for (int ni = 0; ni < 8; ni++) {
            int col = h * HD + ni * 8 + 2 * t;
            *(float2*)&g_attn[r0 * DM + col] =
                make_float2(r2f(f2tf(o[mt][ni][0] * inv0)), r2f(f2tf(o[mt][ni][1] * inv0)));
            *(float2*)&g_attn[(r0 + 8) * DM + col] =
                make_float2(r2f(f2tf(o[mt][ni][2] * inv1)), r2f(f2tf(o[mt][ni][3] * inv1)));
        }
    }
}

// ---------------------------------------------------------------------------
extern "C" void kernel_launch(void* const* d_in, const int* in_sizes, int n_in,
                              void* d_out, int out_size)
{
    const float* x  = (const float*)d_in[0];
    const float* cs = (const float*)d_in[1];
    const float* sn = (const float*)d_in[2];
    const float* Wq = (const float*)d_in[3];
    const float* Wk = (const float*)d_in[4];
    const float* Wv = (const float*)d_in[5];
    const float* Wo = (const float*)d_in[6];
    float* out = (float*)d_out;
    (void)in_sizes; (void)n_in; (void)out_size;

    cudaFuncSetAttribute(qkv_gemm, cudaFuncAttributeMaxDynamicSharedMemorySize, GEMM_SMEM);
    cudaFuncSetAttribute(out_gemm, cudaFuncAttributeMaxDynamicSharedMemorySize, GEMM_SMEM);
    cudaFuncSetAttribute(attn_mma, cudaFuncAttributeMaxDynamicSharedMemorySize, ATT_SMEM);

    // 1) round x + weights onto the tf32 grid
    prep_round<<<6656, 256>>>(x, Wq, Wk, Wv, Wo);

    // 2) QKV projections + fused RoPE + permuted head-major stores
    qkv_gemm<<<dim3(12, 32), 256, GEMM_SMEM>>>(cs, sn);

    // 3) attention: grid (8 q-tiles of 256, 16 heads, 2 batch)
    attn_mma<<<dim3(SEQ / 256, NH, BB), 256, ATT_SMEM>>>();

    // 4) output projection
    out_gemm<<<dim3(8, 32), 256, GEMM_SMEM>>>(out);
}

// round 10
// speedup vs baseline: 1.0483x; 1.0483x over previous
#include <cuda_runtime.h>
#include <cstdint>

#define NH   16
#define NKV  4
#define HD   64
#define DM   1024
#define BB   2
#define SEQ  2048
#define MROWS (BB*SEQ)   // 4096

// Q pre-scale: HD^-0.5 * log2(e)  (softmax done in exp2 domain)
#define QSC 0.18033688011112042f

// ---------------------------------------------------------------------------
// Scratch (allocation-free device globals)
// ---------------------------------------------------------------------------
__device__ float g_xr [(size_t)MROWS * DM];       // tf32-rounded x
__device__ float g_wqr[(size_t)DM * DM];
__device__ float g_wkr[(size_t)DM * 256];
__device__ float g_wvr[(size_t)DM * 256];
__device__ float g_wor[(size_t)DM * DM];
__device__ float g_q  [(size_t)BB * NH  * SEQ * HD];  // head-major, d-permuted, *QSC, rope'd
__device__ float g_k  [(size_t)BB * NKV * SEQ * HD];  // head-major, d-permuted, rope'd
__device__ float g_v  [(size_t)BB * NKV * HD * SEQ];  // head-major TRANSPOSED: [d][seq]
__device__ float g_attn[(size_t)MROWS * DM];          // (b,n,1024), tf32-rounded

// ---------------------------------------------------------------------------
// helpers
// ---------------------------------------------------------------------------
__device__ __forceinline__ uint32_t f2tf(float f) {
    uint32_t u;
    asm("cvt.rna.tf32.f32 %0, %1;" : "=r"(u) : "f"(f));
    return u;
}
__device__ __forceinline__ float r2f(uint32_t u) { return __uint_as_float(u); }

__device__ __forceinline__ float ex2f(float x) {
    float r;
    asm("ex2.approx.ftz.f32 %0, %1;" : "=f"(r) : "f"(x));
    return r;
}
__device__ __forceinline__ int perm8p(int j) {
    int u = j & 7;
    return (j & ~7) + ((u < 4) ? 2 * u : 2 * (u - 4) + 1);
}
__device__ __forceinline__ void mma8(float c[4], const uint32_t a[4], const uint32_t b[2]) {
    asm volatile(
        "mma.sync.aligned.m16n8k8.row.col.f32.tf32.tf32.f32 "
        "{%0,%1,%2,%3},{%4,%5,%6,%7},{%8,%9},{%0,%1,%2,%3};"
        : "+f"(c[0]), "+f"(c[1]), "+f"(c[2]), "+f"(c[3])
        : "r"(a[0]), "r"(a[1]), "r"(a[2]), "r"(a[3]), "r"(b[0]), "r"(b[1]));
}
__device__ __forceinline__ void cpa16(uint32_t dst, const void* src) {
    asm volatile("cp.async.cg.shared.global [%0], [%1], 16;" :: "r"(dst), "l"(src) : "memory");
}
#define CPA_COMMIT() asm volatile("cp.async.commit_group;" ::: "memory")

// ---------------------------------------------------------------------------
// Pre-pass: round x + weights to the tf32 grid (then mma can eat them raw).
// ---------------------------------------------------------------------------
__global__ void prep_round(const float* __restrict__ x,  const float* __restrict__ Wq,
                           const float* __restrict__ Wk, const float* __restrict__ Wv,
                           const float* __restrict__ Wo)
{
    size_t i = (size_t)blockIdx.x * 256 + threadIdx.x;   // float4 index
    const float* src; float* dst; size_t off;
    if      (i < 1048576) { src = x;  dst = g_xr;  off = i; }
    else if (i < 1310720) { src = Wq; dst = g_wqr; off = i - 1048576; }
    else if (i < 1376256) { src = Wk; dst = g_wkr; off = i - 1310720; }
    else if (i < 1441792) { src = Wv; dst = g_wvr; off = i - 1376256; }
    else                  { src = Wo; dst = g_wor; off = i - 1441792; }
    float4 v = ((const float4*)src)[off];
    v.x = r2f(f2tf(v.x)); v.y = r2f(f2tf(v.y));
    v.z = r2f(f2tf(v.z)); v.w = r2f(f2tf(v.w));
    ((float4*)dst)[off] = v;
}

// ---------------------------------------------------------------------------
// cp.async 3-stage GEMM: 128x128 tile, kstep 32, 256 threads, warp tile 64x32.
// Stage: As[128][40] (5120 w) + Bs[32][132] (4224 w) = 9344 words.
// ---------------------------------------------------------------------------
#define GSTAGE 9344
#define GEMM_SMEM (3 * GSTAGE * 4)   // 112128 B

__device__ __forceinline__ void gemm_main(uint32_t* sm, uint32_t smb,
    const float* __restrict__ A, const float* __restrict__ B,
    int ldb, int n0, int row0, float acc[4][4][4])
{
    const int K = DM, KT = DM / 32;
    const int tid = threadIdx.x, lane = tid & 31, wid = tid >> 5;
    const int g = lane >> 2, t = lane & 3;
    const int m0 = (wid >> 2) * 64, nw = (wid & 3) * 32;

    const int ar = tid >> 3, ac = (tid & 7) << 2;
    const int bk = tid >> 5, bn = (tid & 31) << 2;
    const uint32_t aDst = (ar * 40 + ac) * 4;
    const uint32_t bDst = (5120 + bk * 132 + bn) * 4;
    const float* aS = A + (size_t)(row0 + ar) * K + ac;
    const float* bS = B + (size_t)bk * ldb + n0 + bn;

    auto issue = [&](int slot, int kt) {
        uint32_t base = smb + slot * (GSTAGE * 4);
        const float* a = aS + kt * 32;
        const float* b = bS + (size_t)kt * 32 * ldb;
#pragma unroll
        for (int i = 0; i < 4; i++)
            cpa16(base + aDst + i * (32 * 40 * 4), a + (size_t)i * 32 * K);
#pragma unroll
        for (int i = 0; i < 4; i++)
            cpa16(base + bDst + i * (8 * 132 * 4), b + (size_t)i * 8 * ldb);
        CPA_COMMIT();
    };

#pragma unroll
    for (int mi = 0; mi < 4; mi++)
#pragma unroll
        for (int ni = 0; ni < 4; ni++)
#pragma unroll
            for (int r = 0; r < 4; r++) acc[mi][ni][r] = 0.f;

    issue(0, 0);
    issue(1, 1);

    for (int kt = 0; kt < KT; kt++) {
        if (kt + 1 < KT) asm volatile("cp.async.wait_group 1;" ::: "memory");
        else             asm volatile("cp.async.wait_group 0;" ::: "memory");
        __syncthreads();
        if (kt + 2 < KT) issue((kt + 2) % 3, kt + 2);

        uint32_t* st = sm + (kt % 3) * GSTAGE;
        uint32_t (*As)[40]  = (uint32_t(*)[40])st;
        uint32_t (*Bs)[132] = (uint32_t(*)[132])(st + 5120);
#pragma unroll
        for (int kk0 = 0; kk0 < 32; kk0 += 8) {
            uint32_t a[4][4], b[4][2];
#pragma unroll
            for (int mi = 0; mi < 4; mi++) {
                int rb = m0 + mi * 16 + g;
                uint2 av0 = *(const uint2*)&As[rb][kk0 + 2 * t];
                uint2 av1 = *(const uint2*)&As[rb + 8][kk0 + 2 * t];
                a[mi][0] = av0.x; a[mi][1] = av1.x; a[mi][2] = av0.y; a[mi][3] = av1.y;
            }
#pragma unroll
            for (int ni = 0; ni < 4; ni++) {
                b[ni][0] = Bs[kk0 + 2 * t][nw + ni * 8 + g];
                b[ni][1] = Bs[kk0 + 2 * t + 1][nw + ni * 8 + g];
            }
#pragma unroll
            for (int mi = 0; mi < 4; mi++)
#pragma unroll
                for (int ni = 0; ni < 4; ni++)
                    mma8(acc[mi][ni], a[mi], b[ni]);
        }
    }
}

// ---------------------------------------------------------------------------
// QKV projection + fused RoPE + permuted head-major stores (V transposed).
// ---------------------------------------------------------------------------
__global__ __launch_bounds__(256, 2) void qkv_gemm(
    const float* __restrict__ cs, const float* __restrict__ sn)
{
    extern __shared__ uint32_t sm[];
    uint32_t smb = (uint32_t)__cvta_generic_to_shared(sm);
    const int bx = blockIdx.x, row0 = blockIdx.y * 128;
    const int tid = threadIdx.x, lane = tid & 31, wid = tid >> 5;
    const int g = lane >> 2, t = lane & 3;
    const int m0 = (wid >> 2) * 64, nw = (wid & 3) * 32;
    float acc[4][4][4];

    if (bx < 8) {
        gemm_main(sm, smb, g_xr, g_wqr, DM, bx * 128, row0, acc);
#pragma unroll
        for (int mi = 0; mi < 4; mi++)
#pragma unroll
            for (int ni = 0; ni < 4; ni++) {
                int gc = bx * 128 + nw + ni * 8 + 2 * t;       // even original col
                int head = gc >> 6, j = (gc & 63) >> 1;
                int pj = perm8p(j), pj2 = perm8p(j + 32);
#pragma unroll
                for (int rr = 0; rr < 2; rr++) {
                    int row = row0 + m0 + mi * 16 + g + rr * 8;
                    int n = row & (SEQ - 1), bi = row >> 11;
                    float cv = cs[n * 32 + j], sv = sn[n * 32 + j];
                    float a0 = acc[mi][ni][rr * 2], a1 = acc[mi][ni][rr * 2 + 1];
                    size_t bp = ((size_t)(bi * NH + head) * SEQ + n) * HD;
                    g_q[bp + pj]  = r2f(f2tf((a0 * cv - a1 * sv) * QSC));
                    g_q[bp + pj2] = r2f(f2tf((a0 * sv + a1 * cv) * QSC));
                }
            }
    } else if (bx < 10) {
        gemm_main(sm, smb, g_xr, g_wkr, 256, (bx - 8) * 128, row0, acc);
#pragma unroll
        for (int mi = 0; mi < 4; mi++)
#pragma unroll
            for (int ni = 0; ni < 4; ni++) {
                int gc = (bx - 8) * 128 + nw + ni * 8 + 2 * t;
                int kvh = gc >> 6, j = (gc & 63) >> 1;
                int pj = perm8p(j), pj2 = perm8p(j + 32);
#pragma unroll
                for (int rr = 0; rr < 2; rr++) {
                    int row = row0 + m0 + mi * 16 + g + rr * 8;
                    int n = row & (SEQ - 1), bi = row >> 11;
                    float cv = cs[n * 32 + j], sv = sn[n * 32 + j];
                    float a0 = acc[mi][ni][rr * 2], a1 = acc[mi][ni][rr * 2 + 1];
                    size_t bp = ((size_t)(bi * NKV + kvh) * SEQ + n) * HD;
                    g_k[bp + pj]  = r2f(f2tf(a0 * cv - a1 * sv));
                    g_k[bp + pj2] = r2f(f2tf(a0 * sv + a1 * cv));
                }
            }
    } else {
        gemm_main(sm, smb, g_xr, g_wvr, 256, (bx - 10) * 128, row0, acc);
#pragma unroll
        for (int mi = 0; mi < 4; mi++)
#pragma unroll
            for (int ni = 0; ni < 4; ni++) {
                int gc = (bx - 10) * 128 + nw + ni * 8 + 2 * t;
                int kvh = gc >> 6, d = gc & 63;
#pragma unroll
                for (int rr = 0; rr < 2; rr++) {
                    int row = row0 + m0 + mi * 16 + g + rr * 8;
                    int n = row & (SEQ - 1), bi = row >> 11;
                    size_t hb = ((size_t)(bi * NKV + kvh) * HD);
                    g_v[(hb + d) * SEQ + n]     = r2f(f2tf(acc[mi][ni][rr * 2]));
                    g_v[(hb + d + 1) * SEQ + n] = r2f(f2tf(acc[mi][ni][rr * 2 + 1]));
                }
            }
    }
}

// ---------------------------------------------------------------------------
// Output projection
// ---------------------------------------------------------------------------
__global__ __launch_bounds__(256, 2) void out_gemm(float* __restrict__ out)
{
    extern __shared__ uint32_t sm[];
    uint32_t smb = (uint32_t)__cvta_generic_to_shared(sm);
    const int tid = threadIdx.x, lane = tid & 31, wid = tid >> 5;
    const int g = lane >> 2, t = lane & 3;
    const int m0 = (wid >> 2) * 64, nw = (wid & 3) * 32;
    const int n0 = blockIdx.x * 128, row0 = blockIdx.y * 128;
    float acc[4][4][4];
    gemm_main(sm, smb, g_attn, g_wor, DM, n0, row0, acc);
#pragma unroll
    for (int mi = 0; mi < 4; mi++) {
        int r = row0 + m0 + mi * 16 + g;
#pragma unroll
        for (int ni = 0; ni < 4; ni++) {
            int c = n0 + nw + ni * 8 + 2 * t;
            *(float2*)(out + (size_t)r * DM + c)       = make_float2(acc[mi][ni][0], acc[mi][ni][1]);
            *(float2*)(out + (size_t)(r + 8) * DM + c) = make_float2(acc[mi][ni][2], acc[mi][ni][3]);
        }
    }
}

// ---------------------------------------------------------------------------
// Flash attention: BM=256, 512 threads (16 warps), 1 CTA/SM, 4-stage KV ring,
// TWO KV blocks processed per barrier (16 barriers total instead of 32).
// V transposed (d x keys); softmax in exp2 domain (QSC pre-scale).
// Smem (u32): Qs[256*72]=18432 | 4 stages x (Ks[64*72]+Vt[64*72]=9216)
// = 55296 words = 221184 B.
// ---------------------------------------------------------------------------
#define ATT_SMEM 221184

__device__ __forceinline__ void attn_issue_kv(uint32_t smb, int slot,
    const float* __restrict__ Kb, const float* __restrict__ Vb, int kt, int tid)
{
    uint32_t base = smb + (18432 + slot * 9216) * 4;
    const float* K0 = Kb + (size_t)kt * 64 * HD;
#pragma unroll
    for (int i = 0; i < 2; i++) {
        int c = tid + i * 512;
        int r = c >> 4, col = (c & 15) << 2;
        cpa16(base + (r * 72 + col) * 4, K0 + r * HD + col);
    }
#pragma unroll
    for (int i = 0; i < 2; i++) {
        int c = tid + i * 512;
        int r = c >> 4, col = (c & 15) << 2;
        cpa16(base + (4608 + r * 72 + col) * 4, Vb + (size_t)r * SEQ + kt * 64 + col);
    }
    CPA_COMMIT();
}

// S = Q*K^T for this warp's 16 rows x 64 keys (exp2 domain via QSC prescale)
__device__ __forceinline__ void s_gemm(float s[8][4],
    const uint32_t* Qs, const uint32_t* Ks, int m0, int g, int t)
{
#pragma unroll
    for (int ni = 0; ni < 8; ni++)
#pragma unroll
        for (int r = 0; r < 4; r++) s[ni][r] = 0.f;
#pragma unroll
    for (int kk = 0; kk < 8; kk++) {
        uint32_t a[4];
        uint2 p0 = *(const uint2*)&Qs[(m0 + g) * 72 + kk * 8 + 2 * t];
        uint2 p1 = *(const uint2*)&Qs[(m0 + g + 8) * 72 + kk * 8 + 2 * t];
        a[0] = p0.x; a[1] = p1.x; a[2] = p0.y; a[3] = p1.y;
#pragma unroll
        for (int ni = 0; ni < 8; ni++) {
            uint2 bv = *(const uint2*)&Ks[(ni * 8 + g) * 72 + kk * 8 + 2 * t];
            uint32_t bb[2] = {bv.x, bv.y};
            mma8(s[ni], a, bb);
        }
    }
}

// online-softmax update on s + rescale o + O += P*V from Vt stage
__device__ __forceinline__ void softmax_pv(float s[8][4], float o[8][4],
    float& m0s, float& m1s, float& l0s, float& l1s,
    const uint32_t* Vt, int g, int t)
{
    float mx0 = -1e30f, mx1 = -1e30f;
#pragma unroll
    for (int ni = 0; ni < 8; ni++) {
        mx0 = fmaxf(mx0, fmaxf(s[ni][0], s[ni][1]));
        mx1 = fmaxf(mx1, fmaxf(s[ni][2], s[ni][3]));
    }
    mx0 = fmaxf(mx0, __shfl_xor_sync(0xffffffffu, mx0, 1));
    mx0 = fmaxf(mx0, __shfl_xor_sync(0xffffffffu, mx0, 2));
    mx1 = fmaxf(mx1, __shfl_xor_sync(0xffffffffu, mx1, 1));
    mx1 = fmaxf(mx1, __shfl_xor_sync(0xffffffffu, mx1, 2));

    float mn0 = fmaxf(m0s, mx0), mn1 = fmaxf(m1s, mx1);
    float cor0 = ex2f(m0s - mn0), cor1 = ex2f(m1s - mn1);
    m0s = mn0; m1s = mn1;

    float rs0 = 0.f, rs1 = 0.f;
#pragma unroll
    for (int ni = 0; ni < 8; ni++) {
        s[ni][0] = ex2f(s[ni][0] - mn0);
        s[ni][1] = ex2f(s[ni][1] - mn0);
        s[ni][2] = ex2f(s[ni][2] - mn1);
        s[ni][3] = ex2f(s[ni][3] - mn1);
        rs0 += s[ni][0] + s[ni][1];
        rs1 += s[ni][2] + s[ni][3];
    }
    rs0 += __shfl_xor_sync(0xffffffffu, rs0, 1);
    rs0 += __shfl_xor_sync(0xffffffffu, rs0, 2);
    rs1 += __shfl_xor_sync(0xffffffffu, rs1, 1);
    rs1 += __shfl_xor_sync(0xffffffffu, rs1, 2);
    l0s = l0s * cor0 + rs0;
    l1s = l1s * cor1 + rs1;

#pragma unroll
    for (int ni = 0; ni < 8; ni++) {
        o[ni][0] *= cor0; o[ni][1] *= cor0;
        o[ni][2] *= cor1; o[ni][3] *= cor1;
    }
#pragma unroll
    for (int kk = 0; kk < 8; kk++) {
        uint32_t a[4];
        a[0] = f2tf(s[kk][0]);
        a[1] = f2tf(s[kk][2]);
        a[2] = f2tf(s[kk][1]);
        a[3] = f2tf(s[kk][3]);
#pragma unroll
        for (int ni = 0; ni < 8; ni++) {
            uint2 bv = *(const uint2*)&Vt[(ni * 8 + g) * 72 + kk * 8 + 2 * t];
            uint32_t bb[2] = {bv.x, bv.y};
            mma8(o[ni], a, bb);
        }
    }
}

__global__ __launch_bounds__(512, 1) void attn_mma()
{
    extern __shared__ uint32_t sm[];
    uint32_t smb = (uint32_t)__cvta_generic_to_shared(sm);
    const int b = blockIdx.z, h = blockIdx.y;
    const int n0 = blockIdx.x * 256;
    const int kvh = h >> 2;
    const int tid = threadIdx.x, lane = tid & 31, wid = tid >> 5;  // wid 0..15
    const int g = lane >> 2, t = lane & 3;
    const int m0 = wid * 16;

    const float* Qb = g_q + ((size_t)(b * NH + h) * SEQ + n0) * HD;
    const float* Kb = g_k + ((size_t)(b * NKV + kvh) * SEQ) * HD;
    const float* Vb = g_v + ((size_t)(b * NKV + kvh) * HD) * SEQ;

    // Q tile: 256 rows x 64 words (own commit group)
#pragma unroll
    for (int i = 0; i < 8; i++) {
        int c = tid + i * 512;
        int r = c >> 4, col = (c & 15) << 2;
        cpa16(smb + (r * 72 + col) * 4, Qb + r * HD + col);
    }
    CPA_COMMIT();
    attn_issue_kv(smb, 0, Kb, Vb, 0, tid);
    attn_issue_kv(smb, 1, Kb, Vb, 1, tid);

    uint32_t* Qs = sm;
    float m0s = -1e30f, m1s = -1e30f, l0s = 0.f, l1s = 0.f;
    float s[8][4], o[8][4];
#pragma unroll
    for (int ni = 0; ni < 8; ni++)
#pragma unroll
        for (int r = 0; r < 4; r++) o[ni][r] = 0.f;

    const int KT = SEQ / 64;   // 32 (even), processed in pairs
    for (int kt = 0; kt < KT; kt += 2) {
        // stages kt and kt+1 must be resident (Q group also covered on first pass)
        asm volatile("cp.async.wait_group 0;" ::: "memory");
        __syncthreads();   // all warps done with pair kt-2/kt-1 -> slots reusable
        if (kt + 2 < KT) attn_issue_kv(smb, (kt + 2) & 3, Kb, Vb, kt + 2, tid);
        if (kt + 3 < KT) attn_issue_kv(smb, (kt + 3) & 3, Kb, Vb, kt + 3, tid);

        // block kt
        {
            uint32_t* Ks = sm + 18432 + (kt & 3) * 9216;
            s_gemm(s, Qs, Ks, m0, g, t);
            softmax_pv(s, o, m0s, m1s, l0s, l1s, Ks + 4608, g, t);
        }
        // block kt+1
        {
            uint32_t* Ks = sm + 18432 + ((kt + 1) & 3) * 9216;
            s_gemm(s, Qs, Ks, m0, g, t);
            softmax_pv(s, o, m0s, m1s, l0s, l1s, Ks + 4608, g, t);
        }
    }

    // epilogue: normalize, round to tf32, write (b,n,1024) for out_gemm
    float inv0 = 1.f / l0s, inv1 = 1.f / l1s;
    size_t r0 = (size_t)b * SEQ + n0 + m0 + g;
#pragma unroll
    for (int ni = 0; ni < 8; ni++) {
        int col = h * HD + ni * 8 + 2 * t;
        *(float2*)&g_attn[r0 * DM + col] =
            make_float2(r2f(f2tf(o[ni][0] * inv0)), r2f(f2tf(o[ni][1] * inv0)));
        *(float2*)&g_attn[(r0 + 8) * DM + col] =
            make_float2(r2f(f2tf(o[ni][2] * inv1)), r2f(f2tf(o[ni][3] * inv1)));
    }
}

// ---------------------------------------------------------------------------
extern "C" void kernel_launch(void* const* d_in, const int* in_sizes, int n_in,
                              void* d_out, int out_size)
{
    const float* x  = (const float*)d_in[0];
    const float* cs = (const float*)d_in[1];
    const float* sn = (const float*)d_in[2];
    const float* Wq = (const float*)d_in[3];
    const float* Wk = (const float*)d_in[4];
    const float* Wv = (const float*)d_in[5];
    const float* Wo = (const float*)d_in[6];
    float* out = (float*)d_out;
    (void)in_sizes; (void)n_in; (void)out_size;

    cudaFuncSetAttribute(qkv_gemm, cudaFuncAttributeMaxDynamicSharedMemorySize, GEMM_SMEM);
    cudaFuncSetAttribute(out_gemm, cudaFuncAttributeMaxDynamicSharedMemorySize, GEMM_SMEM);
    cudaFuncSetAttribute(attn_mma, cudaFuncAttributeMaxDynamicSharedMemorySize, ATT_SMEM);

    // 1) round x + weights onto the tf32 grid
    prep_round<<<6656, 256>>>(x, Wq, Wk, Wv, Wo);

    // 2) QKV projections + fused RoPE + permuted head-major stores
    qkv_gemm<<<dim3(12, 32), 256, GEMM_SMEM>>>(cs, sn);

    // 3) attention: grid (8 q-tiles of 256, 16 heads, 2 batch)
    attn_mma<<<dim3(SEQ / 256, NH, BB), 512, ATT_SMEM>>>();

    // 4) output projection
    out_gemm<<<dim3(8, 32), 256, GEMM_SMEM>>>(out);
}

// round 11
// speedup vs baseline: 1.0613x; 1.0124x over previous
#include <cuda_runtime.h>
#include <cstdint>

#define NH   16
#define NKV  4
#define HD   64
#define DM   1024
#define BB   2
#define SEQ  2048
#define MROWS (BB*SEQ)   // 4096

// Q pre-scale: HD^-0.5 * log2(e)  (softmax done in exp2 domain)
#define QSC 0.18033688011112042f

// ---------------------------------------------------------------------------
// Scratch (allocation-free device globals)
// ---------------------------------------------------------------------------
__device__ float g_xr [(size_t)MROWS * DM];       // tf32-rounded x
__device__ float g_wqr[(size_t)DM * DM];
__device__ float g_wkr[(size_t)DM * 256];
__device__ float g_wvr[(size_t)DM * 256];
__device__ float g_wor[(size_t)DM * DM];
__device__ float g_q  [(size_t)BB * NH  * SEQ * HD];  // head-major, d-permuted, *QSC, rope'd
__device__ float g_k  [(size_t)BB * NKV * SEQ * HD];  // head-major, d-permuted, rope'd
__device__ float g_v  [(size_t)BB * NKV * HD * SEQ];  // head-major TRANSPOSED: [d][seq]
__device__ float g_attn[(size_t)MROWS * DM];          // (b,n,1024), tf32-rounded

// ---------------------------------------------------------------------------
// helpers
// ---------------------------------------------------------------------------
__device__ __forceinline__ uint32_t f2tf(float f) {
    uint32_t u;
    asm("cvt.rna.tf32.f32 %0, %1;" : "=r"(u) : "f"(f));
    return u;
}
__device__ __forceinline__ float r2f(uint32_t u) { return __uint_as_float(u); }

__device__ __forceinline__ float ex2f(float x) {
    float r;
    asm("ex2.approx.ftz.f32 %0, %1;" : "=f"(r) : "f"(x));
    return r;
}
__device__ __forceinline__ int perm8p(int j) {
    int u = j & 7;
    return (j & ~7) + ((u < 4) ? 2 * u : 2 * (u - 4) + 1);
}
__device__ __forceinline__ void mma8(float c[4], const uint32_t a[4], const uint32_t b[2]) {
    asm volatile(
        "mma.sync.aligned.m16n8k8.row.col.f32.tf32.tf32.f32 "
        "{%0,%1,%2,%3},{%4,%5,%6,%7},{%8,%9},{%0,%1,%2,%3};"
        : "+f"(c[0]), "+f"(c[1]), "+f"(c[2]), "+f"(c[3])
        : "r"(a[0]), "r"(a[1]), "r"(a[2]), "r"(a[3]), "r"(b[0]), "r"(b[1]));
}
__device__ __forceinline__ void cpa16(uint32_t dst, const void* src) {
    asm volatile("cp.async.cg.shared.global [%0], [%1], 16;" :: "r"(dst), "l"(src) : "memory");
}
#define CPA_COMMIT() asm volatile("cp.async.commit_group;" ::: "memory")

// ---------------------------------------------------------------------------
// Pre-pass: round x + weights to the tf32 grid (then mma can eat them raw).
// ---------------------------------------------------------------------------
__global__ void prep_round(const float* __restrict__ x,  const float* __restrict__ Wq,
                           const float* __restrict__ Wk, const float* __restrict__ Wv,
                           const float* __restrict__ Wo)
{
    size_t i = (size_t)blockIdx.x * 256 + threadIdx.x;   // float4 index
    const float* src; float* dst; size_t off;
    if      (i < 1048576) { src = x;  dst = g_xr;  off = i; }
    else if (i < 1310720) { src = Wq; dst = g_wqr; off = i - 1048576; }
    else if (i < 1376256) { src = Wk; dst = g_wkr; off = i - 1310720; }
    else if (i < 1441792) { src = Wv; dst = g_wvr; off = i - 1376256; }
    else                  { src = Wo; dst = g_wor; off = i - 1441792; }
    float4 v = ((const float4*)src)[off];
    v.x = r2f(f2tf(v.x)); v.y = r2f(f2tf(v.y));
    v.z = r2f(f2tf(v.z)); v.w = r2f(f2tf(v.w));
    ((float4*)dst)[off] = v;
}

// ---------------------------------------------------------------------------
// cp.async 3-stage GEMM: 128x128 tile, kstep 32, 256 threads, warp tile 64x32.
// Stage: As[128][40] (5120 w) + Bs[32][132] (4224 w) = 9344 words.
// ---------------------------------------------------------------------------
#define GSTAGE 9344
#define GEMM_SMEM (3 * GSTAGE * 4)   // 112128 B

__device__ __forceinline__ void gemm_main(uint32_t* sm, uint32_t smb,
    const float* __restrict__ A, const float* __restrict__ B,
    int ldb, int n0, int row0, float acc[4][4][4])
{
    const int K = DM, KT = DM / 32;
    const int tid = threadIdx.x, lane = tid & 31, wid = tid >> 5;
    const int g = lane >> 2, t = lane & 3;
    const int m0 = (wid >> 2) * 64, nw = (wid & 3) * 32;

    const int ar = tid >> 3, ac = (tid & 7) << 2;
    const int bk = tid >> 5, bn = (tid & 31) << 2;
    const uint32_t aDst = (ar * 40 + ac) * 4;
    const uint32_t bDst = (5120 + bk * 132 + bn) * 4;
    const float* aS = A + (size_t)(row0 + ar) * K + ac;
    const float* bS = B + (size_t)bk * ldb + n0 + bn;

    auto issue = [&](int slot, int kt) {
        uint32_t base = smb + slot * (GSTAGE * 4);
        const float* a = aS + kt * 32;
        const float* b = bS + (size_t)kt * 32 * ldb;
#pragma unroll
        for (int i = 0; i < 4; i++)
            cpa16(base + aDst + i * (32 * 40 * 4), a + (size_t)i * 32 * K);
#pragma unroll
        for (int i = 0; i < 4; i++)
            cpa16(base + bDst + i * (8 * 132 * 4), b + (size_t)i * 8 * ldb);
        CPA_COMMIT();
    };

#pragma unroll
    for (int mi = 0; mi < 4; mi++)
#pragma unroll
        for (int ni = 0; ni < 4; ni++)
#pragma unroll
            for (int r = 0; r < 4; r++) acc[mi][ni][r] = 0.f;

    issue(0, 0);
    issue(1, 1);

    for (int kt = 0; kt < KT; kt++) {
        if (kt + 1 < KT) asm volatile("cp.async.wait_group 1;" ::: "memory");
        else             asm volatile("cp.async.wait_group 0;" ::: "memory");
        __syncthreads();
        if (kt + 2 < KT) issue((kt + 2) % 3, kt + 2);

        uint32_t* st = sm + (kt % 3) * GSTAGE;
        uint32_t (*As)[40]  = (uint32_t(*)[40])st;
        uint32_t (*Bs)[132] = (uint32_t(*)[132])(st + 5120);
#pragma unroll
        for (int kk0 = 0; kk0 < 32; kk0 += 8) {
            uint32_t a[4][4], b[4][2];
#pragma unroll
            for (int mi = 0; mi < 4; mi++) {
                int rb = m0 + mi * 16 + g;
                uint2 av0 = *(const uint2*)&As[rb][kk0 + 2 * t];
                uint2 av1 = *(const uint2*)&As[rb + 8][kk0 + 2 * t];
                a[mi][0] = av0.x; a[mi][1] = av1.x; a[mi][2] = av0.y; a[mi][3] = av1.y;
            }
#pragma unroll
            for (int ni = 0; ni < 4; ni++) {
                b[ni][0] = Bs[kk0 + 2 * t][nw + ni * 8 + g];
                b[ni][1] = Bs[kk0 + 2 * t + 1][nw + ni * 8 + g];
            }
#pragma unroll
            for (int mi = 0; mi < 4; mi++)
#pragma unroll
                for (int ni = 0; ni < 4; ni++)
                    mma8(acc[mi][ni], a[mi], b[ni]);
        }
    }
}

// ---------------------------------------------------------------------------
// QKV projection + fused RoPE + permuted head-major stores (V transposed).
// ---------------------------------------------------------------------------
__global__ __launch_bounds__(256, 2) void qkv_gemm(
    const float* __restrict__ cs, const float* __restrict__ sn)
{
    extern __shared__ uint32_t sm[];
    uint32_t smb = (uint32_t)__cvta_generic_to_shared(sm);
    const int bx = blockIdx.x, row0 = blockIdx.y * 128;
    const int tid = threadIdx.x, lane = tid & 31, wid = tid >> 5;
    const int g = lane >> 2, t = lane & 3;
    const int m0 = (wid >> 2) * 64, nw = (wid & 3) * 32;
    float acc[4][4][4];

    if (bx < 8) {
        gemm_main(sm, smb, g_xr, g_wqr, DM, bx * 128, row0, acc);
#pragma unroll
        for (int mi = 0; mi < 4; mi++)
#pragma unroll
            for (int ni = 0; ni < 4; ni++) {
                int gc = bx * 128 + nw + ni * 8 + 2 * t;       // even original col
                int head = gc >> 6, j = (gc & 63) >> 1;
                int pj = perm8p(j), pj2 = perm8p(j + 32);
#pragma unroll
                for (int rr = 0; rr < 2; rr++) {
                    int row = row0 + m0 + mi * 16 + g + rr * 8;
                    int n = row & (SEQ - 1), bi = row >> 11;
                    float cv = cs[n * 32 + j], sv = sn[n * 32 + j];
                    float a0 = acc[mi][ni][rr * 2], a1 = acc[mi][ni][rr * 2 + 1];
                    size_t bp = ((size_t)(bi * NH + head) * SEQ + n) * HD;
                    g_q[bp + pj]  = r2f(f2tf((a0 * cv - a1 * sv) * QSC));
                    g_q[bp + pj2] = r2f(f2tf((a0 * sv + a1 * cv) * QSC));
                }
            }
    } else if (bx < 10) {
        gemm_main(sm, smb, g_xr, g_wkr, 256, (bx - 8) * 128, row0, acc);
#pragma unroll
        for (int mi = 0; mi < 4; mi++)
#pragma unroll
            for (int ni = 0; ni < 4; ni++) {
                int gc = (bx - 8) * 128 + nw + ni * 8 + 2 * t;
                int kvh = gc >> 6, j = (gc & 63) >> 1;
                int pj = perm8p(j), pj2 = perm8p(j + 32);
#pragma unroll
                for (int rr = 0; rr < 2; rr++) {
                    int row = row0 + m0 + mi * 16 + g + rr * 8;
                    int n = row & (SEQ - 1), bi = row >> 11;
                    float cv = cs[n * 32 + j], sv = sn[n * 32 + j];
                    float a0 = acc[mi][ni][rr * 2], a1 = acc[mi][ni][rr * 2 + 1];
                    size_t bp = ((size_t)(bi * NKV + kvh) * SEQ + n) * HD;
                    g_k[bp + pj]  = r2f(f2tf(a0 * cv - a1 * sv));
                    g_k[bp + pj2] = r2f(f2tf(a0 * sv + a1 * cv));
                }
            }
    } else {
        gemm_main(sm, smb, g_xr, g_wvr, 256, (bx - 10) * 128, row0, acc);
#pragma unroll
        for (int mi = 0; mi < 4; mi++)
#pragma unroll
            for (int ni = 0; ni < 4; ni++) {
                int gc = (bx - 10) * 128 + nw + ni * 8 + 2 * t;
                int kvh = gc >> 6, d = gc & 63;
#pragma unroll
                for (int rr = 0; rr < 2; rr++) {
                    int row = row0 + m0 + mi * 16 + g + rr * 8;
                    int n = row & (SEQ - 1), bi = row >> 11;
                    size_t hb = ((size_t)(bi * NKV + kvh) * HD);
                    g_v[(hb + d) * SEQ + n]     = r2f(f2tf(acc[mi][ni][rr * 2]));
                    g_v[(hb + d + 1) * SEQ + n] = r2f(f2tf(acc[mi][ni][rr * 2 + 1]));
                }
            }
    }
}

// ---------------------------------------------------------------------------
// Output projection
// ---------------------------------------------------------------------------
__global__ __launch_bounds__(256, 2) void out_gemm(float* __restrict__ out)
{
    extern __shared__ uint32_t sm[];
    uint32_t smb = (uint32_t)__cvta_generic_to_shared(sm);
    const int tid = threadIdx.x, lane = tid & 31, wid = tid >> 5;
    const int g = lane >> 2, t = lane & 3;
    const int m0 = (wid >> 2) * 64, nw = (wid & 3) * 32;
    const int n0 = blockIdx.x * 128, row0 = blockIdx.y * 128;
    float acc[4][4][4];
    gemm_main(sm, smb, g_attn, g_wor, DM, n0, row0, acc);
#pragma unroll
    for (int mi = 0; mi < 4; mi++) {
        int r = row0 + m0 + mi * 16 + g;
#pragma unroll
        for (int ni = 0; ni < 4; ni++) {
            int c = n0 + nw + ni * 8 + 2 * t;
            *(float2*)(out + (size_t)r * DM + c)       = make_float2(acc[mi][ni][0], acc[mi][ni][1]);
            *(float2*)(out + (size_t)(r + 8) * DM + c) = make_float2(acc[mi][ni][2], acc[mi][ni][3]);
        }
    }
}

// ---------------------------------------------------------------------------
// Flash attention: BM=256, 512 threads (16 warps), 1 CTA/SM.
// Q held in REGISTERS (loaded once from pre-rounded g_q — raw bits are on the
// tf32 grid, so feeding them to mma is bit-identical to cvt). No Qs smem.
// 6-stage KV ring, TWO KV blocks per barrier (16 barriers, prefetch 2 pairs).
// V transposed (d x keys); softmax in exp2 domain (QSC pre-scale).
// Smem (u32): 6 stages x (Ks[64*72]+Vt[64*72]=9216) = 55296 words = 221184 B.
// ---------------------------------------------------------------------------
#define ATT_SMEM 221184

__device__ __forceinline__ void attn_issue_kv(uint32_t smb, int slot,
    const float* __restrict__ Kb, const float* __restrict__ Vb, int kt, int tid)
{
    uint32_t base = smb + slot * 9216 * 4;
    const float* K0 = Kb + (size_t)kt * 64 * HD;
#pragma unroll
    for (int i = 0; i < 2; i++) {
        int c = tid + i * 512;
        int r = c >> 4, col = (c & 15) << 2;
        cpa16(base + (r * 72 + col) * 4, K0 + r * HD + col);
    }
#pragma unroll
    for (int i = 0; i < 2; i++) {
        int c = tid + i * 512;
        int r = c >> 4, col = (c & 15) << 2;
        cpa16(base + (4608 + r * 72 + col) * 4, Vb + (size_t)r * SEQ + kt * 64 + col);
    }
    CPA_COMMIT();
}

// S = Q*K^T with Q a-frags in registers
__device__ __forceinline__ void s_gemm_q(float s[8][4],
    const uint32_t q[8][4], const uint32_t* Ks, int g, int t)
{
#pragma unroll
    for (int ni = 0; ni < 8; ni++)
#pragma unroll
        for (int r = 0; r < 4; r++) s[ni][r] = 0.f;
#pragma unroll
    for (int kk = 0; kk < 8; kk++) {
#pragma unroll
        for (int ni = 0; ni < 8; ni++) {
            uint2 bv = *(const uint2*)&Ks[(ni * 8 + g) * 72 + kk * 8 + 2 * t];
            uint32_t bb[2] = {bv.x, bv.y};
            mma8(s[ni], q[kk], bb);
        }
    }
}

// online-softmax update on s + rescale o + O += P*V from Vt stage
__device__ __forceinline__ void softmax_pv(float s[8][4], float o[8][4],
    float& m0s, float& m1s, float& l0s, float& l1s,
    const uint32_t* Vt, int g, int t)
{
    float mx0 = -1e30f, mx1 = -1e30f;
#pragma unroll
    for (int ni = 0; ni < 8; ni++) {
        mx0 = fmaxf(mx0, fmaxf(s[ni][0], s[ni][1]));
        mx1 = fmaxf(mx1, fmaxf(s[ni][2], s[ni][3]));
    }
    mx0 = fmaxf(mx0, __shfl_xor_sync(0xffffffffu, mx0, 1));
    mx0 = fmaxf(mx0, __shfl_xor_sync(0xffffffffu, mx0, 2));
    mx1 = fmaxf(mx1, __shfl_xor_sync(0xffffffffu, mx1, 1));
    mx1 = fmaxf(mx1, __shfl_xor_sync(0xffffffffu, mx1, 2));

    float mn0 = fmaxf(m0s, mx0), mn1 = fmaxf(m1s, mx1);
    float cor0 = ex2f(m0s - mn0), cor1 = ex2f(m1s - mn1);
    m0s = mn0; m1s = mn1;

    float rs0 = 0.f, rs1 = 0.f;
#pragma unroll
    for (int ni = 0; ni < 8; ni++) {
        s[ni][0] = ex2f(s[ni][0] - mn0);
        s[ni][1] = ex2f(s[ni][1] - mn0);
        s[ni][2] = ex2f(s[ni][2] - mn1);
        s[ni][3] = ex2f(s[ni][3] - mn1);
        rs0 += s[ni][0] + s[ni][1];
        rs1 += s[ni][2] + s[ni][3];
    }
    rs0 += __shfl_xor_sync(0xffffffffu, rs0, 1);
    rs0 += __shfl_xor_sync(0xffffffffu, rs0, 2);
    rs1 += __shfl_xor_sync(0xffffffffu, rs1, 1);
    rs1 += __shfl_xor_sync(0xffffffffu, rs1, 2);
    l0s = l0s * cor0 + rs0;
    l1s = l1s * cor1 + rs1;

#pragma unroll
    for (int ni = 0; ni < 8; ni++) {
        o[ni][0] *= cor0; o[ni][1] *= cor0;
        o[ni][2] *= cor1; o[ni][3] *= cor1;
    }
#pragma unroll
    for (int kk = 0; kk < 8; kk++) {
        uint32_t a[4];
        a[0] = f2tf(s[kk][0]);
        a[1] = f2tf(s[kk][2]);
        a[2] = f2tf(s[kk][1]);
        a[3] = f2tf(s[kk][3]);
#pragma unroll
        for (int ni = 0; ni < 8; ni++) {
            uint2 bv = *(const uint2*)&Vt[(ni * 8 + g) * 72 + kk * 8 + 2 * t];
            uint32_t bb[2] = {bv.x, bv.y};
            mma8(o[ni], a, bb);
        }
    }
}

__global__ __launch_bounds__(512, 1) void attn_mma()
{
    extern __shared__ uint32_t sm[];
    uint32_t smb = (uint32_t)__cvta_generic_to_shared(sm);
    const int b = blockIdx.z, h = blockIdx.y;
    const int n0 = blockIdx.x * 256;
    const int kvh = h >> 2;
    const int tid = threadIdx.x, lane = tid & 31, wid = tid >> 5;  // wid 0..15
    const int g = lane >> 2, t = lane & 3;
    const int m0 = wid * 16;

    const float* Kb = g_k + ((size_t)(b * NKV + kvh) * SEQ) * HD;
    const float* Vb = g_v + ((size_t)(b * NKV + kvh) * HD) * SEQ;

    // prefetch 4 KV stages
    attn_issue_kv(smb, 0, Kb, Vb, 0, tid);
    attn_issue_kv(smb, 1, Kb, Vb, 1, tid);
    attn_issue_kv(smb, 2, Kb, Vb, 2, tid);
    attn_issue_kv(smb, 3, Kb, Vb, 3, tid);

    // Q a-frags directly from global (values already on the tf32 grid)
    uint32_t q[8][4];
    {
        const uint32_t* Qg = (const uint32_t*)(g_q +
            ((size_t)(b * NH + h) * SEQ + n0 + m0) * HD);
        const uint32_t* r0p = Qg + g * HD;
        const uint32_t* r1p = Qg + (g + 8) * HD;
#pragma unroll
        for (int kk = 0; kk < 8; kk++) {
            uint2 u0 = *(const uint2*)(r0p + kk * 8 + 2 * t);
            uint2 u1 = *(const uint2*)(r1p + kk * 8 + 2 * t);
            q[kk][0] = u0.x; q[kk][1] = u1.x; q[kk][2] = u0.y; q[kk][3] = u1.y;
        }
    }

    float m0s = -1e30f, m1s = -1e30f, l0s = 0.f, l1s = 0.f;
    float s[8][4], o[8][4];
#pragma unroll
    for (int ni = 0; ni < 8; ni++)
#pragma unroll
        for (int r = 0; r < 4; r++) o[ni][r] = 0.f;

    const int KT = SEQ / 64;   // 32, processed in pairs
    for (int kt = 0; kt < KT; kt += 2) {
        // wait for stages kt, kt+1 (allow the 2 newest pairs to stay pending)
        if (kt + 2 < KT) asm volatile("cp.async.wait_group 2;" ::: "memory");
        else             asm volatile("cp.async.wait_group 0;" ::: "memory");
        __syncthreads();   // all warps done with pair kt-2 -> slots (kt+4/5)%6 free
        if (kt + 4 < KT) attn_issue_kv(smb, (kt + 4) % 6, Kb, Vb, kt + 4, tid);
        if (kt + 5 < KT) attn_issue_kv(smb, (kt + 5) % 6, Kb, Vb, kt + 5, tid);

        // block kt
        {
            uint32_t* Ks = sm + (kt % 6) * 9216;
            s_gemm_q(s, q, Ks, g, t);
            softmax_pv(s, o, m0s, m1s, l0s, l1s, Ks + 4608, g, t);
        }
        // block kt+1
        {
            uint32_t* Ks = sm + ((kt + 1) % 6) * 9216;
            s_gemm_q(s, q, Ks, g, t);
            softmax_pv(s, o, m0s, m1s, l0s, l1s, Ks + 4608, g, t);
        }
    }

    // epilogue: normalize, round to tf32, write (b,n,1024) for out_gemm
    float inv0 = 1.f / l0s, inv1 = 1.f / l1s;
    size_t r0 = (size_t)b * SEQ + n0 + m0 + g;
#pragma unroll
    for (int ni = 0; ni < 8; ni++) {
        int col = h * HD + ni * 8 + 2 * t;
        *(float2*)&g_attn[r0 * DM + col] =
            make_float2(r2f(f2tf(o[ni][0] * inv0)), r2f(f2tf(o[ni][1] * inv0)));
        *(float2*)&g_attn[(r0 + 8) * DM + col] =
            make_float2(r2f(f2tf(o[ni][2] * inv1)), r2f(f2tf(o[ni][3] * inv1)));
    }
}

// ---------------------------------------------------------------------------
extern "C" void kernel_launch(void* const* d_in, const int* in_sizes, int n_in,
                              void* d_out, int out_size)
{
    const float* x  = (const float*)d_in[0];
    const float* cs = (const float*)d_in[1];
    const float* sn = (const float*)d_in[2];
    const float* Wq = (const float*)d_in[3];
    const float* Wk = (const float*)d_in[4];
    const float* Wv = (const float*)d_in[5];
    const float* Wo = (const float*)d_in[6];
    float* out = (float*)d_out;
    (void)in_sizes; (void)n_in; (void)out_size;

    cudaFuncSetAttribute(qkv_gemm, cudaFuncAttributeMaxDynamicSharedMemorySize, GEMM_SMEM);
    cudaFuncSetAttribute(out_gemm, cudaFuncAttributeMaxDynamicSharedMemorySize, GEMM_SMEM);
    cudaFuncSetAttribute(attn_mma, cudaFuncAttributeMaxDynamicSharedMemorySize, ATT_SMEM);

    // 1) round x + weights onto the tf32 grid
    prep_round<<<6656, 256>>>(x, Wq, Wk, Wv, Wo);

    // 2) QKV projections + fused RoPE + permuted head-major stores
    qkv_gemm<<<dim3(12, 32), 256, GEMM_SMEM>>>(cs, sn);

    // 3) attention: grid (8 q-tiles of 256, 16 heads, 2 batch)
    attn_mma<<<dim3(SEQ / 256, NH, BB), 512, ATT_SMEM>>>();

    // 4) output projection
    out_gemm<<<dim3(8, 32), 256, GEMM_SMEM>>>(out);
}

// round 12
// speedup vs baseline: 1.0653x; 1.0038x over previous
#include <cuda_runtime.h>
#include <cstdint>

#define NH   16
#define NKV  4
#define HD   64
#define DM   1024
#define BB   2
#define SEQ  2048
#define MROWS (BB*SEQ)   // 4096

// Q pre-scale: HD^-0.5 * log2(e)  (softmax done in exp2 domain)
#define QSC 0.18033688011112042f

// ---------------------------------------------------------------------------
// Scratch (allocation-free device globals)
// ---------------------------------------------------------------------------
__device__ float g_xr [(size_t)MROWS * DM];       // tf32-rounded x
__device__ float g_wqr[(size_t)DM * DM];
__device__ float g_wkr[(size_t)DM * 256];
__device__ float g_wvr[(size_t)DM * 256];
__device__ float g_wor[(size_t)DM * DM];
__device__ float g_q  [(size_t)BB * NH  * SEQ * HD];  // head-major, d-permuted, *QSC, rope'd
__device__ float g_k  [(size_t)BB * NKV * SEQ * HD];  // head-major, d-permuted, rope'd
__device__ float g_v  [(size_t)BB * NKV * HD * SEQ];  // head-major TRANSPOSED: [d][seq]
__device__ float g_attn[(size_t)MROWS * DM];          // (b,n,1024), tf32-rounded

// ---------------------------------------------------------------------------
// helpers
// ---------------------------------------------------------------------------
__device__ __forceinline__ uint32_t f2tf(float f) {
    uint32_t u;
    asm("cvt.rna.tf32.f32 %0, %1;" : "=r"(u) : "f"(f));
    return u;
}
__device__ __forceinline__ float r2f(uint32_t u) { return __uint_as_float(u); }

__device__ __forceinline__ float ex2f(float x) {
    float r;
    asm("ex2.approx.ftz.f32 %0, %1;" : "=f"(r) : "f"(x));
    return r;
}
__device__ __forceinline__ int perm8p(int j) {
    int u = j & 7;
    return (j & ~7) + ((u < 4) ? 2 * u : 2 * (u - 4) + 1);
}
__device__ __forceinline__ void mma8(float c[4], const uint32_t a[4], const uint32_t b[2]) {
    asm volatile(
        "mma.sync.aligned.m16n8k8.row.col.f32.tf32.tf32.f32 "
        "{%0,%1,%2,%3},{%4,%5,%6,%7},{%8,%9},{%0,%1,%2,%3};"
        : "+f"(c[0]), "+f"(c[1]), "+f"(c[2]), "+f"(c[3])
        : "r"(a[0]), "r"(a[1]), "r"(a[2]), "r"(a[3]), "r"(b[0]), "r"(b[1]));
}
__device__ __forceinline__ void cpa16(uint32_t dst, const void* src) {
    asm volatile("cp.async.cg.shared.global [%0], [%1], 16;" :: "r"(dst), "l"(src) : "memory");
}
#define CPA_COMMIT() asm volatile("cp.async.commit_group;" ::: "memory")

// ---------------------------------------------------------------------------
// Pre-pass: round x + weights to the tf32 grid (then mma can eat them raw).
// ---------------------------------------------------------------------------
__global__ void prep_round(const float* __restrict__ x,  const float* __restrict__ Wq,
                           const float* __restrict__ Wk, const float* __restrict__ Wv,
                           const float* __restrict__ Wo)
{
    size_t i = (size_t)blockIdx.x * 256 + threadIdx.x;   // float4 index
    const float* src; float* dst; size_t off;
    if      (i < 1048576) { src = x;  dst = g_xr;  off = i; }
    else if (i < 1310720) { src = Wq; dst = g_wqr; off = i - 1048576; }
    else if (i < 1376256) { src = Wk; dst = g_wkr; off = i - 1310720; }
    else if (i < 1441792) { src = Wv; dst = g_wvr; off = i - 1376256; }
    else                  { src = Wo; dst = g_wor; off = i - 1441792; }
    float4 v = ((const float4*)src)[off];
    v.x = r2f(f2tf(v.x)); v.y = r2f(f2tf(v.y));
    v.z = r2f(f2tf(v.z)); v.w = r2f(f2tf(v.w));
    ((float4*)dst)[off] = v;
}

// ---------------------------------------------------------------------------
// cp.async 3-stage GEMM: 128x128 CTA tile, kstep 32, 128 threads (4 warps),
// warp tile 64x64 (4 mtiles x 8 ntiles) -> 128 B smem traffic per mma
// (vs 192 for 64x32). __launch_bounds__(128,2): up to 255 regs/thread.
// Stage: As[128][40] (5120 w) + Bs[32][132] (4224 w) = 9344 words.
// ---------------------------------------------------------------------------
#define GSTAGE 9344
#define GEMM_SMEM (3 * GSTAGE * 4)   // 112128 B

__device__ __forceinline__ void gemm_main(uint32_t* sm, uint32_t smb,
    const float* __restrict__ A, const float* __restrict__ B,
    int ldb, int n0, int row0, float acc[4][8][4])
{
    const int K = DM, KT = DM / 32;
    const int tid = threadIdx.x, lane = tid & 31, wid = tid >> 5;  // wid 0..3
    const int g = lane >> 2, t = lane & 3;
    const int m0 = (wid >> 1) * 64, nw = (wid & 1) * 64;

    // load addressing: A tile 128x32 words (1024 float4 / 128 thr = 8 each),
    // B tile 32x128 words (8 each)
    const int ar = tid >> 3, ac = (tid & 7) << 2;    // A: row ar+16i, col ac
    const int bk = tid >> 5, bn = (tid & 31) << 2;   // B: row bk+4i, col bn
    const uint32_t aDst = (ar * 40 + ac) * 4;
    const uint32_t bDst = (5120 + bk * 132 + bn) * 4;
    const float* aS = A + (size_t)(row0 + ar) * K + ac;
    const float* bS = B + (size_t)bk * ldb + n0 + bn;

    auto issue = [&](int slot, int kt) {
        uint32_t base = smb + slot * (GSTAGE * 4);
        const float* a = aS + kt * 32;
        const float* b = bS + (size_t)kt * 32 * ldb;
#pragma unroll
        for (int i = 0; i < 8; i++)
            cpa16(base + aDst + i * (16 * 40 * 4), a + (size_t)i * 16 * K);
#pragma unroll
        for (int i = 0; i < 8; i++)
            cpa16(base + bDst + i * (4 * 132 * 4), b + (size_t)i * 4 * ldb);
        CPA_COMMIT();
    };

#pragma unroll
    for (int mi = 0; mi < 4; mi++)
#pragma unroll
        for (int ni = 0; ni < 8; ni++)
#pragma unroll
            for (int r = 0; r < 4; r++) acc[mi][ni][r] = 0.f;

    issue(0, 0);
    issue(1, 1);

    for (int kt = 0; kt < KT; kt++) {
        if (kt + 1 < KT) asm volatile("cp.async.wait_group 1;" ::: "memory");
        else             asm volatile("cp.async.wait_group 0;" ::: "memory");
        __syncthreads();
        if (kt + 2 < KT) issue((kt + 2) % 3, kt + 2);

        uint32_t* st = sm + (kt % 3) * GSTAGE;
        uint32_t (*As)[40]  = (uint32_t(*)[40])st;
        uint32_t (*Bs)[132] = (uint32_t(*)[132])(st + 5120);
#pragma unroll
        for (int kk0 = 0; kk0 < 32; kk0 += 8) {
            uint32_t a[4][4], b[8][2];
#pragma unroll
            for (int mi = 0; mi < 4; mi++) {
                int rb = m0 + mi * 16 + g;
                uint2 av0 = *(const uint2*)&As[rb][kk0 + 2 * t];
                uint2 av1 = *(const uint2*)&As[rb + 8][kk0 + 2 * t];
                a[mi][0] = av0.x; a[mi][1] = av1.x; a[mi][2] = av0.y; a[mi][3] = av1.y;
            }
#pragma unroll
            for (int ni = 0; ni < 8; ni++) {
                b[ni][0] = Bs[kk0 + 2 * t][nw + ni * 8 + g];
                b[ni][1] = Bs[kk0 + 2 * t + 1][nw + ni * 8 + g];
            }
#pragma unroll
            for (int mi = 0; mi < 4; mi++)
#pragma unroll
                for (int ni = 0; ni < 8; ni++)
                    mma8(acc[mi][ni], a[mi], b[ni]);
        }
    }
}

// ---------------------------------------------------------------------------
// QKV projection + fused RoPE + permuted head-major stores (V transposed).
// grid (12, 32), 128 threads: bx 0..7 -> Q, 8..9 -> K, 10..11 -> V.
// ---------------------------------------------------------------------------
__global__ __launch_bounds__(128, 2) void qkv_gemm(
    const float* __restrict__ cs, const float* __restrict__ sn)
{
    extern __shared__ uint32_t sm[];
    uint32_t smb = (uint32_t)__cvta_generic_to_shared(sm);
    const int bx = blockIdx.x, row0 = blockIdx.y * 128;
    const int tid = threadIdx.x, lane = tid & 31, wid = tid >> 5;
    const int g = lane >> 2, t = lane & 3;
    const int m0 = (wid >> 1) * 64, nw = (wid & 1) * 64;
    float acc[4][8][4];

    if (bx < 8) {
        gemm_main(sm, smb, g_xr, g_wqr, DM, bx * 128, row0, acc);
#pragma unroll
        for (int mi = 0; mi < 4; mi++)
#pragma unroll
            for (int ni = 0; ni < 8; ni++) {
                int gc = bx * 128 + nw + ni * 8 + 2 * t;       // even original col
                int head = gc >> 6, j = (gc & 63) >> 1;
                int pj = perm8p(j), pj2 = perm8p(j + 32);
#pragma unroll
                for (int rr = 0; rr < 2; rr++) {
                    int row = row0 + m0 + mi * 16 + g + rr * 8;
                    int n = row & (SEQ - 1), bi = row >> 11;
                    float cv = cs[n * 32 + j], sv = sn[n * 32 + j];
                    float a0 = acc[mi][ni][rr * 2], a1 = acc[mi][ni][rr * 2 + 1];
                    size_t bp = ((size_t)(bi * NH + head) * SEQ + n) * HD;
                    g_q[bp + pj]  = r2f(f2tf((a0 * cv - a1 * sv) * QSC));
                    g_q[bp + pj2] = r2f(f2tf((a0 * sv + a1 * cv) * QSC));
                }
            }
    } else if (bx < 10) {
        gemm_main(sm, smb, g_xr, g_wkr, 256, (bx - 8) * 128, row0, acc);
#pragma unroll
        for (int mi = 0; mi < 4; mi++)
#pragma unroll
            for (int ni = 0; ni < 8; ni++) {
                int gc = (bx - 8) * 128 + nw + ni * 8 + 2 * t;
                int kvh = gc >> 6, j = (gc & 63) >> 1;
                int pj = perm8p(j), pj2 = perm8p(j + 32);
#pragma unroll
                for (int rr = 0; rr < 2; rr++) {
                    int row = row0 + m0 + mi * 16 + g + rr * 8;
                    int n = row & (SEQ - 1), bi = row >> 11;
                    float cv = cs[n * 32 + j], sv = sn[n * 32 + j];
                    float a0 = acc[mi][ni][rr * 2], a1 = acc[mi][ni][rr * 2 + 1];
                    size_t bp = ((size_t)(bi * NKV + kvh) * SEQ + n) * HD;
                    g_k[bp + pj]  = r2f(f2tf(a0 * cv - a1 * sv));
                    g_k[bp + pj2] = r2f(f2tf(a0 * sv + a1 * cv));
                }
            }
    } else {
        gemm_main(sm, smb, g_xr, g_wvr, 256, (bx - 10) * 128, row0, acc);
#pragma unroll
        for (int mi = 0; mi < 4; mi++)
#pragma unroll
            for (int ni = 0; ni < 8; ni++) {
                int gc = (bx - 10) * 128 + nw + ni * 8 + 2 * t;
                int kvh = gc >> 6, d = gc & 63;
#pragma unroll
                for (int rr = 0; rr < 2; rr++) {
                    int row = row0 + m0 + mi * 16 + g + rr * 8;
                    int n = row & (SEQ - 1), bi = row >> 11;
                    size_t hb = ((size_t)(bi * NKV + kvh) * HD);
                    g_v[(hb + d) * SEQ + n]     = r2f(f2tf(acc[mi][ni][rr * 2]));
                    g_v[(hb + d + 1) * SEQ + n] = r2f(f2tf(acc[mi][ni][rr * 2 + 1]));
                }
            }
    }
}

// ---------------------------------------------------------------------------
// Output projection: grid (8, 32), 128 threads.
// ---------------------------------------------------------------------------
__global__ __launch_bounds__(128, 2) void out_gemm(float* __restrict__ out)
{
    extern __shared__ uint32_t sm[];
    uint32_t smb = (uint32_t)__cvta_generic_to_shared(sm);
    const int tid = threadIdx.x, lane = tid & 31, wid = tid >> 5;
    const int g = lane >> 2, t = lane & 3;
    const int m0 = (wid >> 1) * 64, nw = (wid & 1) * 64;
    const int n0 = blockIdx.x * 128, row0 = blockIdx.y * 128;
    float acc[4][8][4];
    gemm_main(sm, smb, g_attn, g_wor, DM, n0, row0, acc);
#pragma unroll
    for (int mi = 0; mi < 4; mi++) {
        int r = row0 + m0 + mi * 16 + g;
#pragma unroll
        for (int ni = 0; ni < 8; ni++) {
            int c = n0 + nw + ni * 8 + 2 * t;
            *(float2*)(out + (size_t)r * DM + c)       = make_float2(acc[mi][ni][0], acc[mi][ni][1]);
            *(float2*)(out + (size_t)(r + 8) * DM + c) = make_float2(acc[mi][ni][2], acc[mi][ni][3]);
        }
    }
}

// ---------------------------------------------------------------------------
// Flash attention (unchanged R11): BM=256, 512 threads, 1 CTA/SM, Q in
// registers, 6-stage KV ring, two KV blocks per barrier, exp2 softmax.
// Smem (u32): 6 stages x (Ks[64*72]+Vt[64*72]=9216) = 55296 words = 221184 B.
// ---------------------------------------------------------------------------
#define ATT_SMEM 221184

__device__ __forceinline__ void attn_issue_kv(uint32_t smb, int slot,
    const float* __restrict__ Kb, const float* __restrict__ Vb, int kt, int tid)
{
    uint32_t base = smb + slot * 9216 * 4;
    const float* K0 = Kb + (size_t)kt * 64 * HD;
#pragma unroll
    for (int i = 0; i < 2; i++) {
        int c = tid + i * 512;
        int r = c >> 4, col = (c & 15) << 2;
        cpa16(base + (r * 72 + col) * 4, K0 + r * HD + col);
    }
#pragma unroll
    for (int i = 0; i < 2; i++) {
        int c = tid + i * 512;
        int r = c >> 4, col = (c & 15) << 2;
        cpa16(base + (4608 + r * 72 + col) * 4, Vb + (size_t)r * SEQ + kt * 64 + col);
    }
    CPA_COMMIT();
}

// S = Q*K^T with Q a-frags in registers
__device__ __forceinline__ void s_gemm_q(float s[8][4],
    const uint32_t q[8][4], const uint32_t* Ks, int g, int t)
{
#pragma unroll
    for (int ni = 0; ni < 8; ni++)
#pragma unroll
        for (int r = 0; r < 4; r++) s[ni][r] = 0.f;
#pragma unroll
    for (int kk = 0; kk < 8; kk++) {
#pragma unroll
        for (int ni = 0; ni < 8; ni++) {
            uint2 bv = *(const uint2*)&Ks[(ni * 8 + g) * 72 + kk * 8 + 2 * t];
            uint32_t bb[2] = {bv.x, bv.y};
            mma8(s[ni], q[kk], bb);
        }
    }
}

// online-softmax update on s + rescale o + O += P*V from Vt stage
__device__ __forceinline__ void softmax_pv(float s[8][4], float o[8][4],
    float& m0s, float& m1s, float& l0s, float& l1s,
    const uint32_t* Vt, int g, int t)
{
    float mx0 = -1e30f, mx1 = -1e30f;
#pragma unroll
    for (int ni = 0; ni < 8; ni++) {
        mx0 = fmaxf(mx0, fmaxf(s[ni][0], s[ni][1]));
        mx1 = fmaxf(mx1, fmaxf(s[ni][2], s[ni][3]));
    }
    mx0 = fmaxf(mx0, __shfl_xor_sync(0xffffffffu, mx0, 1));
    mx0 = fmaxf(mx0, __shfl_xor_sync(0xffffffffu, mx0, 2));
    mx1 = fmaxf(mx1, __shfl_xor_sync(0xffffffffu, mx1, 1));
    mx1 = fmaxf(mx1, __shfl_xor_sync(0xffffffffu, mx1, 2));

    float mn0 = fmaxf(m0s, mx0), mn1 = fmaxf(m1s, mx1);
    float cor0 = ex2f(m0s - mn0), cor1 = ex2f(m1s - mn1);
    m0s = mn0; m1s = mn1;

    float rs0 = 0.f, rs1 = 0.f;
#pragma unroll
    for (int ni = 0; ni < 8; ni++) {
        s[ni][0] = ex2f(s[ni][0] - mn0);
        s[ni][1] = ex2f(s[ni][1] - mn0);
        s[ni][2] = ex2f(s[ni][2] - mn1);
        s[ni][3] = ex2f(s[ni][3] - mn1);
        rs0 += s[ni][0] + s[ni][1];
        rs1 += s[ni][2] + s[ni][3];
    }
    rs0 += __shfl_xor_sync(0xffffffffu, rs0, 1);
    rs0 += __shfl_xor_sync(0xffffffffu, rs0, 2);
    rs1 += __shfl_xor_sync(0xffffffffu, rs1, 1);
    rs1 += __shfl_xor_sync(0xffffffffu, rs1, 2);
    l0s = l0s * cor0 + rs0;
    l1s = l1s * cor1 + rs1;

#pragma unroll
    for (int ni = 0; ni < 8; ni++) {
        o[ni][0] *= cor0; o[ni][1] *= cor0;
        o[ni][2] *= cor1; o[ni][3] *= cor1;
    }
#pragma unroll
    for (int kk = 0; kk < 8; kk++) {
        uint32_t a[4];
        a[0] = f2tf(s[kk][0]);
        a[1] = f2tf(s[kk][2]);
        a[2] = f2tf(s[kk][1]);
        a[3] = f2tf(s[kk][3]);
#pragma unroll
        for (int ni = 0; ni < 8; ni++) {
            uint2 bv = *(const uint2*)&Vt[(ni * 8 + g) * 72 + kk * 8 + 2 * t];
            uint32_t bb[2] = {bv.x, bv.y};
            mma8(o[ni], a, bb);
        }
    }
}

__global__ __launch_bounds__(512, 1) void attn_mma()
{
    extern __shared__ uint32_t sm[];
    uint32_t smb = (uint32_t)__cvta_generic_to_shared(sm);
    const int b = blockIdx.z, h = blockIdx.y;
    const int n0 = blockIdx.x * 256;
    const int kvh = h >> 2;
    const int tid = threadIdx.x, lane = tid & 31, wid = tid >> 5;  // wid 0..15
    const int g = lane >> 2, t = lane & 3;
    const int m0 = wid * 16;

    const float* Kb = g_k + ((size_t)(b * NKV + kvh) * SEQ) * HD;
    const float* Vb = g_v + ((size_t)(b * NKV + kvh) * HD) * SEQ;

    // prefetch 4 KV stages
    attn_issue_kv(smb, 0, Kb, Vb, 0, tid);
    attn_issue_kv(smb, 1, Kb, Vb, 1, tid);
    attn_issue_kv(smb, 2, Kb, Vb, 2, tid);
    attn_issue_kv(smb, 3, Kb, Vb, 3, tid);

    // Q a-frags directly from global (values already on the tf32 grid)
    uint32_t q[8][4];
    {
        const uint32_t* Qg = (const uint32_t*)(g_q +
            ((size_t)(b * NH + h) * SEQ + n0 + m0) * HD);
        const uint32_t* r0p = Qg + g * HD;
        const uint32_t* r1p = Qg + (g + 8) * HD;
#pragma unroll
        for (int kk = 0; kk < 8; kk++) {
            uint2 u0 = *(const uint2*)(r0p + kk * 8 + 2 * t);
            uint2 u1 = *(const uint2*)(r1p + kk * 8 + 2 * t);
            q[kk][0] = u0.x; q[kk][1] = u1.x; q[kk][2] = u0.y; q[kk][3] = u1.y;
        }
    }

    float m0s = -1e30f, m1s = -1e30f, l0s = 0.f, l1s = 0.f;
    float s[8][4], o[8][4];
#pragma unroll
    for (int ni = 0; ni < 8; ni++)
#pragma unroll
        for (int r = 0; r < 4; r++) o[ni][r] = 0.f;

    const int KT = SEQ / 64;   // 32, processed in pairs
    for (int kt = 0; kt < KT; kt += 2) {
        if (kt + 2 < KT) asm volatile("cp.async.wait_group 2;" ::: "memory");
        else             asm volatile("cp.async.wait_group 0;" ::: "memory");
        __syncthreads();
        if (kt + 4 < KT) attn_issue_kv(smb, (kt + 4) % 6, Kb, Vb, kt + 4, tid);
        if (kt + 5 < KT) attn_issue_kv(smb, (kt + 5) % 6, Kb, Vb, kt + 5, tid);

        {
            uint32_t* Ks = sm + (kt % 6) * 9216;
            s_gemm_q(s, q, Ks, g, t);
            softmax_pv(s, o, m0s, m1s, l0s, l1s, Ks + 4608, g, t);
        }
        {
            uint32_t* Ks = sm + ((kt + 1) % 6) * 9216;
            s_gemm_q(s, q, Ks, g, t);
            softmax_pv(s, o, m0s, m1s, l0s, l1s, Ks + 4608, g, t);
        }
    }

    // epilogue: normalize, round to tf32, write (b,n,1024) for out_gemm
    float inv0 = 1.f / l0s, inv1 = 1.f / l1s;
    size_t r0 = (size_t)b * SEQ + n0 + m0 + g;
#pragma unroll
    for (int ni = 0; ni < 8; ni++) {
        int col = h * HD + ni * 8 + 2 * t;
        *(float2*)&g_attn[r0 * DM + col] =
            make_float2(r2f(f2tf(o[ni][0] * inv0)), r2f(f2tf(o[ni][1] * inv0)));
        *(float2*)&g_attn[(r0 + 8) * DM + col] =
            make_float2(r2f(f2tf(o[ni][2] * inv1)), r2f(f2tf(o[ni][3] * inv1)));
    }
}

// ---------------------------------------------------------------------------
extern "C" void kernel_launch(void* const* d_in, const int* in_sizes, int n_in,
                              void* d_out, int out_size)
{
    const float* x  = (const float*)d_in[0];
    const float* cs = (const float*)d_in[1];
    const float* sn = (const float*)d_in[2];
    const float* Wq = (const float*)d_in[3];
    const float* Wk = (const float*)d_in[4];
    const float* Wv = (const float*)d_in[5];
    const float* Wo = (const float*)d_in[6];
    float* out = (float*)d_out;
    (void)in_sizes; (void)n_in; (void)out_size;

    cudaFuncSetAttribute(qkv_gemm, cudaFuncAttributeMaxDynamicSharedMemorySize, GEMM_SMEM);
    cudaFuncSetAttribute(out_gemm, cudaFuncAttributeMaxDynamicSharedMemorySize, GEMM_SMEM);
    cudaFuncSetAttribute(attn_mma, cudaFuncAttributeMaxDynamicSharedMemorySize, ATT_SMEM);

    // 1) round x + weights onto the tf32 grid
    prep_round<<<6656, 256>>>(x, Wq, Wk, Wv, Wo);

    // 2) QKV projections + fused RoPE + permuted head-major stores
    qkv_gemm<<<dim3(12, 32), 128, GEMM_SMEM>>>(cs, sn);

    // 3) attention: grid (8 q-tiles of 256, 16 heads, 2 batch)
    attn_mma<<<dim3(SEQ / 256, NH, BB), 512, ATT_SMEM>>>();

    // 4) output projection
    out_gemm<<<dim3(8, 32), 128, GEMM_SMEM>>>(out);
}

// round 13
// speedup vs baseline: 1.0748x; 1.0090x over previous
#include <cuda_runtime.h>
#include <cstdint>

#define NH   16
#define NKV  4
#define HD   64
#define DM   1024
#define BB   2
#define SEQ  2048
#define MROWS (BB*SEQ)   // 4096

// Q pre-scale: HD^-0.5 * log2(e)  (softmax done in exp2 domain)
#define QSC 0.18033688011112042f

// ---------------------------------------------------------------------------
// Scratch (allocation-free device globals)
// ---------------------------------------------------------------------------
__device__ float g_xr [(size_t)MROWS * DM];       // tf32-rounded x
__device__ float g_wqr[(size_t)DM * DM];
__device__ float g_wkr[(size_t)DM * 256];
__device__ float g_wvr[(size_t)DM * 256];
__device__ float g_wor[(size_t)DM * DM];
__device__ float g_q  [(size_t)BB * NH  * SEQ * HD];  // head-major, d-permuted, *QSC, rope'd
__device__ float g_k  [(size_t)BB * NKV * SEQ * HD];  // head-major, d-permuted, rope'd
__device__ float g_v  [(size_t)BB * NKV * HD * SEQ];  // head-major TRANSPOSED: [d][seq]
__device__ float g_attn[(size_t)MROWS * DM];          // (b,n,1024), tf32-rounded

// ---------------------------------------------------------------------------
// helpers
// ---------------------------------------------------------------------------
__device__ __forceinline__ uint32_t f2tf(float f) {
    uint32_t u;
    asm("cvt.rna.tf32.f32 %0, %1;" : "=r"(u) : "f"(f));
    return u;
}
__device__ __forceinline__ float r2f(uint32_t u) { return __uint_as_float(u); }

__device__ __forceinline__ float ex2f(float x) {
    float r;
    asm("ex2.approx.ftz.f32 %0, %1;" : "=f"(r) : "f"(x));
    return r;
}
__device__ __forceinline__ int perm8p(int j) {
    int u = j & 7;
    return (j & ~7) + ((u < 4) ? 2 * u : 2 * (u - 4) + 1);
}
__device__ __forceinline__ void mma8(float c[4], const uint32_t a[4], const uint32_t b[2]) {
    asm volatile(
        "mma.sync.aligned.m16n8k8.row.col.f32.tf32.tf32.f32 "
        "{%0,%1,%2,%3},{%4,%5,%6,%7},{%8,%9},{%0,%1,%2,%3};"
        : "+f"(c[0]), "+f"(c[1]), "+f"(c[2]), "+f"(c[3])
        : "r"(a[0]), "r"(a[1]), "r"(a[2]), "r"(a[3]), "r"(b[0]), "r"(b[1]));
}
__device__ __forceinline__ void cpa16(uint32_t dst, const void* src) {
    asm volatile("cp.async.cg.shared.global [%0], [%1], 16;" :: "r"(dst), "l"(src) : "memory");
}
#define CPA_COMMIT() asm volatile("cp.async.commit_group;" ::: "memory")

// ---------------------------------------------------------------------------
// Pre-pass: round x + weights to the tf32 grid (then mma can eat them raw).
// ---------------------------------------------------------------------------
__global__ void prep_round(const float* __restrict__ x,  const float* __restrict__ Wq,
                           const float* __restrict__ Wk, const float* __restrict__ Wv,
                           const float* __restrict__ Wo)
{
    size_t i = (size_t)blockIdx.x * 256 + threadIdx.x;   // float4 index
    const float* src; float* dst; size_t off;
    if      (i < 1048576) { src = x;  dst = g_xr;  off = i; }
    else if (i < 1310720) { src = Wq; dst = g_wqr; off = i - 1048576; }
    else if (i < 1376256) { src = Wk; dst = g_wkr; off = i - 1310720; }
    else if (i < 1441792) { src = Wv; dst = g_wvr; off = i - 1376256; }
    else                  { src = Wo; dst = g_wor; off = i - 1441792; }
    float4 v = ((const float4*)src)[off];
    v.x = r2f(f2tf(v.x)); v.y = r2f(f2tf(v.y));
    v.z = r2f(f2tf(v.z)); v.w = r2f(f2tf(v.w));
    ((float4*)dst)[off] = v;
}

// ---------------------------------------------------------------------------
// Shared GEMM constants: 128x128 CTA tile, kstep 32, 3-stage cp.async ring.
// Stage: As[128][40] (5120 w) + Bs[32][132] (4224 w) = 9344 words.
// ---------------------------------------------------------------------------
#define GSTAGE 9344
#define GEMM_SMEM (3 * GSTAGE * 4)   // 112128 B

// ---------------------------------------------------------------------------
// Variant A (for out_gemm): 256 threads (8 warps), warp tile 64x32.
// 16 warps/SM at 2 CTAs/SM -> best latency hiding (R11-measured 58.6us).
// ---------------------------------------------------------------------------
__device__ __forceinline__ void gemm_main32(uint32_t* sm, uint32_t smb,
    const float* __restrict__ A, const float* __restrict__ B,
    int ldb, int n0, int row0, float acc[4][4][4])
{
    const int K = DM, KT = DM / 32;
    const int tid = threadIdx.x, lane = tid & 31, wid = tid >> 5;
    const int g = lane >> 2, t = lane & 3;
    const int m0 = (wid >> 2) * 64, nw = (wid & 3) * 32;

    const int ar = tid >> 3, ac = (tid & 7) << 2;
    const int bk = tid >> 5, bn = (tid & 31) << 2;
    const uint32_t aDst = (ar * 40 + ac) * 4;
    const uint32_t bDst = (5120 + bk * 132 + bn) * 4;
    const float* aS = A + (size_t)(row0 + ar) * K + ac;
    const float* bS = B + (size_t)bk * ldb + n0 + bn;

    auto issue = [&](int slot, int kt) {
        uint32_t base = smb + slot * (GSTAGE * 4);
        const float* a = aS + kt * 32;
        const float* b = bS + (size_t)kt * 32 * ldb;
#pragma unroll
        for (int i = 0; i < 4; i++)
            cpa16(base + aDst + i * (32 * 40 * 4), a + (size_t)i * 32 * K);
#pragma unroll
        for (int i = 0; i < 4; i++)
            cpa16(base + bDst + i * (8 * 132 * 4), b + (size_t)i * 8 * ldb);
        CPA_COMMIT();
    };

#pragma unroll
    for (int mi = 0; mi < 4; mi++)
#pragma unroll
        for (int ni = 0; ni < 4; ni++)
#pragma unroll
            for (int r = 0; r < 4; r++) acc[mi][ni][r] = 0.f;

    issue(0, 0);
    issue(1, 1);

    for (int kt = 0; kt < KT; kt++) {
        if (kt + 1 < KT) asm volatile("cp.async.wait_group 1;" ::: "memory");
        else             asm volatile("cp.async.wait_group 0;" ::: "memory");
        __syncthreads();
        if (kt + 2 < KT) issue((kt + 2) % 3, kt + 2);

        uint32_t* st = sm + (kt % 3) * GSTAGE;
        uint32_t (*As)[40]  = (uint32_t(*)[40])st;
        uint32_t (*Bs)[132] = (uint32_t(*)[132])(st + 5120);
#pragma unroll
        for (int kk0 = 0; kk0 < 32; kk0 += 8) {
            uint32_t a[4][4], b[4][2];
#pragma unroll
            for (int mi = 0; mi < 4; mi++) {
                int rb = m0 + mi * 16 + g;
                uint2 av0 = *(const uint2*)&As[rb][kk0 + 2 * t];
                uint2 av1 = *(const uint2*)&As[rb + 8][kk0 + 2 * t];
                a[mi][0] = av0.x; a[mi][1] = av1.x; a[mi][2] = av0.y; a[mi][3] = av1.y;
            }
#pragma unroll
            for (int ni = 0; ni < 4; ni++) {
                b[ni][0] = Bs[kk0 + 2 * t][nw + ni * 8 + g];
                b[ni][1] = Bs[kk0 + 2 * t + 1][nw + ni * 8 + g];
            }
#pragma unroll
            for (int mi = 0; mi < 4; mi++)
#pragma unroll
                for (int ni = 0; ni < 4; ni++)
                    mma8(acc[mi][ni], a[mi], b[ni]);
        }
    }
}

// ---------------------------------------------------------------------------
// Variant B (for qkv): 128 threads (4 warps), warp tile 64x64 — fewer smem
// bytes/mma; epilogue-heavy qkv tolerates the lower occupancy (R12-measured
// net gain).
// ---------------------------------------------------------------------------
__device__ __forceinline__ void gemm_main64(uint32_t* sm, uint32_t smb,
    const float* __restrict__ A, const float* __restrict__ B,
    int ldb, int n0, int row0, float acc[4][8][4])
{
    const int K = DM, KT = DM / 32;
    const int tid = threadIdx.x, lane = tid & 31, wid = tid >> 5;  // wid 0..3
    const int g = lane >> 2, t = lane & 3;
    const int m0 = (wid >> 1) * 64, nw = (wid & 1) * 64;

    const int ar = tid >> 3, ac = (tid & 7) << 2;
    const int bk = tid >> 5, bn = (tid & 31) << 2;
    const uint32_t aDst = (ar * 40 + ac) * 4;
    const uint32_t bDst = (5120 + bk * 132 + bn) * 4;
    const float* aS = A + (size_t)(row0 + ar) * K + ac;
    const float* bS = B + (size_t)bk * ldb + n0 + bn;

    auto issue = [&](int slot, int kt) {
        uint32_t base = smb + slot * (GSTAGE * 4);
        const float* a = aS + kt * 32;
        const float* b = bS + (size_t)kt * 32 * ldb;
#pragma unroll
        for (int i = 0; i < 8; i++)
            cpa16(base + aDst + i * (16 * 40 * 4), a + (size_t)i * 16 * K);
#pragma unroll
        for (int i = 0; i < 8; i++)
            cpa16(base + bDst + i * (4 * 132 * 4), b + (size_t)i * 4 * ldb);
        CPA_COMMIT();
    };

#pragma unroll
    for (int mi = 0; mi < 4; mi++)
#pragma unroll
        for (int ni = 0; ni < 8; ni++)
#pragma unroll
            for (int r = 0; r < 4; r++) acc[mi][ni][r] = 0.f;

    issue(0, 0);
    issue(1, 1);

    for (int kt = 0; kt < KT; kt++) {
        if (kt + 1 < KT) asm volatile("cp.async.wait_group 1;" ::: "memory");
        else             asm volatile("cp.async.wait_group 0;" ::: "memory");
        __syncthreads();
        if (kt + 2 < KT) issue((kt + 2) % 3, kt + 2);

        uint32_t* st = sm + (kt % 3) * GSTAGE;
        uint32_t (*As)[40]  = (uint32_t(*)[40])st;
        uint32_t (*Bs)[132] = (uint32_t(*)[132])(st + 5120);
#pragma unroll
        for (int kk0 = 0; kk0 < 32; kk0 += 8) {
            uint32_t a[4][4], b[8][2];
#pragma unroll
            for (int mi = 0; mi < 4; mi++) {
                int rb = m0 + mi * 16 + g;
                uint2 av0 = *(const uint2*)&As[rb][kk0 + 2 * t];
                uint2 av1 = *(const uint2*)&As[rb + 8][kk0 + 2 * t];
                a[mi][0] = av0.x; a[mi][1] = av1.x; a[mi][2] = av0.y; a[mi][3] = av1.y;
            }
#pragma unroll
            for (int ni = 0; ni < 8; ni++) {
                b[ni][0] = Bs[kk0 + 2 * t][nw + ni * 8 + g];
                b[ni][1] = Bs[kk0 + 2 * t + 1][nw + ni * 8 + g];
            }
#pragma unroll
            for (int mi = 0; mi < 4; mi++)
#pragma unroll
                for (int ni = 0; ni < 8; ni++)
                    mma8(acc[mi][ni], a[mi], b[ni]);
        }
    }
}

// ---------------------------------------------------------------------------
// QKV projection + fused RoPE + permuted head-major stores (V transposed).
// grid (12, 32), 128 threads: bx 0..7 -> Q, 8..9 -> K, 10..11 -> V.
// ---------------------------------------------------------------------------
__global__ __launch_bounds__(128, 2) void qkv_gemm(
    const float* __restrict__ cs, const float* __restrict__ sn)
{
    extern __shared__ uint32_t sm[];
    uint32_t smb = (uint32_t)__cvta_generic_to_shared(sm);
    const int bx = blockIdx.x, row0 = blockIdx.y * 128;
    const int tid = threadIdx.x, lane = tid & 31, wid = tid >> 5;
    const int g = lane >> 2, t = lane & 3;
    const int m0 = (wid >> 1) * 64, nw = (wid & 1) * 64;
    float acc[4][8][4];

    if (bx < 8) {
        gemm_main64(sm, smb, g_xr, g_wqr, DM, bx * 128, row0, acc);
#pragma unroll
        for (int mi = 0; mi < 4; mi++)
#pragma unroll
            for (int ni = 0; ni < 8; ni++) {
                int gc = bx * 128 + nw + ni * 8 + 2 * t;       // even original col
                int head = gc >> 6, j = (gc & 63) >> 1;
                int pj = perm8p(j), pj2 = perm8p(j + 32);
#pragma unroll
                for (int rr = 0; rr < 2; rr++) {
                    int row = row0 + m0 + mi * 16 + g + rr * 8;
                    int n = row & (SEQ - 1), bi = row >> 11;
                    float cv = cs[n * 32 + j], sv = sn[n * 32 + j];
                    float a0 = acc[mi][ni][rr * 2], a1 = acc[mi][ni][rr * 2 + 1];
                    size_t bp = ((size_t)(bi * NH + head) * SEQ + n) * HD;
                    g_q[bp + pj]  = r2f(f2tf((a0 * cv - a1 * sv) * QSC));
                    g_q[bp + pj2] = r2f(f2tf((a0 * sv + a1 * cv) * QSC));
                }
            }
    } else if (bx < 10) {
        gemm_main64(sm, smb, g_xr, g_wkr, 256, (bx - 8) * 128, row0, acc);
#pragma unroll
        for (int mi = 0; mi < 4; mi++)
#pragma unroll
            for (int ni = 0; ni < 8; ni++) {
                int gc = (bx - 8) * 128 + nw + ni * 8 + 2 * t;
                int kvh = gc >> 6, j = (gc & 63) >> 1;
                int pj = perm8p(j), pj2 = perm8p(j + 32);
#pragma unroll
                for (int rr = 0; rr < 2; rr++) {
                    int row = row0 + m0 + mi * 16 + g + rr * 8;
                    int n = row & (SEQ - 1), bi = row >> 11;
                    float cv = cs[n * 32 + j], sv = sn[n * 32 + j];
                    float a0 = acc[mi][ni][rr * 2], a1 = acc[mi][ni][rr * 2 + 1];
                    size_t bp = ((size_t)(bi * NKV + kvh) * SEQ + n) * HD;
                    g_k[bp + pj]  = r2f(f2tf(a0 * cv - a1 * sv));
                    g_k[bp + pj2] = r2f(f2tf(a0 * sv + a1 * cv));
                }
            }
    } else {
        gemm_main64(sm, smb, g_xr, g_wvr, 256, (bx - 10) * 128, row0, acc);
#pragma unroll
        for (int mi = 0; mi < 4; mi++)
#pragma unroll
            for (int ni = 0; ni < 8; ni++) {
                int gc = (bx - 10) * 128 + nw + ni * 8 + 2 * t;
                int kvh = gc >> 6, d = gc & 63;
#pragma unroll
                for (int rr = 0; rr < 2; rr++) {
                    int row = row0 + m0 + mi * 16 + g + rr * 8;
                    int n = row & (SEQ - 1), bi = row >> 11;
                    size_t hb = ((size_t)(bi * NKV + kvh) * HD);
                    g_v[(hb + d) * SEQ + n]     = r2f(f2tf(acc[mi][ni][rr * 2]));
                    g_v[(hb + d + 1) * SEQ + n] = r2f(f2tf(acc[mi][ni][rr * 2 + 1]));
                }
            }
    }
}

// ---------------------------------------------------------------------------
// Output projection: grid (8, 32), 256 threads (variant A — R11 shape).
// ---------------------------------------------------------------------------
__global__ __launch_bounds__(256, 2) void out_gemm(float* __restrict__ out)
{
    extern __shared__ uint32_t sm[];
    uint32_t smb = (uint32_t)__cvta_generic_to_shared(sm);
    const int tid = threadIdx.x, lane = tid & 31, wid = tid >> 5;
    const int g = lane >> 2, t = lane & 3;
    const int m0 = (wid >> 2) * 64, nw = (wid & 3) * 32;
    const int n0 = blockIdx.x * 128, row0 = blockIdx.y * 128;
    float acc[4][4][4];
    gemm_main32(sm, smb, g_attn, g_wor, DM, n0, row0, acc);
#pragma unroll
    for (int mi = 0; mi < 4; mi++) {
        int r = row0 + m0 + mi * 16 + g;
#pragma unroll
        for (int ni = 0; ni < 4; ni++) {
            int c = n0 + nw + ni * 8 + 2 * t;
            *(float2*)(out + (size_t)r * DM + c)       = make_float2(acc[mi][ni][0], acc[mi][ni][1]);
            *(float2*)(out + (size_t)(r + 8) * DM + c) = make_float2(acc[mi][ni][2], acc[mi][ni][3]);
        }
    }
}

// ---------------------------------------------------------------------------
// Flash attention (unchanged R11): BM=256, 512 threads, 1 CTA/SM, Q in
// registers, 6-stage KV ring, two KV blocks per barrier, exp2 softmax.
// Smem (u32): 6 stages x (Ks[64*72]+Vt[64*72]=9216) = 55296 words = 221184 B.
// ---------------------------------------------------------------------------
#define ATT_SMEM 221184

__device__ __forceinline__ void attn_issue_kv(uint32_t smb, int slot,
    const float* __restrict__ Kb, const float* __restrict__ Vb, int kt, int tid)
{
    uint32_t base = smb + slot * 9216 * 4;
    const float* K0 = Kb + (size_t)kt * 64 * HD;
#pragma unroll
    for (int i = 0; i < 2; i++) {
        int c = tid + i * 512;
        int r = c >> 4, col = (c & 15) << 2;
        cpa16(base + (r * 72 + col) * 4, K0 + r * HD + col);
    }
#pragma unroll
    for (int i = 0; i < 2; i++) {
        int c = tid + i * 512;
        int r = c >> 4, col = (c & 15) << 2;
        cpa16(base + (4608 + r * 72 + col) * 4, Vb + (size_t)r * SEQ + kt * 64 + col);
    }
    CPA_COMMIT();
}

// S = Q*K^T with Q a-frags in registers
__device__ __forceinline__ void s_gemm_q(float s[8][4],
    const uint32_t q[8][4], const uint32_t* Ks, int g, int t)
{
#pragma unroll
    for (int ni = 0; ni < 8; ni++)
#pragma unroll
        for (int r = 0; r < 4; r++) s[ni][r] = 0.f;
#pragma unroll
    for (int kk = 0; kk < 8; kk++) {
#pragma unroll
        for (int ni = 0; ni < 8; ni++) {
            uint2 bv = *(const uint2*)&Ks[(ni * 8 + g) * 72 + kk * 8 + 2 * t];
            uint32_t bb[2] = {bv.x, bv.y};
            mma8(s[ni], q[kk], bb);
        }
    }
}

// online-softmax update on s + rescale o + O += P*V from Vt stage
__device__ __forceinline__ void softmax_pv(float s[8][4], float o[8][4],
    float& m0s, float& m1s, float& l0s, float& l1s,
    const uint32_t* Vt, int g, int t)
{
    float mx0 = -1e30f, mx1 = -1e30f;
#pragma unroll
    for (int ni = 0; ni < 8; ni++) {
        mx0 = fmaxf(mx0, fmaxf(s[ni][0], s[ni][1]));
        mx1 = fmaxf(mx1, fmaxf(s[ni][2], s[ni][3]));
    }
    mx0 = fmaxf(mx0, __shfl_xor_sync(0xffffffffu, mx0, 1));
    mx0 = fmaxf(mx0, __shfl_xor_sync(0xffffffffu, mx0, 2));
    mx1 = fmaxf(mx1, __shfl_xor_sync(0xffffffffu, mx1, 1));
    mx1 = fmaxf(mx1, __shfl_xor_sync(0xffffffffu, mx1, 2));

    float mn0 = fmaxf(m0s, mx0), mn1 = fmaxf(m1s, mx1);
    float cor0 = ex2f(m0s - mn0), cor1 = ex2f(m1s - mn1);
    m0s = mn0; m1s = mn1;

    float rs0 = 0.f, rs1 = 0.f;
#pragma unroll
    for (int ni = 0; ni < 8; ni++) {
        s[ni][0] = ex2f(s[ni][0] - mn0);
        s[ni][1] = ex2f(s[ni][1] - mn0);
        s[ni][2] = ex2f(s[ni][2] - mn1);
        s[ni][3] = ex2f(s[ni][3] - mn1);
        rs0 += s[ni][0] + s[ni][1];
        rs1 += s[ni][2] + s[ni][3];
    }
    rs0 += __shfl_xor_sync(0xffffffffu, rs0, 1);
    rs0 += __shfl_xor_sync(0xffffffffu, rs0, 2);
    rs1 += __shfl_xor_sync(0xffffffffu, rs1, 1);
    rs1 += __shfl_xor_sync(0xffffffffu, rs1, 2);
    l0s = l0s * cor0 + rs0;
    l1s = l1s * cor1 + rs1;

#pragma unroll
    for (int ni = 0; ni < 8; ni++) {
        o[ni][0] *= cor0; o[ni][1] *= cor0;
        o[ni][2] *= cor1; o[ni][3] *= cor1;
    }
#pragma unroll
    for (int kk = 0; kk < 8; kk++) {
        uint32_t a[4];
        a[0] = f2tf(s[kk][0]);
        a[1] = f2tf(s[kk][2]);
        a[2] = f2tf(s[kk][1]);
        a[3] = f2tf(s[kk][3]);
#pragma unroll
        for (int ni = 0; ni < 8; ni++) {
            uint2 bv = *(const uint2*)&Vt[(ni * 8 + g) * 72 + kk * 8 + 2 * t];
            uint32_t bb[2] = {bv.x, bv.y};
            mma8(o[ni], a, bb);
        }
    }
}

__global__ __launch_bounds__(512, 1) void attn_mma()
{
    extern __shared__ uint32_t sm[];
    uint32_t smb = (uint32_t)__cvta_generic_to_shared(sm);
    const int b = blockIdx.z, h = blockIdx.y;
    const int n0 = blockIdx.x * 256;
    const int kvh = h >> 2;
    const int tid = threadIdx.x, lane = tid & 31, wid = tid >> 5;  // wid 0..15
    const int g = lane >> 2, t = lane & 3;
    const int m0 = wid * 16;

    const float* Kb = g_k + ((size_t)(b * NKV + kvh) * SEQ) * HD;
    const float* Vb = g_v + ((size_t)(b * NKV + kvh) * HD) * SEQ;

    // prefetch 4 KV stages
    attn_issue_kv(smb, 0, Kb, Vb, 0, tid);
    attn_issue_kv(smb, 1, Kb, Vb, 1, tid);
    attn_issue_kv(smb, 2, Kb, Vb, 2, tid);
    attn_issue_kv(smb, 3, Kb, Vb, 3, tid);

    // Q a-frags directly from global (values already on the tf32 grid)
    uint32_t q[8][4];
    {
        const uint32_t* Qg = (const uint32_t*)(g_q +
            ((size_t)(b * NH + h) * SEQ + n0 + m0) * HD);
        const uint32_t* r0p = Qg + g * HD;
        const uint32_t* r1p = Qg + (g + 8) * HD;
#pragma unroll
        for (int kk = 0; kk < 8; kk++) {
            uint2 u0 = *(const uint2*)(r0p + kk * 8 + 2 * t);
            uint2 u1 = *(const uint2*)(r1p + kk * 8 + 2 * t);
            q[kk][0] = u0.x; q[kk][1] = u1.x; q[kk][2] = u0.y; q[kk][3] = u1.y;
        }
    }

    float m0s = -1e30f, m1s = -1e30f, l0s = 0.f, l1s = 0.f;
    float s[8][4], o[8][4];
#pragma unroll
    for (int ni = 0; ni < 8; ni++)
#pragma unroll
        for (int r = 0; r < 4; r++) o[ni][r] = 0.f;

    const int KT = SEQ / 64;   // 32, processed in pairs
    for (int kt = 0; kt < KT; kt += 2) {
        if (kt + 2 < KT) asm volatile("cp.async.wait_group 2;" ::: "memory");
        else             asm volatile("cp.async.wait_group 0;" ::: "memory");
        __syncthreads();
        if (kt + 4 < KT) attn_issue_kv(smb, (kt + 4) % 6, Kb, Vb, kt + 4, tid);
        if (kt + 5 < KT) attn_issue_kv(smb, (kt + 5) % 6, Kb, Vb, kt + 5, tid);

        {
            uint32_t* Ks = sm + (kt % 6) * 9216;
            s_gemm_q(s, q, Ks, g, t);
            softmax_pv(s, o, m0s, m1s, l0s, l1s, Ks + 4608, g, t);
        }
        {
            uint32_t* Ks = sm + ((kt + 1) % 6) * 9216;
            s_gemm_q(s, q, Ks, g, t);
            softmax_pv(s, o, m0s, m1s, l0s, l1s, Ks + 4608, g, t);
        }
    }

    // epilogue: normalize, round to tf32, write (b,n,1024) for out_gemm
    float inv0 = 1.f / l0s, inv1 = 1.f / l1s;
    size_t r0 = (size_t)b * SEQ + n0 + m0 + g;
#pragma unroll
    for (int ni = 0; ni < 8; ni++) {
        int col = h * HD + ni * 8 + 2 * t;
        *(float2*)&g_attn[r0 * DM + col] =
            make_float2(r2f(f2tf(o[ni][0] * inv0)), r2f(f2tf(o[ni][1] * inv0)));
        *(float2*)&g_attn[(r0 + 8) * DM + col] =
            make_float2(r2f(f2tf(o[ni][2] * inv1)), r2f(f2tf(o[ni][3] * inv1)));
    }
}

// ---------------------------------------------------------------------------
extern "C" void kernel_launch(void* const* d_in, const int* in_sizes, int n_in,
                              void* d_out, int out_size)
{
    const float* x  = (const float*)d_in[0];
    const float* cs = (const float*)d_in[1];
    const float* sn = (const float*)d_in[2];
    const float* Wq = (const float*)d_in[3];
    const float* Wk = (const float*)d_in[4];
    const float* Wv = (const float*)d_in[5];
    const float* Wo = (const float*)d_in[6];
    float* out = (float*)d_out;
    (void)in_sizes; (void)n_in; (void)out_size;

    cudaFuncSetAttribute(qkv_gemm, cudaFuncAttributeMaxDynamicSharedMemorySize, GEMM_SMEM);
    cudaFuncSetAttribute(out_gemm, cudaFuncAttributeMaxDynamicSharedMemorySize, GEMM_SMEM);
    cudaFuncSetAttribute(attn_mma, cudaFuncAttributeMaxDynamicSharedMemorySize, ATT_SMEM);

    // 1) round x + weights onto the tf32 grid
    prep_round<<<6656, 256>>>(x, Wq, Wk, Wv, Wo);

    // 2) QKV projections + fused RoPE + permuted head-major stores (64x64 tiles)
    qkv_gemm<<<dim3(12, 32), 128, GEMM_SMEM>>>(cs, sn);

    // 3) attention: grid (8 q-tiles of 256, 16 heads, 2 batch)
    attn_mma<<<dim3(SEQ / 256, NH, BB), 512, ATT_SMEM>>>();

    // 4) output projection (64x32 tiles, 16 warps/SM)
    out_gemm<<<dim3(8, 32), 256, GEMM_SMEM>>>(out);
}

// round 14
// speedup vs baseline: 1.0859x; 1.0103x over previous
#include <cuda_runtime.h>
#include <cstdint>

#define NH   16
#define NKV  4
#define HD   64
#define DM   1024
#define BB   2
#define SEQ  2048
#define MROWS (BB*SEQ)   // 4096

// Q pre-scale: HD^-0.5 * log2(e)  (softmax done in exp2 domain)
#define QSC 0.18033688011112042f

// ---------------------------------------------------------------------------
// Scratch (allocation-free device globals)
// ---------------------------------------------------------------------------
__device__ float g_xr [(size_t)MROWS * DM];       // tf32-rounded x
__device__ float g_wqr[(size_t)DM * DM];
__device__ float g_wkr[(size_t)DM * 256];
__device__ float g_wvr[(size_t)DM * 256];
__device__ float g_wor[(size_t)DM * DM];
__device__ float g_q  [(size_t)BB * NH  * SEQ * HD];  // head-major, d-permuted, *QSC, rope'd
__device__ float g_k  [(size_t)BB * NKV * SEQ * HD];  // head-major, d-permuted, rope'd
__device__ float g_v  [(size_t)BB * NKV * HD * SEQ];  // head-major TRANSPOSED: [d][seq]
__device__ float g_attn[(size_t)MROWS * DM];          // (b,n,1024), tf32-rounded

// ---------------------------------------------------------------------------
// helpers
// ---------------------------------------------------------------------------
__device__ __forceinline__ uint32_t f2tf(float f) {
    uint32_t u;
    asm("cvt.rna.tf32.f32 %0, %1;" : "=r"(u) : "f"(f));
    return u;
}
__device__ __forceinline__ float r2f(uint32_t u) { return __uint_as_float(u); }

__device__ __forceinline__ float ex2f(float x) {
    float r;
    asm("ex2.approx.ftz.f32 %0, %1;" : "=f"(r) : "f"(x));
    return r;
}
__device__ __forceinline__ int perm8p(int j) {
    int u = j & 7;
    return (j & ~7) + ((u < 4) ? 2 * u : 2 * (u - 4) + 1);
}
__device__ __forceinline__ void mma8(float c[4], const uint32_t a[4], const uint32_t b[2]) {
    asm volatile(
        "mma.sync.aligned.m16n8k8.row.col.f32.tf32.tf32.f32 "
        "{%0,%1,%2,%3},{%4,%5,%6,%7},{%8,%9},{%0,%1,%2,%3};"
        : "+f"(c[0]), "+f"(c[1]), "+f"(c[2]), "+f"(c[3])
        : "r"(a[0]), "r"(a[1]), "r"(a[2]), "r"(a[3]), "r"(b[0]), "r"(b[1]));
}
__device__ __forceinline__ void cpa16(uint32_t dst, const void* src) {
    asm volatile("cp.async.cg.shared.global [%0], [%1], 16;" :: "r"(dst), "l"(src) : "memory");
}
#define CPA_COMMIT() asm volatile("cp.async.commit_group;" ::: "memory")

// ---------------------------------------------------------------------------
// Pre-pass: round x + weights to the tf32 grid (then mma can eat them raw).
// ---------------------------------------------------------------------------
__global__ void prep_round(const float* __restrict__ x,  const float* __restrict__ Wq,
                           const float* __restrict__ Wk, const float* __restrict__ Wv,
                           const float* __restrict__ Wo)
{
    size_t i = (size_t)blockIdx.x * 256 + threadIdx.x;   // float4 index
    const float* src; float* dst; size_t off;
    if      (i < 1048576) { src = x;  dst = g_xr;  off = i; }
    else if (i < 1310720) { src = Wq; dst = g_wqr; off = i - 1048576; }
    else if (i < 1376256) { src = Wk; dst = g_wkr; off = i - 1310720; }
    else if (i < 1441792) { src = Wv; dst = g_wvr; off = i - 1376256; }
    else                  { src = Wo; dst = g_wor; off = i - 1441792; }
    float4 v = ((const float4*)src)[off];
    v.x = r2f(f2tf(v.x)); v.y = r2f(f2tf(v.y));
    v.z = r2f(f2tf(v.z)); v.w = r2f(f2tf(v.w));
    ((float4*)dst)[off] = v;
}

// ---------------------------------------------------------------------------
// Shared GEMM constants: 128x128 CTA tile, kstep 32.
// Stage: As[128][40] (5120 w) + Bs[32][132] (4224 w) = 9344 words.
// ---------------------------------------------------------------------------
#define GSTAGE 9344
#define GEMM_SMEM (3 * GSTAGE * 4)   // 112128 B (out_gemm: 3-stage, 2 CTA/SM)
#define QKV_SMEM  (2 * GSTAGE * 4)   //  74752 B (qkv: 2-stage, 3 CTA/SM)

// ---------------------------------------------------------------------------
// Variant A (out_gemm): 256 threads (8 warps), warp tile 64x32, 3-stage ring.
// 16 warps/SM at 2 CTAs/SM; 256 CTAs -> single wave. (R11-measured 58.6us)
// ---------------------------------------------------------------------------
__device__ __forceinline__ void gemm_main32(uint32_t* sm, uint32_t smb,
    const float* __restrict__ A, const float* __restrict__ B,
    int ldb, int n0, int row0, float acc[4][4][4])
{
    const int K = DM, KT = DM / 32;
    const int tid = threadIdx.x, lane = tid & 31, wid = tid >> 5;
    const int g = lane >> 2, t = lane & 3;
    const int m0 = (wid >> 2) * 64, nw = (wid & 3) * 32;

    const int ar = tid >> 3, ac = (tid & 7) << 2;
    const int bk = tid >> 5, bn = (tid & 31) << 2;
    const uint32_t aDst = (ar * 40 + ac) * 4;
    const uint32_t bDst = (5120 + bk * 132 + bn) * 4;
    const float* aS = A + (size_t)(row0 + ar) * K + ac;
    const float* bS = B + (size_t)bk * ldb + n0 + bn;

    auto issue = [&](int slot, int kt) {
        uint32_t base = smb + slot * (GSTAGE * 4);
        const float* a = aS + kt * 32;
        const float* b = bS + (size_t)kt * 32 * ldb;
#pragma unroll
        for (int i = 0; i < 4; i++)
            cpa16(base + aDst + i * (32 * 40 * 4), a + (size_t)i * 32 * K);
#pragma unroll
        for (int i = 0; i < 4; i++)
            cpa16(base + bDst + i * (8 * 132 * 4), b + (size_t)i * 8 * ldb);
        CPA_COMMIT();
    };

#pragma unroll
    for (int mi = 0; mi < 4; mi++)
#pragma unroll
        for (int ni = 0; ni < 4; ni++)
#pragma unroll
            for (int r = 0; r < 4; r++) acc[mi][ni][r] = 0.f;

    issue(0, 0);
    issue(1, 1);

    for (int kt = 0; kt < KT; kt++) {
        if (kt + 1 < KT) asm volatile("cp.async.wait_group 1;" ::: "memory");
        else             asm volatile("cp.async.wait_group 0;" ::: "memory");
        __syncthreads();
        if (kt + 2 < KT) issue((kt + 2) % 3, kt + 2);

        uint32_t* st = sm + (kt % 3) * GSTAGE;
        uint32_t (*As)[40]  = (uint32_t(*)[40])st;
        uint32_t (*Bs)[132] = (uint32_t(*)[132])(st + 5120);
#pragma unroll
        for (int kk0 = 0; kk0 < 32; kk0 += 8) {
            uint32_t a[4][4], b[4][2];
#pragma unroll
            for (int mi = 0; mi < 4; mi++) {
                int rb = m0 + mi * 16 + g;
                uint2 av0 = *(const uint2*)&As[rb][kk0 + 2 * t];
                uint2 av1 = *(const uint2*)&As[rb + 8][kk0 + 2 * t];
                a[mi][0] = av0.x; a[mi][1] = av1.x; a[mi][2] = av0.y; a[mi][3] = av1.y;
            }
#pragma unroll
            for (int ni = 0; ni < 4; ni++) {
                b[ni][0] = Bs[kk0 + 2 * t][nw + ni * 8 + g];
                b[ni][1] = Bs[kk0 + 2 * t + 1][nw + ni * 8 + g];
            }
#pragma unroll
            for (int mi = 0; mi < 4; mi++)
#pragma unroll
                for (int ni = 0; ni < 4; ni++)
                    mma8(acc[mi][ni], a[mi], b[ni]);
        }
    }
}

// ---------------------------------------------------------------------------
// Variant B2 (qkv): 128 threads (4 warps), warp tile 64x64, 2-STAGE ring ->
// 74.75 KB smem -> 3 CTAs/SM -> 384 CTAs in ONE wave, 12 warps/SM.
// Two barriers per k-step (slot reuse needs post-compute barrier).
// ---------------------------------------------------------------------------
__device__ __forceinline__ void gemm_main64_2s(uint32_t* sm, uint32_t smb,
    const float* __restrict__ A, const float* __restrict__ B,
    int ldb, int n0, int row0, float acc[4][8][4])
{
    const int K = DM, KT = DM / 32;
    const int tid = threadIdx.x, lane = tid & 31, wid = tid >> 5;  // wid 0..3
    const int g = lane >> 2, t = lane & 3;
    const int m0 = (wid >> 1) * 64, nw = (wid & 1) * 64;

    const int ar = tid >> 3, ac = (tid & 7) << 2;
    const int bk = tid >> 5, bn = (tid & 31) << 2;
    const uint32_t aDst = (ar * 40 + ac) * 4;
    const uint32_t bDst = (5120 + bk * 132 + bn) * 4;
    const float* aS = A + (size_t)(row0 + ar) * K + ac;
    const float* bS = B + (size_t)bk * ldb + n0 + bn;

    auto issue = [&](int slot, int kt) {
        uint32_t base = smb + slot * (GSTAGE * 4);
        const float* a = aS + kt * 32;
        const float* b = bS + (size_t)kt * 32 * ldb;
#pragma unroll
        for (int i = 0; i < 8; i++)
            cpa16(base + aDst + i * (16 * 40 * 4), a + (size_t)i * 16 * K);
#pragma unroll
        for (int i = 0; i < 8; i++)
            cpa16(base + bDst + i * (4 * 132 * 4), b + (size_t)i * 4 * ldb);
        CPA_COMMIT();
    };

#pragma unroll
    for (int mi = 0; mi < 4; mi++)
#pragma unroll
        for (int ni = 0; ni < 8; ni++)
#pragma unroll
            for (int r = 0; r < 4; r++) acc[mi][ni][r] = 0.f;

    issue(0, 0);
    issue(1, 1);

    for (int kt = 0; kt < KT; kt++) {
        if (kt + 1 < KT) asm volatile("cp.async.wait_group 1;" ::: "memory");
        else             asm volatile("cp.async.wait_group 0;" ::: "memory");
        __syncthreads();   // stage kt ready for all warps

        uint32_t* st = sm + (kt & 1) * GSTAGE;
        uint32_t (*As)[40]  = (uint32_t(*)[40])st;
        uint32_t (*Bs)[132] = (uint32_t(*)[132])(st + 5120);
#pragma unroll
        for (int kk0 = 0; kk0 < 32; kk0 += 8) {
            uint32_t a[4][4], b[8][2];
#pragma unroll
            for (int mi = 0; mi < 4; mi++) {
                int rb = m0 + mi * 16 + g;
                uint2 av0 = *(const uint2*)&As[rb][kk0 + 2 * t];
                uint2 av1 = *(const uint2*)&As[rb + 8][kk0 + 2 * t];
                a[mi][0] = av0.x; a[mi][1] = av1.x; a[mi][2] = av0.y; a[mi][3] = av1.y;
            }
#pragma unroll
            for (int ni = 0; ni < 8; ni++) {
                b[ni][0] = Bs[kk0 + 2 * t][nw + ni * 8 + g];
                b[ni][1] = Bs[kk0 + 2 * t + 1][nw + ni * 8 + g];
            }
#pragma unroll
            for (int mi = 0; mi < 4; mi++)
#pragma unroll
                for (int ni = 0; ni < 8; ni++)
                    mma8(acc[mi][ni], a[mi], b[ni]);
        }
        if (kt + 2 < KT) {
            __syncthreads();            // all warps done reading slot kt&1
            issue(kt & 1, kt + 2);      // refill it
        }
    }
}

// ---------------------------------------------------------------------------
// QKV projection + fused RoPE + permuted head-major stores (V transposed).
// grid (12, 32), 128 threads, 3 CTAs/SM: bx 0..7 -> Q, 8..9 -> K, 10..11 -> V.
// ---------------------------------------------------------------------------
__global__ __launch_bounds__(128, 3) void qkv_gemm(
    const float* __restrict__ cs, const float* __restrict__ sn)
{
    extern __shared__ uint32_t sm[];
    uint32_t smb = (uint32_t)__cvta_generic_to_shared(sm);
    const int bx = blockIdx.x, row0 = blockIdx.y * 128;
    const int tid = threadIdx.x, lane = tid & 31, wid = tid >> 5;
    const int g = lane >> 2, t = lane & 3;
    const int m0 = (wid >> 1) * 64, nw = (wid & 1) * 64;
    float acc[4][8][4];

    if (bx < 8) {
        gemm_main64_2s(sm, smb, g_xr, g_wqr, DM, bx * 128, row0, acc);
#pragma unroll
        for (int mi = 0; mi < 4; mi++)
#pragma unroll
            for (int ni = 0; ni < 8; ni++) {
                int gc = bx * 128 + nw + ni * 8 + 2 * t;       // even original col
                int head = gc >> 6, j = (gc & 63) >> 1;
                int pj = perm8p(j), pj2 = perm8p(j + 32);
#pragma unroll
                for (int rr = 0; rr < 2; rr++) {
                    int row = row0 + m0 + mi * 16 + g + rr * 8;
                    int n = row & (SEQ - 1), bi = row >> 11;
                    float cv = cs[n * 32 + j], sv = sn[n * 32 + j];
                    float a0 = acc[mi][ni][rr * 2], a1 = acc[mi][ni][rr * 2 + 1];
                    size_t bp = ((size_t)(bi * NH + head) * SEQ + n) * HD;
                    g_q[bp + pj]  = r2f(f2tf((a0 * cv - a1 * sv) * QSC));
                    g_q[bp + pj2] = r2f(f2tf((a0 * sv + a1 * cv) * QSC));
                }
            }
    } else if (bx < 10) {
        gemm_main64_2s(sm, smb, g_xr, g_wkr, 256, (bx - 8) * 128, row0, acc);
#pragma unroll
        for (int mi = 0; mi < 4; mi++)
#pragma unroll
            for (int ni = 0; ni < 8; ni++) {
                int gc = (bx - 8) * 128 + nw + ni * 8 + 2 * t;
                int kvh = gc >> 6, j = (gc & 63) >> 1;
                int pj = perm8p(j), pj2 = perm8p(j + 32);
#pragma unroll
                for (int rr = 0; rr < 2; rr++) {
                    int row = row0 + m0 + mi * 16 + g + rr * 8;
                    int n = row & (SEQ - 1), bi = row >> 11;
                    float cv = cs[n * 32 + j], sv = sn[n * 32 + j];
                    float a0 = acc[mi][ni][rr * 2], a1 = acc[mi][ni][rr * 2 + 1];
                    size_t bp = ((size_t)(bi * NKV + kvh) * SEQ + n) * HD;
                    g_k[bp + pj]  = r2f(f2tf(a0 * cv - a1 * sv));
                    g_k[bp + pj2] = r2f(f2tf(a0 * sv + a1 * cv));
                }
            }
    } else {
        gemm_main64_2s(sm, smb, g_xr, g_wvr, 256, (bx - 10) * 128, row0, acc);
#pragma unroll
        for (int mi = 0; mi < 4; mi++)
#pragma unroll
            for (int ni = 0; ni < 8; ni++) {
                int gc = (bx - 10) * 128 + nw + ni * 8 + 2 * t;
                int kvh = gc >> 6, d = gc & 63;
#pragma unroll
                for (int rr = 0; rr < 2; rr++) {
                    int row = row0 + m0 + mi * 16 + g + rr * 8;
                    int n = row & (SEQ - 1), bi = row >> 11;
                    size_t hb = ((size_t)(bi * NKV + kvh) * HD);
                    g_v[(hb + d) * SEQ + n]     = r2f(f2tf(acc[mi][ni][rr * 2]));
                    g_v[(hb + d + 1) * SEQ + n] = r2f(f2tf(acc[mi][ni][rr * 2 + 1]));
                }
            }
    }
}

// ---------------------------------------------------------------------------
// Output projection: grid (8, 32), 256 threads (variant A).
// ---------------------------------------------------------------------------
__global__ __launch_bounds__(256, 2) void out_gemm(float* __restrict__ out)
{
    extern __shared__ uint32_t sm[];
    uint32_t smb = (uint32_t)__cvta_generic_to_shared(sm);
    const int tid = threadIdx.x, lane = tid & 31, wid = tid >> 5;
    const int g = lane >> 2, t = lane & 3;
    const int m0 = (wid >> 2) * 64, nw = (wid & 3) * 32;
    const int n0 = blockIdx.x * 128, row0 = blockIdx.y * 128;
    float acc[4][4][4];
    gemm_main32(sm, smb, g_attn, g_wor, DM, n0, row0, acc);
#pragma unroll
    for (int mi = 0; mi < 4; mi++) {
        int r = row0 + m0 + mi * 16 + g;
#pragma unroll
        for (int ni = 0; ni < 4; ni++) {
            int c = n0 + nw + ni * 8 + 2 * t;
            *(float2*)(out + (size_t)r * DM + c)       = make_float2(acc[mi][ni][0], acc[mi][ni][1]);
            *(float2*)(out + (size_t)(r + 8) * DM + c) = make_float2(acc[mi][ni][2], acc[mi][ni][3]);
        }
    }
}

// ---------------------------------------------------------------------------
// Flash attention (unchanged R13): BM=256, 512 threads, 1 CTA/SM, Q in
// registers, 6-stage KV ring, two KV blocks per barrier, exp2 softmax.
// Smem (u32): 6 stages x (Ks[64*72]+Vt[64*72]=9216) = 55296 words = 221184 B.
// ---------------------------------------------------------------------------
#define ATT_SMEM 221184

__device__ __forceinline__ void attn_issue_kv(uint32_t smb, int slot,
    const float* __restrict__ Kb, const float* __restrict__ Vb, int kt, int tid)
{
    uint32_t base = smb + slot * 9216 * 4;
    const float* K0 = Kb + (size_t)kt * 64 * HD;
#pragma unroll
    for (int i = 0; i < 2; i++) {
        int c = tid + i * 512;
        int r = c >> 4, col = (c & 15) << 2;
        cpa16(base + (r * 72 + col) * 4, K0 + r * HD + col);
    }
#pragma unroll
    for (int i = 0; i < 2; i++) {
        int c = tid + i * 512;
        int r = c >> 4, col = (c & 15) << 2;
        cpa16(base + (4608 + r * 72 + col) * 4, Vb + (size_t)r * SEQ + kt * 64 + col);
    }
    CPA_COMMIT();
}

// S = Q*K^T with Q a-frags in registers
__device__ __forceinline__ void s_gemm_q(float s[8][4],
    const uint32_t q[8][4], const uint32_t* Ks, int g, int t)
{
#pragma unroll
    for (int ni = 0; ni < 8; ni++)
#pragma unroll
        for (int r = 0; r < 4; r++) s[ni][r] = 0.f;
#pragma unroll
    for (int kk = 0; kk < 8; kk++) {
#pragma unroll
        for (int ni = 0; ni < 8; ni++) {
            uint2 bv = *(const uint2*)&Ks[(ni * 8 + g) * 72 + kk * 8 + 2 * t];
            uint32_t bb[2] = {bv.x, bv.y};
            mma8(s[ni], q[kk], bb);
        }
    }
}

// online-softmax update on s + rescale o + O += P*V from Vt stage
__device__ __forceinline__ void softmax_pv(float s[8][4], float o[8][4],
    float& m0s, float& m1s, float& l0s, float& l1s,
    const uint32_t* Vt, int g, int t)
{
    float mx0 = -1e30f, mx1 = -1e30f;
#pragma unroll
    for (int ni = 0; ni < 8; ni++) {
        mx0 = fmaxf(mx0, fmaxf(s[ni][0], s[ni][1]));
        mx1 = fmaxf(mx1, fmaxf(s[ni][2], s[ni][3]));
    }
    mx0 = fmaxf(mx0, __shfl_xor_sync(0xffffffffu, mx0, 1));
    mx0 = fmaxf(mx0, __shfl_xor_sync(0xffffffffu, mx0, 2));
    mx1 = fmaxf(mx1, __shfl_xor_sync(0xffffffffu, mx1, 1));
    mx1 = fmaxf(mx1, __shfl_xor_sync(0xffffffffu, mx1, 2));

    float mn0 = fmaxf(m0s, mx0), mn1 = fmaxf(m1s, mx1);
    float cor0 = ex2f(m0s - mn0), cor1 = ex2f(m1s - mn1);
    m0s = mn0; m1s = mn1;

    float rs0 = 0.f, rs1 = 0.f;
#pragma unroll
    for (int ni = 0; ni < 8; ni++) {
        s[ni][0] = ex2f(s[ni][0] - mn0);
        s[ni][1] = ex2f(s[ni][1] - mn0);
        s[ni][2] = ex2f(s[ni][2] - mn1);
        s[ni][3] = ex2f(s[ni][3] - mn1);
        rs0 += s[ni][0] + s[ni][1];
        rs1 += s[ni][2] + s[ni][3];
    }
    rs0 += __shfl_xor_sync(0xffffffffu, rs0, 1);
    rs0 += __shfl_xor_sync(0xffffffffu, rs0, 2);
    rs1 += __shfl_xor_sync(0xffffffffu, rs1, 1);
    rs1 += __shfl_xor_sync(0xffffffffu, rs1, 2);
    l0s = l0s * cor0 + rs0;
    l1s = l1s * cor1 + rs1;

#pragma unroll
    for (int ni = 0; ni < 8; ni++) {
        o[ni][0] *= cor0; o[ni][1] *= cor0;
        o[ni][2] *= cor1; o[ni][3] *= cor1;
    }
#pragma unroll
    for (int kk = 0; kk < 8; kk++) {
        uint32_t a[4];
        a[0] = f2tf(s[kk][0]);
        a[1] = f2tf(s[kk][2]);
        a[2] = f2tf(s[kk][1]);
        a[3] = f2tf(s[kk][3]);
#pragma unroll
        for (int ni = 0; ni < 8; ni++) {
            uint2 bv = *(const uint2*)&Vt[(ni * 8 + g) * 72 + kk * 8 + 2 * t];
            uint32_t bb[2] = {bv.x, bv.y};
            mma8(o[ni], a, bb);
        }
    }
}

__global__ __launch_bounds__(512, 1) void attn_mma()
{
    extern __shared__ uint32_t sm[];
    uint32_t smb = (uint32_t)__cvta_generic_to_shared(sm);
    const int b = blockIdx.z, h = blockIdx.y;
    const int n0 = blockIdx.x * 256;
    const int kvh = h >> 2;
    const int tid = threadIdx.x, lane = tid & 31, wid = tid >> 5;  // wid 0..15
    const int g = lane >> 2, t = lane & 3;
    const int m0 = wid * 16;

    const float* Kb = g_k + ((size_t)(b * NKV + kvh) * SEQ) * HD;
    const float* Vb = g_v + ((size_t)(b * NKV + kvh) * HD) * SEQ;

    // prefetch 4 KV stages
    attn_issue_kv(smb, 0, Kb, Vb, 0, tid);
    attn_issue_kv(smb, 1, Kb, Vb, 1, tid);
    attn_issue_kv(smb, 2, Kb, Vb, 2, tid);
    attn_issue_kv(smb, 3, Kb, Vb, 3, tid);

    // Q a-frags directly from global (values already on the tf32 grid)
    uint32_t q[8][4];
    {
        const uint32_t* Qg = (const uint32_t*)(g_q +
            ((size_t)(b * NH + h) * SEQ + n0 + m0) * HD);
        const uint32_t* r0p = Qg + g * HD;
        const uint32_t* r1p = Qg + (g + 8) * HD;
#pragma unroll
        for (int kk = 0; kk < 8; kk++) {
            uint2 u0 = *(const uint2*)(r0p + kk * 8 + 2 * t);
            uint2 u1 = *(const uint2*)(r1p + kk * 8 + 2 * t);
            q[kk][0] = u0.x; q[kk][1] = u1.x; q[kk][2] = u0.y; q[kk][3] = u1.y;
        }
    }

    float m0s = -1e30f, m1s = -1e30f, l0s = 0.f, l1s = 0.f;
    float s[8][4], o[8][4];
#pragma unroll
    for (int ni = 0; ni < 8; ni++)
#pragma unroll
        for (int r = 0; r < 4; r++) o[ni][r] = 0.f;

    const int KT = SEQ / 64;   // 32, processed in pairs
    for (int kt = 0; kt < KT; kt += 2) {
        if (kt + 2 < KT) asm volatile("cp.async.wait_group 2;" ::: "memory");
        else             asm volatile("cp.async.wait_group 0;" ::: "memory");
        __syncthreads();
        if (kt + 4 < KT) attn_issue_kv(smb, (kt + 4) % 6, Kb, Vb, kt + 4, tid);
        if (kt + 5 < KT) attn_issue_kv(smb, (kt + 5) % 6, Kb, Vb, kt + 5, tid);

        {
            uint32_t* Ks = sm + (kt % 6) * 9216;
            s_gemm_q(s, q, Ks, g, t);
            softmax_pv(s, o, m0s, m1s, l0s, l1s, Ks + 4608, g, t);
        }
        {
            uint32_t* Ks = sm + ((kt + 1) % 6) * 9216;
            s_gemm_q(s, q, Ks, g, t);
            softmax_pv(s, o, m0s, m1s, l0s, l1s, Ks + 4608, g, t);
        }
    }

    // epilogue: normalize, round to tf32, write (b,n,1024) for out_gemm
    float inv0 = 1.f / l0s, inv1 = 1.f / l1s;
    size_t r0 = (size_t)b * SEQ + n0 + m0 + g;
#pragma unroll
    for (int ni = 0; ni < 8; ni++) {
        int col = h * HD + ni * 8 + 2 * t;
        *(float2*)&g_attn[r0 * DM + col] =
            make_float2(r2f(f2tf(o[ni][0] * inv0)), r2f(f2tf(o[ni][1] * inv0)));
        *(float2*)&g_attn[(r0 + 8) * DM + col] =
            make_float2(r2f(f2tf(o[ni][2] * inv1)), r2f(f2tf(o[ni][3] * inv1)));
    }
}

// ---------------------------------------------------------------------------
extern "C" void kernel_launch(void* const* d_in, const int* in_sizes, int n_in,
                              void* d_out, int out_size)
{
    const float* x  = (const float*)d_in[0];
    const float* cs = (const float*)d_in[1];
    const float* sn = (const float*)d_in[2];
    const float* Wq = (const float*)d_in[3];
    const float* Wk = (const float*)d_in[4];
    const float* Wv = (const float*)d_in[5];
    const float* Wo = (const float*)d_in[6];
    float* out = (float*)d_out;
    (void)in_sizes; (void)n_in; (void)out_size;

    cudaFuncSetAttribute(qkv_gemm, cudaFuncAttributeMaxDynamicSharedMemorySize, QKV_SMEM);
    cudaFuncSetAttribute(out_gemm, cudaFuncAttributeMaxDynamicSharedMemorySize, GEMM_SMEM);
    cudaFuncSetAttribute(attn_mma, cudaFuncAttributeMaxDynamicSharedMemorySize, ATT_SMEM);

    // 1) round x + weights onto the tf32 grid
    prep_round<<<6656, 256>>>(x, Wq, Wk, Wv, Wo);

    // 2) QKV projections + fused RoPE (64x64 tiles, 2-stage, 3 CTAs/SM)
    qkv_gemm<<<dim3(12, 32), 128, QKV_SMEM>>>(cs, sn);

    // 3) attention: grid (8 q-tiles of 256, 16 heads, 2 batch)
    attn_mma<<<dim3(SEQ / 256, NH, BB), 512, ATT_SMEM>>>();

    // 4) output projection (64x32 tiles, 3-stage, 16 warps/SM)
    out_gemm<<<dim3(8, 32), 256, GEMM_SMEM>>>(out);
}

// round 16
// speedup vs baseline: 1.2165x; 1.1202x over previous
#include <cuda_runtime.h>
#include <cuda_fp16.h>
#include <cstdint>

#define NH   16
#define NKV  4
#define HD   64
#define DM   1024
#define BB   2
#define SEQ  2048
#define MROWS (BB*SEQ)   // 4096

// Q pre-scale: HD^-0.5 * log2(e)  (softmax done in exp2 domain)
#define QSC 0.18033688011112042f

// ---------------------------------------------------------------------------
// Scratch (allocation-free device globals)
// ---------------------------------------------------------------------------
__device__ float g_xr [(size_t)MROWS * DM];       // tf32-rounded x
__device__ float g_wqr[(size_t)DM * DM];
__device__ float g_wkr[(size_t)DM * 256];
__device__ float g_wvr[(size_t)DM * 256];
__device__ float g_wor[(size_t)DM * DM];
__device__ float g_q  [(size_t)BB * NH  * SEQ * HD];  // head-major, d-permuted, *QSC, rope'd
__device__ float g_k  [(size_t)BB * NKV * SEQ * HD];  // head-major, d-permuted, rope'd
__device__ __half g_v[(size_t)BB * NKV * HD * SEQ];   // TRANSPOSED [d][seq], fp16, key-pair-permuted
__device__ float g_attn[(size_t)MROWS * DM];          // (b,n,1024), tf32-rounded

// ---------------------------------------------------------------------------
// helpers
// ---------------------------------------------------------------------------
__device__ __forceinline__ uint32_t f2tf(float f) {
    uint32_t u;
    asm("cvt.rna.tf32.f32 %0, %1;" : "=r"(u) : "f"(f));
    return u;
}
__device__ __forceinline__ float r2f(uint32_t u) { return __uint_as_float(u); }

__device__ __forceinline__ float ex2f(float x) {
    float r;
    asm("ex2.approx.ftz.f32 %0, %1;" : "=f"(r) : "f"(x));
    return r;
}
__device__ __forceinline__ int perm8p(int j) {
    int u = j & 7;
    return (j & ~7) + ((u < 4) ? 2 * u : 2 * (u - 4) + 1);
}
// fp16 index of key n within a g_v row (pair u -> u32 pos 2u | 2(u-4)+1 per 16)
__device__ __forceinline__ int vremap(int n) {
    int u = (n >> 1) & 7, h = n & 1;
    int pos = (u < 4) ? 2 * u : 2 * (u - 4) + 1;
    return (n & ~15) + pos * 2 + h;
}
__device__ __forceinline__ uint32_t packh(float lo, float hi) {
    uint32_t r;
    asm("cvt.rn.f16x2.f32 %0, %1, %2;" : "=r"(r) : "f"(hi), "f"(lo));
    return r;
}
__device__ __forceinline__ void mma8(float c[4], const uint32_t a[4], const uint32_t b[2]) {
    asm volatile(
        "mma.sync.aligned.m16n8k8.row.col.f32.tf32.tf32.f32 "
        "{%0,%1,%2,%3},{%4,%5,%6,%7},{%8,%9},{%0,%1,%2,%3};"
        : "+f"(c[0]), "+f"(c[1]), "+f"(c[2]), "+f"(c[3])
        : "r"(a[0]), "r"(a[1]), "r"(a[2]), "r"(a[3]), "r"(b[0]), "r"(b[1]));
}
__device__ __forceinline__ void mma16h(float c[4], const uint32_t a[4], uint32_t b0, uint32_t b1) {
    asm volatile(
        "mma.sync.aligned.m16n8k16.row.col.f32.f16.f16.f32 "
        "{%0,%1,%2,%3},{%4,%5,%6,%7},{%8,%9},{%0,%1,%2,%3};"
        : "+f"(c[0]), "+f"(c[1]), "+f"(c[2]), "+f"(c[3])
        : "r"(a[0]), "r"(a[1]), "r"(a[2]), "r"(a[3]), "r"(b0), "r"(b1));
}
__device__ __forceinline__ void cpa16(uint32_t dst, const void* src) {
    asm volatile("cp.async.cg.shared.global [%0], [%1], 16;" :: "r"(dst), "l"(src) : "memory");
}
#define CPA_COMMIT() asm volatile("cp.async.commit_group;" ::: "memory")

// ---------------------------------------------------------------------------
// Pre-pass: round x + weights to the tf32 grid (then mma can eat them raw).
// ---------------------------------------------------------------------------
__global__ void prep_round(const float* __restrict__ x,  const float* __restrict__ Wq,
                           const float* __restrict__ Wk, const float* __restrict__ Wv,
                           const float* __restrict__ Wo)
{
    size_t i = (size_t)blockIdx.x * 256 + threadIdx.x;   // float4 index
    const float* src; float* dst; size_t off;
    if      (i < 1048576) { src = x;  dst = g_xr;  off = i; }
    else if (i < 1310720) { src = Wq; dst = g_wqr; off = i - 1048576; }
    else if (i < 1376256) { src = Wk; dst = g_wkr; off = i - 1310720; }
    else if (i < 1441792) { src = Wv; dst = g_wvr; off = i - 1376256; }
    else                  { src = Wo; dst = g_wor; off = i - 1441792; }
    float4 v = ((const float4*)src)[off];
    v.x = r2f(f2tf(v.x)); v.y = r2f(f2tf(v.y));
    v.z = r2f(f2tf(v.z)); v.w = r2f(f2tf(v.w));
    ((float4*)dst)[off] = v;
}

// ---------------------------------------------------------------------------
// Shared GEMM constants: 128x128 CTA tile, kstep 32.
// Stage: As[128][40] (5120 w) + Bs[32][132] (4224 w) = 9344 words.
// ---------------------------------------------------------------------------
#define GSTAGE 9344
#define GEMM_SMEM (3 * GSTAGE * 4)   // 112128 B (out_gemm: 3-stage, 2 CTA/SM)
#define QKV_SMEM  (2 * GSTAGE * 4)   //  74752 B (qkv: 2-stage, 3 CTA/SM)

// ---------------------------------------------------------------------------
// Variant A (out_gemm): 256 threads (8 warps), warp tile 64x32, 3-stage ring.
// ---------------------------------------------------------------------------
__device__ __forceinline__ void gemm_main32(uint32_t* sm, uint32_t smb,
    const float* __restrict__ A, const float* __restrict__ B,
    int ldb, int n0, int row0, float acc[4][4][4])
{
    const int K = DM, KT = DM / 32;
    const int tid = threadIdx.x, lane = tid & 31, wid = tid >> 5;
    const int g = lane >> 2, t = lane & 3;
    const int m0 = (wid >> 2) * 64, nw = (wid & 3) * 32;

    const int ar = tid >> 3, ac = (tid & 7) << 2;
    const int bk = tid >> 5, bn = (tid & 31) << 2;
    const uint32_t aDst = (ar * 40 + ac) * 4;
    const uint32_t bDst = (5120 + bk * 132 + bn) * 4;
    const float* aS = A + (size_t)(row0 + ar) * K + ac;
    const float* bS = B + (size_t)bk * ldb + n0 + bn;

    auto issue = [&](int slot, int kt) {
        uint32_t base = smb + slot * (GSTAGE * 4);
        const float* a = aS + kt * 32;
        const float* b = bS + (size_t)kt * 32 * ldb;
#pragma unroll
        for (int i = 0; i < 4; i++)
            cpa16(base + aDst + i * (32 * 40 * 4), a + (size_t)i * 32 * K);
#pragma unroll
        for (int i = 0; i < 4; i++)
            cpa16(base + bDst + i * (8 * 132 * 4), b + (size_t)i * 8 * ldb);
        CPA_COMMIT();
    };

#pragma unroll
    for (int mi = 0; mi < 4; mi++)
#pragma unroll
        for (int ni = 0; ni < 4; ni++)
#pragma unroll
            for (int r = 0; r < 4; r++) acc[mi][ni][r] = 0.f;

    issue(0, 0);
    issue(1, 1);

    for (int kt = 0; kt < KT; kt++) {
        if (kt + 1 < KT) asm volatile("cp.async.wait_group 1;" ::: "memory");
        else             asm volatile("cp.async.wait_group 0;" ::: "memory");
        __syncthreads();
        if (kt + 2 < KT) issue((kt + 2) % 3, kt + 2);

        uint32_t* st = sm + (kt % 3) * GSTAGE;
        uint32_t (*As)[40]  = (uint32_t(*)[40])st;
        uint32_t (*Bs)[132] = (uint32_t(*)[132])(st + 5120);
#pragma unroll
        for (int kk0 = 0; kk0 < 32; kk0 += 8) {
            uint32_t a[4][4], b[4][2];
#pragma unroll
            for (int mi = 0; mi < 4; mi++) {
                int rb = m0 + mi * 16 + g;
                uint2 av0 = *(const uint2*)&As[rb][kk0 + 2 * t];
                uint2 av1 = *(const uint2*)&As[rb + 8][kk0 + 2 * t];
                a[mi][0] = av0.x; a[mi][1] = av1.x; a[mi][2] = av0.y; a[mi][3] = av1.y;
            }
#pragma unroll
            for (int ni = 0; ni < 4; ni++) {
                b[ni][0] = Bs[kk0 + 2 * t][nw + ni * 8 + g];
                b[ni][1] = Bs[kk0 + 2 * t + 1][nw + ni * 8 + g];
            }
#pragma unroll
            for (int mi = 0; mi < 4; mi++)
#pragma unroll
                for (int ni = 0; ni < 4; ni++)
                    mma8(acc[mi][ni], a[mi], b[ni]);
        }
    }
}

// ---------------------------------------------------------------------------
// Variant B2 (qkv): 128 threads (4 warps), warp tile 64x64, 2-stage ring,
// 3 CTAs/SM -> 384 CTAs in one wave.
// ---------------------------------------------------------------------------
__device__ __forceinline__ void gemm_main64_2s(uint32_t* sm, uint32_t smb,
    const float* __restrict__ A, const float* __restrict__ B,
    int ldb, int n0, int row0, float acc[4][8][4])
{
    const int K = DM, KT = DM / 32;
    const int tid = threadIdx.x, lane = tid & 31, wid = tid >> 5;  // wid 0..3
    const int g = lane >> 2, t = lane & 3;
    const int m0 = (wid >> 1) * 64, nw = (wid & 1) * 64;

    const int ar = tid >> 3, ac = (tid & 7) << 2;
    const int bk = tid >> 5, bn = (tid & 31) << 2;
    const uint32_t aDst = (ar * 40 + ac) * 4;
    const uint32_t bDst = (5120 + bk * 132 + bn) * 4;
    const float* aS = A + (size_t)(row0 + ar) * K + ac;
    const float* bS = B + (size_t)bk * ldb + n0 + bn;

    auto issue = [&](int slot, int kt) {
        uint32_t base = smb + slot * (GSTAGE * 4);
        const float* a = aS + kt * 32;
        const float* b = bS + (size_t)kt * 32 * ldb;
#pragma unroll
        for (int i = 0; i < 8; i++)
            cpa16(base + aDst + i * (16 * 40 * 4), a + (size_t)i * 16 * K);
#pragma unroll
        for (int i = 0; i < 8; i++)
            cpa16(base + bDst + i * (4 * 132 * 4), b + (size_t)i * 4 * ldb);
        CPA_COMMIT();
    };

#pragma unroll
    for (int mi = 0; mi < 4; mi++)
#pragma unroll
        for (int ni = 0; ni < 8; ni++)
#pragma unroll
            for (int r = 0; r < 4; r++) acc[mi][ni][r] = 0.f;

    issue(0, 0);
    issue(1, 1);

    for (int kt = 0; kt < KT; kt++) {
        if (kt + 1 < KT) asm volatile("cp.async.wait_group 1;" ::: "memory");
        else             asm volatile("cp.async.wait_group 0;" ::: "memory");
        __syncthreads();   // stage kt ready for all warps

        uint32_t* st = sm + (kt & 1) * GSTAGE;
        uint32_t (*As)[40]  = (uint32_t(*)[40])st;
        uint32_t (*Bs)[132] = (uint32_t(*)[132])(st + 5120);
#pragma unroll
        for (int kk0 = 0; kk0 < 32; kk0 += 8) {
            uint32_t a[4][4], b[8][2];
#pragma unroll
            for (int mi = 0; mi < 4; mi++) {
                int rb = m0 + mi * 16 + g;
                uint2 av0 = *(const uint2*)&As[rb][kk0 + 2 * t];
                uint2 av1 = *(const uint2*)&As[rb + 8][kk0 + 2 * t];
                a[mi][0] = av0.x; a[mi][1] = av1.x; a[mi][2] = av0.y; a[mi][3] = av1.y;
            }
#pragma unroll
            for (int ni = 0; ni < 8; ni++) {
                b[ni][0] = Bs[kk0 + 2 * t][nw + ni * 8 + g];
                b[ni][1] = Bs[kk0 + 2 * t + 1][nw + ni * 8 + g];
            }
#pragma unroll
            for (int mi = 0; mi < 4; mi++)
#pragma unroll
                for (int ni = 0; ni < 8; ni++)
                    mma8(acc[mi][ni], a[mi], b[ni]);
        }
        if (kt + 2 < KT) {
            __syncthreads();            // all warps done reading slot kt&1
            issue(kt & 1, kt + 2);      // refill it
        }
    }
}

// ---------------------------------------------------------------------------
// QKV projection + fused RoPE + permuted head-major stores (V: fp16 transposed
// + key-pair-permuted). grid (12, 32), 128 threads, 3 CTAs/SM.
// ---------------------------------------------------------------------------
__global__ __launch_bounds__(128, 3) void qkv_gemm(
    const float* __restrict__ cs, const float* __restrict__ sn)
{
    extern __shared__ uint32_t sm[];
    uint32_t smb = (uint32_t)__cvta_generic_to_shared(sm);
    const int bx = blockIdx.x, row0 = blockIdx.y * 128;
    const int tid = threadIdx.x, lane = tid & 31, wid = tid >> 5;
    const int g = lane >> 2, t = lane & 3;
    const int m0 = (wid >> 1) * 64, nw = (wid & 1) * 64;
    float acc[4][8][4];

    if (bx < 8) {
        gemm_main64_2s(sm, smb, g_xr, g_wqr, DM, bx * 128, row0, acc);
#pragma unroll
        for (int mi = 0; mi < 4; mi++)
#pragma unroll
            for (int ni = 0; ni < 8; ni++) {
                int gc = bx * 128 + nw + ni * 8 + 2 * t;       // even original col
                int head = gc >> 6, j = (gc & 63) >> 1;
                int pj = perm8p(j), pj2 = perm8p(j + 32);
#pragma unroll
                for (int rr = 0; rr < 2; rr++) {
                    int row = row0 + m0 + mi * 16 + g + rr * 8;
                    int n = row & (SEQ - 1), bi = row >> 11;
                    float cv = cs[n * 32 + j], sv = sn[n * 32 + j];
                    float a0 = acc[mi][ni][rr * 2], a1 = acc[mi][ni][rr * 2 + 1];
                    size_t bp = ((size_t)(bi * NH + head) * SEQ + n) * HD;
                    g_q[bp + pj]  = r2f(f2tf((a0 * cv - a1 * sv) * QSC));
                    g_q[bp + pj2] = r2f(f2tf((a0 * sv + a1 * cv) * QSC));
                }
            }
    } else if (bx < 10) {
        gemm_main64_2s(sm, smb, g_xr, g_wkr, 256, (bx - 8) * 128, row0, acc);
#pragma unroll
        for (int mi = 0; mi < 4; mi++)
#pragma unroll
            for (int ni = 0; ni < 8; ni++) {
                int gc = (bx - 8) * 128 + nw + ni * 8 + 2 * t;
                int kvh = gc >> 6, j = (gc & 63) >> 1;
                int pj = perm8p(j), pj2 = perm8p(j + 32);
#pragma unroll
                for (int rr = 0; rr < 2; rr++) {
                    int row = row0 + m0 + mi * 16 + g + rr * 8;
                    int n = row & (SEQ - 1), bi = row >> 11;
                    float cv = cs[n * 32 + j], sv = sn[n * 32 + j];
                    float a0 = acc[mi][ni][rr * 2], a1 = acc[mi][ni][rr * 2 + 1];
                    size_t bp = ((size_t)(bi * NKV + kvh) * SEQ + n) * HD;
                    g_k[bp + pj]  = r2f(f2tf(a0 * cv - a1 * sv));
                    g_k[bp + pj2] = r2f(f2tf(a0 * sv + a1 * cv));
                }
            }
    } else {
        gemm_main64_2s(sm, smb, g_xr, g_wvr, 256, (bx - 10) * 128, row0, acc);
        // V: fp16 transposed store g_v[bh][d][key], key-pair-permuted per 16
#pragma unroll
        for (int mi = 0; mi < 4; mi++)
#pragma unroll
            for (int ni = 0; ni < 8; ni++) {
                int gc = (bx - 10) * 128 + nw + ni * 8 + 2 * t;
                int kvh = gc >> 6, d = gc & 63;
#pragma unroll
                for (int rr = 0; rr < 2; rr++) {
                    int row = row0 + m0 + mi * 16 + g + rr * 8;
                    int n = row & (SEQ - 1), bi = row >> 11;
                    int nv = vremap(n);
                    size_t hb = (size_t)(bi * NKV + kvh) * HD;
                    g_v[(hb + d) * SEQ + nv]     = __float2half(acc[mi][ni][rr * 2]);
                    g_v[(hb + d + 1) * SEQ + nv] = __float2half(acc[mi][ni][rr * 2 + 1]);
                }
            }
    }
}

// ---------------------------------------------------------------------------
// Output projection: grid (8, 32), 256 threads (variant A).
// ---------------------------------------------------------------------------
__global__ __launch_bounds__(256, 2) void out_gemm(float* __restrict__ out)
{
    extern __shared__ uint32_t sm[];
    uint32_t smb = (uint32_t)__cvta_generic_to_shared(sm);
    const int tid = threadIdx.x, lane = tid & 31, wid = tid >> 5;
    const int g = lane >> 2, t = lane & 3;
    const int m0 = (wid >> 2) * 64, nw = (wid & 3) * 32;
    const int n0 = blockIdx.x * 128, row0 = blockIdx.y * 128;
    float acc[4][4][4];
    gemm_main32(sm, smb, g_attn, g_wor, DM, n0, row0, acc);
#pragma unroll
    for (int mi = 0; mi < 4; mi++) {
        int r = row0 + m0 + mi * 16 + g;
#pragma unroll
        for (int ni = 0; ni < 4; ni++) {
            int c = n0 + nw + ni * 8 + 2 * t;
            *(float2*)(out + (size_t)r * DM + c)       = make_float2(acc[mi][ni][0], acc[mi][ni][1]);
            *(float2*)(out + (size_t)(r + 8) * DM + c) = make_float2(acc[mi][ni][2], acc[mi][ni][3]);
        }
    }
}

// ---------------------------------------------------------------------------
// Flash attention: BM=256, 512 threads, 1 CTA/SM, Q in registers,
// 6-stage KV ring, two KV blocks per barrier. QK^T in tf32; P*V in fp16
// (m16n8k16): V tile fp16 64x64 keys (row ld 40 u32, keys pair-permuted).
// Stage: Ks 64*72=4608 w + Vt 64*40=2560 w = 7168 w. 6 stages = 172032 B.
// ---------------------------------------------------------------------------
#define ASTG 7168
#define ATT_SMEM (6 * ASTG * 4)   // 172032

__device__ __forceinline__ void attn_issue_kv(uint32_t smb, int slot,
    const float* __restrict__ Kb, const __half* __restrict__ Vb, int kt, int tid)
{
    uint32_t base = smb + slot * (ASTG * 4);
    const float* K0 = Kb + (size_t)kt * 64 * HD;
#pragma unroll
    for (int i = 0; i < 2; i++) {
        int c = tid + i * 512;
        int r = c >> 4, col = (c & 15) << 2;
        cpa16(base + (r * 72 + col) * 4, K0 + r * HD + col);
    }
    // V fp16 tile: 64 d-rows x 64 keys (128 B/row), 512 chunks of 16 B
    {
        int r = tid >> 3, col = tid & 7;
        cpa16(base + (4608 + r * 40 + col * 4) * 4,
              Vb + (size_t)r * SEQ + kt * 64 + col * 8);
    }
    CPA_COMMIT();
}

// S = Q*K^T with Q a-frags in registers (tf32)
__device__ __forceinline__ void s_gemm_q(float s[8][4],
    const uint32_t q[8][4], const uint32_t* Ks, int g, int t)
{
#pragma unroll
    for (int ni = 0; ni < 8; ni++)
#pragma unroll
        for (int r = 0; r < 4; r++) s[ni][r] = 0.f;
#pragma unroll
    for (int kk = 0; kk < 8; kk++) {
#pragma unroll
        for (int ni = 0; ni < 8; ni++) {
            uint2 bv = *(const uint2*)&Ks[(ni * 8 + g) * 72 + kk * 8 + 2 * t];
            uint32_t bb[2] = {bv.x, bv.y};
            mma8(s[ni], q[kk], bb);
        }
    }
}

// online-softmax update on s + rescale o + O += P*V (fp16 k16) from Vt stage
__device__ __forceinline__ void softmax_pv(float s[8][4], float o[8][4],
    float& m0s, float& m1s, float& l0s, float& l1s,
    const uint32_t* Vt, int g, int t)
{
    float mx0 = -1e30f, mx1 = -1e30f;
#pragma unroll
    for (int ni = 0; ni < 8; ni++) {
        mx0 = fmaxf(mx0, fmaxf(s[ni][0], s[ni][1]));
        mx1 = fmaxf(mx1, fmaxf(s[ni][2], s[ni][3]));
    }
    mx0 = fmaxf(mx0, __shfl_xor_sync(0xffffffffu, mx0, 1));
    mx0 = fmaxf(mx0, __shfl_xor_sync(0xffffffffu, mx0, 2));
    mx1 = fmaxf(mx1, __shfl_xor_sync(0xffffffffu, mx1, 1));
    mx1 = fmaxf(mx1, __shfl_xor_sync(0xffffffffu, mx1, 2));

    float mn0 = fmaxf(m0s, mx0), mn1 = fmaxf(m1s, mx1);
    float cor0 = ex2f(m0s - mn0), cor1 = ex2f(m1s - mn1);
    m0s = mn0; m1s = mn1;

    float rs0 = 0.f, rs1 = 0.f;
#pragma unroll
    for (int ni = 0; ni < 8; ni++) {
        s[ni][0] = ex2f(s[ni][0] - mn0);
        s[ni][1] = ex2f(s[ni][1] - mn0);
        s[ni][2] = ex2f(s[ni][2] - mn1);
        s[ni][3] = ex2f(s[ni][3] - mn1);
        rs0 += s[ni][0] + s[ni][1];
        rs1 += s[ni][2] + s[ni][3];
    }
    rs0 += __shfl_xor_sync(0xffffffffu, rs0, 1);
    rs0 += __shfl_xor_sync(0xffffffffu, rs0, 2);
    rs1 += __shfl_xor_sync(0xffffffffu, rs1, 1);
    rs1 += __shfl_xor_sync(0xffffffffu, rs1, 2);
    l0s = l0s * cor0 + rs0;
    l1s = l1s * cor1 + rs1;

#pragma unroll
    for (int ni = 0; ni < 8; ni++) {
        o[ni][0] *= cor0; o[ni][1] *= cor0;
        o[ni][2] *= cor1; o[ni][3] *= cor1;
    }
    // P*V in fp16: k=16 per mma; A-frag = packed S C-frags of blocks 2kk2,2kk2+1
#pragma unroll
    for (int kk2 = 0; kk2 < 4; kk2++) {
        uint32_t a[4];
        a[0] = packh(s[2 * kk2][0],     s[2 * kk2][1]);       // row g,   k=2t,2t+1
        a[1] = packh(s[2 * kk2][2],     s[2 * kk2][3]);       // row g+8
        a[2] = packh(s[2 * kk2 + 1][0], s[2 * kk2 + 1][1]);   // row g,   k=2t+8,2t+9
        a[3] = packh(s[2 * kk2 + 1][2], s[2 * kk2 + 1][3]);   // row g+8
#pragma unroll
        for (int ni = 0; ni < 8; ni++) {
            uint2 bv = *(const uint2*)&Vt[(ni * 8 + g) * 40 + kk2 * 8 + 2 * t];
            mma16h(o[ni], a, bv.x, bv.y);
        }
    }
}

__global__ __launch_bounds__(512, 1) void attn_mma()
{
    extern __shared__ uint32_t sm[];
    uint32_t smb = (uint32_t)__cvta_generic_to_shared(sm);
    const int b = blockIdx.z, h = blockIdx.y;
    const int n0 = blockIdx.x * 256;
    const int kvh = h >> 2;
    const int tid = threadIdx.x, lane = tid & 31, wid = tid >> 5;  // wid 0..15
    const int g = lane >> 2, t = lane & 3;
    const int m0 = wid * 16;

    const float* Kb = g_k + ((size_t)(b * NKV + kvh) * SEQ) * HD;
    const __half* Vb = g_v + ((size_t)(b * NKV + kvh) * HD) * SEQ;

    // prefetch 4 KV stages
    attn_issue_kv(smb, 0, Kb, Vb, 0, tid);
    attn_issue_kv(smb, 1, Kb, Vb, 1, tid);
    attn_issue_kv(smb, 2, Kb, Vb, 2, tid);
    attn_issue_kv(smb, 3, Kb, Vb, 3, tid);

    // Q a-frags directly from global (values already on the tf32 grid)
    uint32_t q[8][4];
    {
        const uint32_t* Qg = (const uint32_t*)(g_q +
            ((size_t)(b * NH + h) * SEQ + n0 + m0) * HD);
        const uint32_t* r0p = Qg + g * HD;
        const uint32_t* r1p = Qg + (g + 8) * HD;
#pragma unroll
        for (int kk = 0; kk < 8; kk++) {
            uint2 u0 = *(const uint2*)(r0p + kk * 8 + 2 * t);
            uint2 u1 = *(const uint2*)(r1p + kk * 8 + 2 * t);
            q[kk][0] = u0.x; q[kk][1] = u1.x; q[kk][2] = u0.y; q[kk][3] = u1.y;
        }
    }

    float m0s = -1e30f, m1s = -1e30f, l0s = 0.f, l1s = 0.f;
    float s[8][4], o[8][4];
#pragma unroll
    for (int ni = 0; ni < 8; ni++)
#pragma unroll
        for (int r = 0; r < 4; r++) o[ni][r] = 0.f;

    const int KT = SEQ / 64;   // 32, processed in pairs
    for (int kt = 0; kt < KT; kt += 2) {
        if (kt + 2 < KT) asm volatile("cp.async.wait_group 2;" ::: "memory");
        else             asm volatile("cp.async.wait_group 0;" ::: "memory");
        __syncthreads();
        if (kt + 4 < KT) attn_issue_kv(smb, (kt + 4) % 6, Kb, Vb, kt + 4, tid);
        if (kt + 5 < KT) attn_issue_kv(smb, (kt + 5) % 6, Kb, Vb, kt + 5, tid);

        {
            uint32_t* Ks = sm + (kt % 6) * ASTG;
            s_gemm_q(s, q, Ks, g, t);
            softmax_pv(s, o, m0s, m1s, l0s, l1s, Ks + 4608, g, t);
        }
        {
            uint32_t* Ks = sm + ((kt + 1) % 6) * ASTG;
            s_gemm_q(s, q, Ks, g, t);
            softmax_pv(s, o, m0s, m1s, l0s, l1s, Ks + 4608, g, t);
        }
    }

    // epilogue: normalize, round to tf32, write (b,n,1024) for out_gemm
    float inv0 = 1.f / l0s, inv1 = 1.f / l1s;
    size_t r0 = (size_t)b * SEQ + n0 + m0 + g;
#pragma unroll
    for (int ni = 0; ni < 8; ni++) {
        int col = h * HD + ni * 8 + 2 * t;
        *(float2*)&g_attn[r0 * DM + col] =
            make_float2(r2f(f2tf(o[ni][0] * inv0)), r2f(f2tf(o[ni][1] * inv0)));
        *(float2*)&g_attn[(r0 + 8) * DM + col] =
            make_float2(r2f(f2tf(o[ni][2] * inv1)), r2f(f2tf(o[ni][3] * inv1)));
    }
}

// ---------------------------------------------------------------------------
extern "C" void kernel_launch(void* const* d_in, const int* in_sizes, int n_in,
                              void* d_out, int out_size)
{
    const float* x  = (const float*)d_in[0];
    const float* cs = (const float*)d_in[1];
    const float* sn = (const float*)d_in[2];
    const float* Wq = (const float*)d_in[3];
    const float* Wk = (const float*)d_in[4];
    const float* Wv = (const float*)d_in[5];
    const float* Wo = (const float*)d_in[6];
    float* out = (float*)d_out;
    (void)in_sizes; (void)n_in; (void)out_size;

    cudaFuncSetAttribute(qkv_gemm, cudaFuncAttributeMaxDynamicSharedMemorySize, QKV_SMEM);
    cudaFuncSetAttribute(out_gemm, cudaFuncAttributeMaxDynamicSharedMemorySize, GEMM_SMEM);
    cudaFuncSetAttribute(attn_mma, cudaFuncAttributeMaxDynamicSharedMemorySize, ATT_SMEM);

    // 1) round x + weights onto the tf32 grid
    prep_round<<<6656, 256>>>(x, Wq, Wk, Wv, Wo);

    // 2) QKV projections + fused RoPE (64x64 tiles, 2-stage, 3 CTAs/SM)
    qkv_gemm<<<dim3(12, 32), 128, QKV_SMEM>>>(cs, sn);

    // 3) attention: grid (8 q-tiles of 256, 16 heads, 2 batch)
    attn_mma<<<dim3(SEQ / 256, NH, BB), 512, ATT_SMEM>>>();

    // 4) output projection (64x32 tiles, 3-stage, 16 warps/SM)
    out_gemm<<<dim3(8, 32), 256, GEMM_SMEM>>>(out);
}

// round 17
// speedup vs baseline: 1.3688x; 1.1252x over previous
#include <cuda_runtime.h>
#include <cuda_fp16.h>
#include <cstdint>

#define NH   16
#define NKV  4
#define HD   64
#define DM   1024
#define BB   2
#define SEQ  2048
#define MROWS (BB*SEQ)   // 4096

// Q pre-scale: HD^-0.5 * log2(e)  (softmax done in exp2 domain)
#define QSC 0.18033688011112042f

// ---------------------------------------------------------------------------
// Scratch (allocation-free device globals)
// ---------------------------------------------------------------------------
__device__ float g_xr [(size_t)MROWS * DM];       // tf32-rounded x
__device__ float g_wqr[(size_t)DM * DM];
__device__ float g_wkr[(size_t)DM * 256];
__device__ float g_wvr[(size_t)DM * 256];
__device__ float g_wor[(size_t)DM * DM];
__device__ __half g_q[(size_t)BB * NH  * SEQ * HD];   // head-major, fp16, d-pair-permuted, *QSC, rope'd
__device__ __half g_k[(size_t)BB * NKV * SEQ * HD];   // head-major, fp16, d-pair-permuted, rope'd
__device__ __half g_v[(size_t)BB * NKV * HD * SEQ];   // TRANSPOSED [d][seq], fp16, key-pair-permuted
__device__ float g_attn[(size_t)MROWS * DM];          // (b,n,1024), tf32-rounded

// ---------------------------------------------------------------------------
// helpers
// ---------------------------------------------------------------------------
__device__ __forceinline__ uint32_t f2tf(float f) {
    uint32_t u;
    asm("cvt.rna.tf32.f32 %0, %1;" : "=r"(u) : "f"(f));
    return u;
}
__device__ __forceinline__ float r2f(uint32_t u) { return __uint_as_float(u); }

__device__ __forceinline__ float ex2f(float x) {
    float r;
    asm("ex2.approx.ftz.f32 %0, %1;" : "=f"(r) : "f"(x));
    return r;
}
// fp16 index of element n within a 16-group (pair u -> u32 pos 2u | 2(u-4)+1)
__device__ __forceinline__ int vremap(int n) {
    int u = (n >> 1) & 7, h = n & 1;
    int pos = (u < 4) ? 2 * u : 2 * (u - 4) + 1;
    return (n & ~15) + pos * 2 + h;
}
__device__ __forceinline__ uint32_t packh(float lo, float hi) {
    uint32_t r;
    asm("cvt.rn.f16x2.f32 %0, %1, %2;" : "=r"(r) : "f"(hi), "f"(lo));
    return r;
}
__device__ __forceinline__ void mma8(float c[4], const uint32_t a[4], const uint32_t b[2]) {
    asm volatile(
        "mma.sync.aligned.m16n8k8.row.col.f32.tf32.tf32.f32 "
        "{%0,%1,%2,%3},{%4,%5,%6,%7},{%8,%9},{%0,%1,%2,%3};"
        : "+f"(c[0]), "+f"(c[1]), "+f"(c[2]), "+f"(c[3])
        : "r"(a[0]), "r"(a[1]), "r"(a[2]), "r"(a[3]), "r"(b[0]), "r"(b[1]));
}
__device__ __forceinline__ void mma16h(float c[4], const uint32_t a[4], uint32_t b0, uint32_t b1) {
    asm volatile(
        "mma.sync.aligned.m16n8k16.row.col.f32.f16.f16.f32 "
        "{%0,%1,%2,%3},{%4,%5,%6,%7},{%8,%9},{%0,%1,%2,%3};"
        : "+f"(c[0]), "+f"(c[1]), "+f"(c[2]), "+f"(c[3])
        : "r"(a[0]), "r"(a[1]), "r"(a[2]), "r"(a[3]), "r"(b0), "r"(b1));
}
__device__ __forceinline__ void cpa16(uint32_t dst, const void* src) {
    asm volatile("cp.async.cg.shared.global [%0], [%1], 16;" :: "r"(dst), "l"(src) : "memory");
}
#define CPA_COMMIT() asm volatile("cp.async.commit_group;" ::: "memory")

// ---------------------------------------------------------------------------
// Pre-pass: round x + weights to the tf32 grid (then mma can eat them raw).
// ---------------------------------------------------------------------------
__global__ void prep_round(const float* __restrict__ x,  const float* __restrict__ Wq,
                           const float* __restrict__ Wk, const float* __restrict__ Wv,
                           const float* __restrict__ Wo)
{
    size_t i = (size_t)blockIdx.x * 256 + threadIdx.x;   // float4 index
    const float* src; float* dst; size_t off;
    if      (i < 1048576) { src = x;  dst = g_xr;  off = i; }
    else if (i < 1310720) { src = Wq; dst = g_wqr; off = i - 1048576; }
    else if (i < 1376256) { src = Wk; dst = g_wkr; off = i - 1310720; }
    else if (i < 1441792) { src = Wv; dst = g_wvr; off = i - 1376256; }
    else                  { src = Wo; dst = g_wor; off = i - 1441792; }
    float4 v = ((const float4*)src)[off];
    v.x = r2f(f2tf(v.x)); v.y = r2f(f2tf(v.y));
    v.z = r2f(f2tf(v.z)); v.w = r2f(f2tf(v.w));
    ((float4*)dst)[off] = v;
}

// ---------------------------------------------------------------------------
// Shared GEMM constants: 128x128 CTA tile, kstep 32.
// Stage: As[128][40] (5120 w) + Bs[32][132] (4224 w) = 9344 words.
// ---------------------------------------------------------------------------
#define GSTAGE 9344
#define GEMM_SMEM (3 * GSTAGE * 4)   // 112128 B (out_gemm: 3-stage, 2 CTA/SM)
#define QKV_SMEM  (2 * GSTAGE * 4)   //  74752 B (qkv: 2-stage, 3 CTA/SM)

// ---------------------------------------------------------------------------
// Variant A (out_gemm): 256 threads (8 warps), warp tile 64x32, 3-stage ring.
// ---------------------------------------------------------------------------
__device__ __forceinline__ void gemm_main32(uint32_t* sm, uint32_t smb,
    const float* __restrict__ A, const float* __restrict__ B,
    int ldb, int n0, int row0, float acc[4][4][4])
{
    const int K = DM, KT = DM / 32;
    const int tid = threadIdx.x, lane = tid & 31, wid = tid >> 5;
    const int g = lane >> 2, t = lane & 3;
    const int m0 = (wid >> 2) * 64, nw = (wid & 3) * 32;

    const int ar = tid >> 3, ac = (tid & 7) << 2;
    const int bk = tid >> 5, bn = (tid & 31) << 2;
    const uint32_t aDst = (ar * 40 + ac) * 4;
    const uint32_t bDst = (5120 + bk * 132 + bn) * 4;
    const float* aS = A + (size_t)(row0 + ar) * K + ac;
    const float* bS = B + (size_t)bk * ldb + n0 + bn;

    auto issue = [&](int slot, int kt) {
        uint32_t base = smb + slot * (GSTAGE * 4);
        const float* a = aS + kt * 32;
        const float* b = bS + (size_t)kt * 32 * ldb;
#pragma unroll
        for (int i = 0; i < 4; i++)
            cpa16(base + aDst + i * (32 * 40 * 4), a + (size_t)i * 32 * K);
#pragma unroll
        for (int i = 0; i < 4; i++)
            cpa16(base + bDst + i * (8 * 132 * 4), b + (size_t)i * 8 * ldb);
        CPA_COMMIT();
    };

#pragma unroll
    for (int mi = 0; mi < 4; mi++)
#pragma unroll
        for (int ni = 0; ni < 4; ni++)
#pragma unroll
            for (int r = 0; r < 4; r++) acc[mi][ni][r] = 0.f;

    issue(0, 0);
    issue(1, 1);

    for (int kt = 0; kt < KT; kt++) {
        if (kt + 1 < KT) asm volatile("cp.async.wait_group 1;" ::: "memory");
        else             asm volatile("cp.async.wait_group 0;" ::: "memory");
        __syncthreads();
        if (kt + 2 < KT) issue((kt + 2) % 3, kt + 2);

        uint32_t* st = sm + (kt % 3) * GSTAGE;
        uint32_t (*As)[40]  = (uint32_t(*)[40])st;
        uint32_t (*Bs)[132] = (uint32_t(*)[132])(st + 5120);
#pragma unroll
        for (int kk0 = 0; kk0 < 32; kk0 += 8) {
            uint32_t a[4][4], b[4][2];
#pragma unroll
            for (int mi = 0; mi < 4; mi++) {
                int rb = m0 + mi * 16 + g;
                uint2 av0 = *(const uint2*)&As[rb][kk0 + 2 * t];
                uint2 av1 = *(const uint2*)&As[rb + 8][kk0 + 2 * t];
                a[mi][0] = av0.x; a[mi][1] = av1.x; a[mi][2] = av0.y; a[mi][3] = av1.y;
            }
#pragma unroll
            for (int ni = 0; ni < 4; ni++) {
                b[ni][0] = Bs[kk0 + 2 * t][nw + ni * 8 + g];
                b[ni][1] = Bs[kk0 + 2 * t + 1][nw + ni * 8 + g];
            }
#pragma unroll
            for (int mi = 0; mi < 4; mi++)
#pragma unroll
                for (int ni = 0; ni < 4; ni++)
                    mma8(acc[mi][ni], a[mi], b[ni]);
        }
    }
}

// ---------------------------------------------------------------------------
// Variant B2 (qkv): 128 threads (4 warps), warp tile 64x64, 2-stage ring,
// 3 CTAs/SM -> 384 CTAs in one wave.
// ---------------------------------------------------------------------------
__device__ __forceinline__ void gemm_main64_2s(uint32_t* sm, uint32_t smb,
    const float* __restrict__ A, const float* __restrict__ B,
    int ldb, int n0, int row0, float acc[4][8][4])
{
    const int K = DM, KT = DM / 32;
    const int tid = threadIdx.x, lane = tid & 31, wid = tid >> 5;  // wid 0..3
    const int g = lane >> 2, t = lane & 3;
    const int m0 = (wid >> 1) * 64, nw = (wid & 1) * 64;

    const int ar = tid >> 3, ac = (tid & 7) << 2;
    const int bk = tid >> 5, bn = (tid & 31) << 2;
    const uint32_t aDst = (ar * 40 + ac) * 4;
    const uint32_t bDst = (5120 + bk * 132 + bn) * 4;
    const float* aS = A + (size_t)(row0 + ar) * K + ac;
    const float* bS = B + (size_t)bk * ldb + n0 + bn;

    auto issue = [&](int slot, int kt) {
        uint32_t base = smb + slot * (GSTAGE * 4);
        const float* a = aS + kt * 32;
        const float* b = bS + (size_t)kt * 32 * ldb;
#pragma unroll
        for (int i = 0; i < 8; i++)
            cpa16(base + aDst + i * (16 * 40 * 4), a + (size_t)i * 16 * K);
#pragma unroll
        for (int i = 0; i < 8; i++)
            cpa16(base + bDst + i * (4 * 132 * 4), b + (size_t)i * 4 * ldb);
        CPA_COMMIT();
    };

#pragma unroll
    for (int mi = 0; mi < 4; mi++)
#pragma unroll
        for (int ni = 0; ni < 8; ni++)
#pragma unroll
            for (int r = 0; r < 4; r++) acc[mi][ni][r] = 0.f;

    issue(0, 0);
    issue(1, 1);

    for (int kt = 0; kt < KT; kt++) {
        if (kt + 1 < KT) asm volatile("cp.async.wait_group 1;" ::: "memory");
        else             asm volatile("cp.async.wait_group 0;" ::: "memory");
        __syncthreads();   // stage kt ready for all warps

        uint32_t* st = sm + (kt & 1) * GSTAGE;
        uint32_t (*As)[40]  = (uint32_t(*)[40])st;
        uint32_t (*Bs)[132] = (uint32_t(*)[132])(st + 5120);
#pragma unroll
        for (int kk0 = 0; kk0 < 32; kk0 += 8) {
            uint32_t a[4][4], b[8][2];
#pragma unroll
            for (int mi = 0; mi < 4; mi++) {
                int rb = m0 + mi * 16 + g;
                uint2 av0 = *(const uint2*)&As[rb][kk0 + 2 * t];
                uint2 av1 = *(const uint2*)&As[rb + 8][kk0 + 2 * t];
                a[mi][0] = av0.x; a[mi][1] = av1.x; a[mi][2] = av0.y; a[mi][3] = av1.y;
            }
#pragma unroll
            for (int ni = 0; ni < 8; ni++) {
                b[ni][0] = Bs[kk0 + 2 * t][nw + ni * 8 + g];
                b[ni][1] = Bs[kk0 + 2 * t + 1][nw + ni * 8 + g];
            }
#pragma unroll
            for (int mi = 0; mi < 4; mi++)
#pragma unroll
                for (int ni = 0; ni < 8; ni++)
                    mma8(acc[mi][ni], a[mi], b[ni]);
        }
        if (kt + 2 < KT) {
            __syncthreads();            // all warps done reading slot kt&1
            issue(kt & 1, kt + 2);      // refill it
        }
    }
}

// ---------------------------------------------------------------------------
// QKV projection + fused RoPE + permuted head-major stores.
// Q/K: fp16, d-pair-in-16 permuted (vremap).  V: fp16 transposed + key-pair-
// permuted.  grid (12, 32), 128 threads, 3 CTAs/SM.
// ---------------------------------------------------------------------------
__global__ __launch_bounds__(128, 3) void qkv_gemm(
    const float* __restrict__ cs, const float* __restrict__ sn)
{
    extern __shared__ uint32_t sm[];
    uint32_t smb = (uint32_t)__cvta_generic_to_shared(sm);
    const int bx = blockIdx.x, row0 = blockIdx.y * 128;
    const int tid = threadIdx.x, lane = tid & 31, wid = tid >> 5;
    const int g = lane >> 2, t = lane & 3;
    const int m0 = (wid >> 1) * 64, nw = (wid & 1) * 64;
    float acc[4][8][4];

    if (bx < 8) {
        gemm_main64_2s(sm, smb, g_xr, g_wqr, DM, bx * 128, row0, acc);
#pragma unroll
        for (int mi = 0; mi < 4; mi++)
#pragma unroll
            for (int ni = 0; ni < 8; ni++) {
                int gc = bx * 128 + nw + ni * 8 + 2 * t;       // even original col
                int head = gc >> 6, j = (gc & 63) >> 1;
                int pj = vremap(j), pj2 = vremap(j + 32);
#pragma unroll
                for (int rr = 0; rr < 2; rr++) {
                    int row = row0 + m0 + mi * 16 + g + rr * 8;
                    int n = row & (SEQ - 1), bi = row >> 11;
                    float cv = cs[n * 32 + j], sv = sn[n * 32 + j];
                    float a0 = acc[mi][ni][rr * 2], a1 = acc[mi][ni][rr * 2 + 1];
                    size_t bp = ((size_t)(bi * NH + head) * SEQ + n) * HD;
                    g_q[bp + pj]  = __float2half((a0 * cv - a1 * sv) * QSC);
                    g_q[bp + pj2] = __float2half((a0 * sv + a1 * cv) * QSC);
                }
            }
    } else if (bx < 10) {
        gemm_main64_2s(sm, smb, g_xr, g_wkr, 256, (bx - 8) * 128, row0, acc);
#pragma unroll
        for (int mi = 0; mi < 4; mi++)
#pragma unroll
            for (int ni = 0; ni < 8; ni++) {
                int gc = (bx - 8) * 128 + nw + ni * 8 + 2 * t;
                int kvh = gc >> 6, j = (gc & 63) >> 1;
                int pj = vremap(j), pj2 = vremap(j + 32);
#pragma unroll
                for (int rr = 0; rr < 2; rr++) {
                    int row = row0 + m0 + mi * 16 + g + rr * 8;
                    int n = row & (SEQ - 1), bi = row >> 11;
                    float cv = cs[n * 32 + j], sv = sn[n * 32 + j];
                    float a0 = acc[mi][ni][rr * 2], a1 = acc[mi][ni][rr * 2 + 1];
                    size_t bp = ((size_t)(bi * NKV + kvh) * SEQ + n) * HD;
                    g_k[bp + pj]  = __float2half(a0 * cv - a1 * sv);
                    g_k[bp + pj2] = __float2half(a0 * sv + a1 * cv);
                }
            }
    } else {
        gemm_main64_2s(sm, smb, g_xr, g_wvr, 256, (bx - 10) * 128, row0, acc);
        // V: fp16 transposed store g_v[bh][d][key], key-pair-permuted per 16
#pragma unroll
        for (int mi = 0; mi < 4; mi++)
#pragma unroll
            for (int ni = 0; ni < 8; ni++) {
                int gc = (bx - 10) * 128 + nw + ni * 8 + 2 * t;
                int kvh = gc >> 6, d = gc & 63;
#pragma unroll
                for (int rr = 0; rr < 2; rr++) {
                    int row = row0 + m0 + mi * 16 + g + rr * 8;
                    int n = row & (SEQ - 1), bi = row >> 11;
                    int nv = vremap(n);
                    size_t hb = (size_t)(bi * NKV + kvh) * HD;
                    g_v[(hb + d) * SEQ + nv]     = __float2half(acc[mi][ni][rr * 2]);
                    g_v[(hb + d + 1) * SEQ + nv] = __float2half(acc[mi][ni][rr * 2 + 1]);
                }
            }
    }
}

// ---------------------------------------------------------------------------
// Output projection: grid (8, 32), 256 threads (variant A).
// ---------------------------------------------------------------------------
__global__ __launch_bounds__(256, 2) void out_gemm(float* __restrict__ out)
{
    extern __shared__ uint32_t sm[];
    uint32_t smb = (uint32_t)__cvta_generic_to_shared(sm);
    const int tid = threadIdx.x, lane = tid & 31, wid = tid >> 5;
    const int g = lane >> 2, t = lane & 3;
    const int m0 = (wid >> 2) * 64, nw = (wid & 3) * 32;
    const int n0 = blockIdx.x * 128, row0 = blockIdx.y * 128;
    float acc[4][4][4];
    gemm_main32(sm, smb, g_attn, g_wor, DM, n0, row0, acc);
#pragma unroll
    for (int mi = 0; mi < 4; mi++) {
        int r = row0 + m0 + mi * 16 + g;
#pragma unroll
        for (int ni = 0; ni < 4; ni++) {
            int c = n0 + nw + ni * 8 + 2 * t;
            *(float2*)(out + (size_t)r * DM + c)       = make_float2(acc[mi][ni][0], acc[mi][ni][1]);
            *(float2*)(out + (size_t)(r + 8) * DM + c) = make_float2(acc[mi][ni][2], acc[mi][ni][3]);
        }
    }
}

// ---------------------------------------------------------------------------
// Flash attention: BM=256, 512 threads, 1 CTA/SM, Q in registers (fp16),
// 6-stage KV ring, two KV blocks per barrier. QK^T AND P*V in fp16 m16n8k16,
// fp32 accumulate. K tile fp16 64 keys x 64 d (d-pair-permuted, ld 40 u32);
// V tile fp16 64 d x 64 keys (key-pair-permuted, ld 40 u32).
// Stage: Ks 64*40=2560 w + Vt 64*40=2560 w = 5120 w. 6 stages = 122880 B.
// ---------------------------------------------------------------------------
#define ASTG 5120
#define ATT_SMEM (6 * ASTG * 4)   // 122880

__device__ __forceinline__ void attn_issue_kv(uint32_t smb, int slot,
    const __half* __restrict__ Kb, const __half* __restrict__ Vb, int kt, int tid)
{
    uint32_t base = smb + slot * (ASTG * 4);
    const int r = tid >> 3, col = tid & 7;   // 64 rows x 8 chunks of 16B
    cpa16(base + (r * 40 + col * 4) * 4,
          Kb + (size_t)(kt * 64 + r) * HD + col * 8);
    cpa16(base + (2560 + r * 40 + col * 4) * 4,
          Vb + (size_t)r * SEQ + kt * 64 + col * 8);
    CPA_COMMIT();
}

// S = Q*K^T, fp16 k16, Q a-frags in registers
__device__ __forceinline__ void s_gemm_q(float s[8][4],
    const uint32_t q[4][4], const uint32_t* Ks, int g, int t)
{
#pragma unroll
    for (int ni = 0; ni < 8; ni++)
#pragma unroll
        for (int r = 0; r < 4; r++) s[ni][r] = 0.f;
#pragma unroll
    for (int kk2 = 0; kk2 < 4; kk2++) {
#pragma unroll
        for (int ni = 0; ni < 8; ni++) {
            uint2 bv = *(const uint2*)&Ks[(ni * 8 + g) * 40 + kk2 * 8 + 2 * t];
            mma16h(s[ni], q[kk2], bv.x, bv.y);
        }
    }
}

// online-softmax update on s + rescale o + O += P*V (fp16 k16) from Vt stage
__device__ __forceinline__ void softmax_pv(float s[8][4], float o[8][4],
    float& m0s, float& m1s, float& l0s, float& l1s,
    const uint32_t* Vt, int g, int t)
{
    float mx0 = -1e30f, mx1 = -1e30f;
#pragma unroll
    for (int ni = 0; ni < 8; ni++) {
        mx0 = fmaxf(mx0, fmaxf(s[ni][0], s[ni][1]));
        mx1 = fmaxf(mx1, fmaxf(s[ni][2], s[ni][3]));
    }
    mx0 = fmaxf(mx0, __shfl_xor_sync(0xffffffffu, mx0, 1));
    mx0 = fmaxf(mx0, __shfl_xor_sync(0xffffffffu, mx0, 2));
    mx1 = fmaxf(mx1, __shfl_xor_sync(0xffffffffu, mx1, 1));
    mx1 = fmaxf(mx1, __shfl_xor_sync(0xffffffffu, mx1, 2));

    float mn0 = fmaxf(m0s, mx0), mn1 = fmaxf(m1s, mx1);
    float cor0 = ex2f(m0s - mn0), cor1 = ex2f(m1s - mn1);
    m0s = mn0; m1s = mn1;

    float rs0 = 0.f, rs1 = 0.f;
#pragma unroll
    for (int ni = 0; ni < 8; ni++) {
        s[ni][0] = ex2f(s[ni][0] - mn0);
        s[ni][1] = ex2f(s[ni][1] - mn0);
        s[ni][2] = ex2f(s[ni][2] - mn1);
        s[ni][3] = ex2f(s[ni][3] - mn1);
        rs0 += s[ni][0] + s[ni][1];
        rs1 += s[ni][2] + s[ni][3];
    }
    rs0 += __shfl_xor_sync(0xffffffffu, rs0, 1);
    rs0 += __shfl_xor_sync(0xffffffffu, rs0, 2);
    rs1 += __shfl_xor_sync(0xffffffffu, rs1, 1);
    rs1 += __shfl_xor_sync(0xffffffffu, rs1, 2);
    l0s = l0s * cor0 + rs0;
    l1s = l1s * cor1 + rs1;

#pragma unroll
    for (int ni = 0; ni < 8; ni++) {
        o[ni][0] *= cor0; o[ni][1] *= cor0;
        o[ni][2] *= cor1; o[ni][3] *= cor1;
    }
    // P*V in fp16: A-frag = packed S C-frags of key-blocks 2kk2, 2kk2+1
#pragma unroll
    for (int kk2 = 0; kk2 < 4; kk2++) {
        uint32_t a[4];
        a[0] = packh(s[2 * kk2][0],     s[2 * kk2][1]);
        a[1] = packh(s[2 * kk2][2],     s[2 * kk2][3]);
        a[2] = packh(s[2 * kk2 + 1][0], s[2 * kk2 + 1][1]);
        a[3] = packh(s[2 * kk2 + 1][2], s[2 * kk2 + 1][3]);
#pragma unroll
        for (int ni = 0; ni < 8; ni++) {
            uint2 bv = *(const uint2*)&Vt[(ni * 8 + g) * 40 + kk2 * 8 + 2 * t];
            mma16h(o[ni], a, bv.x, bv.y);
        }
    }
}

__global__ __launch_bounds__(512, 1) void attn_mma()
{
    extern __shared__ uint32_t sm[];
    uint32_t smb = (uint32_t)__cvta_generic_to_shared(sm);
    const int b = blockIdx.z, h = blockIdx.y;
    const int n0 = blockIdx.x * 256;
    const int kvh = h >> 2;
    const int tid = threadIdx.x, lane = tid & 31, wid = tid >> 5;  // wid 0..15
    const int g = lane >> 2, t = lane & 3;
    const int m0 = wid * 16;

    const __half* Kb = g_k + ((size_t)(b * NKV + kvh) * SEQ) * HD;
    const __half* Vb = g_v + ((size_t)(b * NKV + kvh) * HD) * SEQ;

    // prefetch 4 KV stages
    attn_issue_kv(smb, 0, Kb, Vb, 0, tid);
    attn_issue_kv(smb, 1, Kb, Vb, 1, tid);
    attn_issue_kv(smb, 2, Kb, Vb, 2, tid);
    attn_issue_kv(smb, 3, Kb, Vb, 3, tid);

    // Q a-frags directly from global (fp16, d-pair-permuted rows of 32 u32)
    uint32_t q[4][4];
    {
        const uint32_t* Qg = (const uint32_t*)(g_q +
            ((size_t)(b * NH + h) * SEQ + n0 + m0) * HD);
        const uint32_t* r0p = Qg + g * (HD / 2);
        const uint32_t* r1p = Qg + (g + 8) * (HD / 2);
#pragma unroll
        for (int kk2 = 0; kk2 < 4; kk2++) {
            uint2 u0 = *(const uint2*)(r0p + kk2 * 8 + 2 * t);
            uint2 u1 = *(const uint2*)(r1p + kk2 * 8 + 2 * t);
            q[kk2][0] = u0.x; q[kk2][1] = u1.x; q[kk2][2] = u0.y; q[kk2][3] = u1.y;
        }
    }

    float m0s = -1e30f, m1s = -1e30f, l0s = 0.f, l1s = 0.f;
    float s[8][4], o[8][4];
#pragma unroll
    for (int ni = 0; ni < 8; ni++)
#pragma unroll
        for (int r = 0; r < 4; r++) o[ni][r] = 0.f;

    const int KT = SEQ / 64;   // 32, processed in pairs
    for (int kt = 0; kt < KT; kt += 2) {
        if (kt + 2 < KT) asm volatile("cp.async.wait_group 2;" ::: "memory");
        else             asm volatile("cp.async.wait_group 0;" ::: "memory");
        __syncthreads();
        if (kt + 4 < KT) attn_issue_kv(smb, (kt + 4) % 6, Kb, Vb, kt + 4, tid);
        if (kt + 5 < KT) attn_issue_kv(smb, (kt + 5) % 6, Kb, Vb, kt + 5, tid);

        {
            uint32_t* Ks = sm + (kt % 6) * ASTG;
            s_gemm_q(s, q, Ks, g, t);
            softmax_pv(s, o, m0s, m1s, l0s, l1s, Ks + 2560, g, t);
        }
        {
            uint32_t* Ks = sm + ((kt + 1) % 6) * ASTG;
            s_gemm_q(s, q, Ks, g, t);
            softmax_pv(s, o, m0s, m1s, l0s, l1s, Ks + 2560, g, t);
        }
    }

    // epilogue: normalize, round to tf32, write (b,n,1024) for out_gemm
    float inv0 = 1.f / l0s, inv1 = 1.f / l1s;
    size_t r0 = (size_t)b * SEQ + n0 + m0 + g;
#pragma unroll
    for (int ni = 0; ni < 8; ni++) {
        int col = h * HD + ni * 8 + 2 * t;
        *(float2*)&g_attn[r0 * DM + col] =
            make_float2(r2f(f2tf(o[ni][0] * inv0)), r2f(f2tf(o[ni][1] * inv0)));
        *(float2*)&g_attn[(r0 + 8) * DM + col] =
            make_float2(r2f(f2tf(o[ni][2] * inv1)), r2f(f2tf(o[ni][3] * inv1)));
    }
}

// ---------------------------------------------------------------------------
extern "C" void kernel_launch(void* const* d_in, const int* in_sizes, int n_in,
                              void* d_out, int out_size)
{
    const float* x  = (const float*)d_in[0];
    const float* cs = (const float*)d_in[1];
    const float* sn = (const float*)d_in[2];
    const float* Wq = (const float*)d_in[3];
    const float* Wk = (const float*)d_in[4];
    const float* Wv = (const float*)d_in[5];
    const float* Wo = (const float*)d_in[6];
    float* out = (float*)d_out;
    (void)in_sizes; (void)n_in; (void)out_size;

    cudaFuncSetAttribute(qkv_gemm, cudaFuncAttributeMaxDynamicSharedMemorySize, QKV_SMEM);
    cudaFuncSetAttribute(out_gemm, cudaFuncAttributeMaxDynamicSharedMemorySize, GEMM_SMEM);
    cudaFuncSetAttribute(attn_mma, cudaFuncAttributeMaxDynamicSharedMemorySize, ATT_SMEM);

    // 1) round x + weights onto the tf32 grid
    prep_round<<<6656, 256>>>(x, Wq, Wk, Wv, Wo);

    // 2) QKV projections + fused RoPE (64x64 tiles, 2-stage, 3 CTAs/SM)
    qkv_gemm<<<dim3(12, 32), 128, QKV_SMEM>>>(cs, sn);

    // 3) attention: grid (8 q-tiles of 256, 16 heads, 2 batch)
    attn_mma<<<dim3(SEQ / 256, NH, BB), 512, ATT_SMEM>>>();

    // 4) output projection (64x32 tiles, 3-stage, 16 warps/SM)
    out_gemm<<<dim3(8, 32), 256, GEMM_SMEM>>>(out);
}